// round 1
// baseline (speedup 1.0000x reference)
#include <cuda_runtime.h>
#include <cuda_bf16.h>
#include <math.h>

// GPT-2 small forward: B=2, T=1024, D=768, F=3072, H=12, L=4, V=50257
// Baseline: fp32 shared-memory SGEMM (128x128x16 tiles, 8x8 microtile),
// fused two-pass softmax attention, LN kernels. All scratch in __device__
// globals; graph-capturable (plain kernel launches only).

#define NT   2048        // B*T tokens
#define TT   1024        // seq len
#define DD   768
#define FF   3072
#define HH   12
#define HD   64
#define LL   4
#define VV   50257
#define D3   2304        // 3*D

// ---------------- scratch ----------------
__device__ float g_x  [NT * DD];   // residual stream
__device__ float g_h  [NT * DD];   // LN output
__device__ float g_qkv[NT * D3];
__device__ float g_att[NT * DD];
__device__ float g_ffn[NT * FF];

// ---------------- reductions ----------------
__device__ __forceinline__ float blk_sum(float v, float* red) {
    #pragma unroll
    for (int o = 16; o; o >>= 1) v += __shfl_xor_sync(0xffffffffu, v, o);
    int wid = threadIdx.x >> 5, lid = threadIdx.x & 31;
    if (lid == 0) red[wid] = v;
    __syncthreads();
    int nw = blockDim.x >> 5;
    float s = (threadIdx.x < nw) ? red[threadIdx.x] : 0.0f;
    #pragma unroll
    for (int o = 16; o; o >>= 1) s += __shfl_xor_sync(0xffffffffu, s, o);
    if (threadIdx.x == 0) red[0] = s;
    __syncthreads();
    s = red[0];
    __syncthreads();
    return s;
}

__device__ __forceinline__ float blk_max(float v, float* red) {
    #pragma unroll
    for (int o = 16; o; o >>= 1) v = fmaxf(v, __shfl_xor_sync(0xffffffffu, v, o));
    int wid = threadIdx.x >> 5, lid = threadIdx.x & 31;
    if (lid == 0) red[wid] = v;
    __syncthreads();
    int nw = blockDim.x >> 5;
    float s = (threadIdx.x < nw) ? red[threadIdx.x] : -1e30f;
    #pragma unroll
    for (int o = 16; o; o >>= 1) s = fmaxf(s, __shfl_xor_sync(0xffffffffu, s, o));
    if (threadIdx.x == 0) red[0] = s;
    __syncthreads();
    s = red[0];
    __syncthreads();
    return s;
}

// ---------------- embed ----------------
__global__ void embed_kernel(const int* __restrict__ tok,
                             const float* __restrict__ wte,
                             const float* __restrict__ wpe,
                             float* __restrict__ x) {
    int n = blockIdx.x;             // b*T + t
    int tpos = n & (TT - 1);
    int t = tok[n];
    const float* we = wte + (size_t)t * DD;
    const float* wp = wpe + (size_t)tpos * DD;
    float* xr = x + (size_t)n * DD;
    for (int i = threadIdx.x; i < DD; i += blockDim.x)
        xr[i] = we[i] + wp[i];
}

// ---------------- layernorm ----------------
__global__ void ln_kernel(const float* __restrict__ x,
                          const float* __restrict__ w,
                          const float* __restrict__ b,
                          float* __restrict__ y) {
    __shared__ float red[32];
    int row = blockIdx.x;
    const float* xr = x + (size_t)row * DD;
    float* yr = y + (size_t)row * DD;
    float v[3];
    float s = 0.f, ss = 0.f;
    #pragma unroll
    for (int i = 0; i < 3; i++) {
        int c = threadIdx.x + i * 256;
        v[i] = xr[c];
        s += v[i];
        ss += v[i] * v[i];
    }
    s  = blk_sum(s,  red);
    ss = blk_sum(ss, red);
    float mu = s * (1.0f / DD);
    float var = ss * (1.0f / DD) - mu * mu;
    float r = rsqrtf(var + 1e-5f);
    #pragma unroll
    for (int i = 0; i < 3; i++) {
        int c = threadIdx.x + i * 256;
        yr[c] = (v[i] - mu) * r * w[c] + b[c];
    }
}

// ---------------- attention (one block per (b,h,q)) ----------------
__global__ void attn_kernel(const float* __restrict__ qkv, float* __restrict__ out) {
    __shared__ float qv[HD];
    __shared__ float sc[TT];
    __shared__ float red[32];
    __shared__ float ppart[128];

    int q = blockIdx.x;
    int h = blockIdx.y;
    int b = blockIdx.z;
    int tid = threadIdx.x;   // 128 threads

    const float* base = qkv + (size_t)b * TT * D3;
    if (tid < HD) qv[tid] = base[(size_t)q * D3 + h * HD + tid];
    __syncthreads();

    // pass 1: scores + max
    float lmax = -1e30f;
    for (int k = tid; k <= q; k += 128) {
        const float* kp = base + (size_t)k * D3 + DD + h * HD;
        float d = 0.f;
        #pragma unroll
        for (int e = 0; e < HD; e++) d += qv[e] * kp[e];
        d *= 0.125f;   // 1/sqrt(64)
        sc[k] = d;
        lmax = fmaxf(lmax, d);
    }
    float mx = blk_max(lmax, red);

    // exp + sum
    float lsum = 0.f;
    for (int k = tid; k <= q; k += 128) {
        float e = __expf(sc[k] - mx);
        sc[k] = e;
        lsum += e;
    }
    float ssum = blk_sum(lsum, red);
    float inv = 1.0f / ssum;
    __syncthreads();

    // pass 2: o[d] = sum_k p_k * V[k][d]; split keys over 2 partitions
    int d = tid & (HD - 1);
    int part = tid >> 6;
    float o = 0.f;
    for (int k = part; k <= q; k += 2) {
        o += sc[k] * base[(size_t)k * D3 + 2 * DD + h * HD + d];
    }
    ppart[tid] = o;
    __syncthreads();
    if (tid < HD)
        out[((size_t)b * TT + q) * DD + h * HD + tid] = (ppart[tid] + ppart[tid + HD]) * inv;
}

// ---------------- GEMM: C[M,N] = A[M,K] @ B (+bias, +gelu, +residual) ----
// TRANSB: B is [N,K] row-major (head_w), else [K,N] row-major.
// Requires: M % 128 == 0, K % 16 == 0. N arbitrary (guarded).
#define BM 128
#define BN 128
#define BKT 16

template<bool TRANSB, bool GELU, bool RESID, bool HASBIAS>
__global__ void __launch_bounds__(256)
gemm_kernel(const float* __restrict__ A, const float* __restrict__ Bm,
            const float* __restrict__ bias, float* __restrict__ C,
            int M, int N, int K) {
    __shared__ float As[BKT][BM];
    __shared__ float Bs[BKT][BN];

    int tid = threadIdx.x;
    int tx = tid & 15, ty = tid >> 4;
    int row0 = blockIdx.y * BM;
    int n0 = blockIdx.x * BN;

    float acc[8][8];
    #pragma unroll
    for (int i = 0; i < 8; i++)
        #pragma unroll
        for (int j = 0; j < 8; j++) acc[i][j] = 0.f;

    for (int k0 = 0; k0 < K; k0 += BKT) {
        // load A tile (transpose into As[kk][mm])
        #pragma unroll
        for (int i = 0; i < 2; i++) {
            int f = tid + i * 256;          // float4 id, 0..511
            int mm = f >> 2;
            int kq = f & 3;
            float4 v = *reinterpret_cast<const float4*>(
                A + (size_t)(row0 + mm) * K + k0 + kq * 4);
            As[kq * 4 + 0][mm] = v.x;
            As[kq * 4 + 1][mm] = v.y;
            As[kq * 4 + 2][mm] = v.z;
            As[kq * 4 + 3][mm] = v.w;
        }
        // load B tile
        if (TRANSB) {
            #pragma unroll
            for (int i = 0; i < 2; i++) {
                int f = tid + i * 256;
                int nn = f >> 2;
                int kq = f & 3;
                int col = n0 + nn;
                float4 v = make_float4(0.f, 0.f, 0.f, 0.f);
                if (col < N)
                    v = *reinterpret_cast<const float4*>(
                        Bm + (size_t)col * K + k0 + kq * 4);
                Bs[kq * 4 + 0][nn] = v.x;
                Bs[kq * 4 + 1][nn] = v.y;
                Bs[kq * 4 + 2][nn] = v.z;
                Bs[kq * 4 + 3][nn] = v.w;
            }
        } else {
            #pragma unroll
            for (int i = 0; i < 2; i++) {
                int f = tid + i * 256;
                int kk = f >> 5;
                int nq = f & 31;
                float4 v = *reinterpret_cast<const float4*>(
                    Bm + (size_t)(k0 + kk) * N + n0 + nq * 4);
                *reinterpret_cast<float4*>(&Bs[kk][nq * 4]) = v;
            }
        }
        __syncthreads();

        #pragma unroll
        for (int kk = 0; kk < BKT; kk++) {
            float a[8], bb[8];
            #pragma unroll
            for (int i = 0; i < 8; i++) a[i] = As[kk][ty * 8 + i];
            #pragma unroll
            for (int j = 0; j < 8; j++) bb[j] = Bs[kk][tx * 8 + j];
            #pragma unroll
            for (int i = 0; i < 8; i++)
                #pragma unroll
                for (int j = 0; j < 8; j++)
                    acc[i][j] += a[i] * bb[j];
        }
        __syncthreads();
    }

    const float cg = 0.7978845608028654f;  // sqrt(2/pi)
    #pragma unroll
    for (int i = 0; i < 8; i++) {
        int r = row0 + ty * 8 + i;
        #pragma unroll
        for (int j = 0; j < 8; j++) {
            int c = n0 + tx * 8 + j;
            if (c < N) {
                float v = acc[i][j];
                if (HASBIAS) v += bias[c];
                if (GELU) {
                    float u = cg * (v + 0.044715f * v * v * v);
                    v = 0.5f * v * (1.0f + tanhf(u));
                }
                size_t idx = (size_t)r * N + c;
                if (RESID) v += C[idx];
                C[idx] = v;
            }
        }
    }
}

// ---------------- host ----------------
extern "C" void kernel_launch(void* const* d_in, const int* in_sizes, int n_in,
                              void* d_out, int out_size) {
    const int*   tok    = (const int*)  d_in[0];
    const float* wte    = (const float*)d_in[1];
    const float* wpe    = (const float*)d_in[2];
    const float* ln1_w  = (const float*)d_in[3];
    const float* ln1_b  = (const float*)d_in[4];
    const float* attn_w = (const float*)d_in[5];
    const float* attn_b = (const float*)d_in[6];
    const float* proj_w = (const float*)d_in[7];
    const float* proj_b = (const float*)d_in[8];
    const float* ln2_w  = (const float*)d_in[9];
    const float* ln2_b  = (const float*)d_in[10];
    const float* fc_w   = (const float*)d_in[11];
    const float* fc_b   = (const float*)d_in[12];
    const float* fc2_w  = (const float*)d_in[13];
    const float* fc2_b  = (const float*)d_in[14];
    const float* lnf_w  = (const float*)d_in[15];
    const float* lnf_b  = (const float*)d_in[16];
    const float* head_w = (const float*)d_in[17];
    float* out = (float*)d_out;

    float *x, *h, *qkv, *att, *ffn;
    cudaGetSymbolAddress((void**)&x,   g_x);
    cudaGetSymbolAddress((void**)&h,   g_h);
    cudaGetSymbolAddress((void**)&qkv, g_qkv);
    cudaGetSymbolAddress((void**)&att, g_att);
    cudaGetSymbolAddress((void**)&ffn, g_ffn);

    embed_kernel<<<NT, 256>>>(tok, wte, wpe, x);

    for (int l = 0; l < LL; l++) {
        ln_kernel<<<NT, 256>>>(x, ln1_w + l * DD, ln1_b + l * DD, h);
        gemm_kernel<false, false, false, true><<<dim3(D3 / BN, NT / BM), 256>>>(
            h, attn_w + (size_t)l * DD * D3, attn_b + l * D3, qkv, NT, D3, DD);
        attn_kernel<<<dim3(TT, HH, 2), 128>>>(qkv, att);
        gemm_kernel<false, false, true, true><<<dim3(DD / BN, NT / BM), 256>>>(
            att, proj_w + (size_t)l * DD * DD, proj_b + l * DD, x, NT, DD, DD);
        ln_kernel<<<NT, 256>>>(x, ln2_w + l * DD, ln2_b + l * DD, h);
        gemm_kernel<false, true, false, true><<<dim3(FF / BN, NT / BM), 256>>>(
            h, fc_w + (size_t)l * DD * FF, fc_b + l * FF, ffn, NT, FF, DD);
        gemm_kernel<false, false, true, true><<<dim3(DD / BN, NT / BM), 256>>>(
            ffn, fc2_w + (size_t)l * FF * DD, fc2_b + l * DD, x, NT, DD, FF);
    }

    ln_kernel<<<NT, 256>>>(x, lnf_w, lnf_b, h);
    gemm_kernel<true, false, false, false><<<dim3((VV + BN - 1) / BN, NT / BM), 256>>>(
        h, head_w, nullptr, out, NT, VV, DD);
}

// round 2
// speedup vs baseline: 1.1001x; 1.1001x over previous
#include <cuda_runtime.h>
#include <cuda_bf16.h>
#include <math.h>
#include <stdint.h>

// GPT-2 small forward: B=2, T=1024, D=768, F=3072, H=12, L=4, V=50257
// R2: all GEMMs on bf16 tensor cores (mma.sync m16n8k16) with hi/lo split
// (3-term compensated product, fp32 accum). Weights pre-packed per launch
// into pair-major bf16 hi/lo global scratch. Attention/LN still fp32.

#define NT   2048        // B*T tokens
#define TT   1024        // seq len
#define DD   768
#define FF   3072
#define HH   12
#define HD   64
#define LL   4
#define VV   50257
#define D3   2304        // 3*D
#define VP   50304       // padded head N (multiple of 128... actually of 4/32)

// ---------------- scratch ----------------
__device__ float g_x  [NT * DD];   // residual stream
__device__ float g_h  [NT * DD];   // LN output
__device__ float g_qkv[NT * D3];
__device__ float g_att[NT * DD];
__device__ float g_ffn[NT * FF];

// packed bf16-pair weights, [K/2][N] uint32, hi and lo
__device__ uint32_t g_wqkv_h[LL * (DD/2) * D3];
__device__ uint32_t g_wqkv_l[LL * (DD/2) * D3];
__device__ uint32_t g_wproj_h[LL * (DD/2) * DD];
__device__ uint32_t g_wproj_l[LL * (DD/2) * DD];
__device__ uint32_t g_wfc_h [LL * (DD/2) * FF];
__device__ uint32_t g_wfc_l [LL * (DD/2) * FF];
__device__ uint32_t g_wfc2_h[LL * (FF/2) * DD];
__device__ uint32_t g_wfc2_l[LL * (FF/2) * DD];
__device__ uint32_t g_whead_h[(DD/2) * VP];
__device__ uint32_t g_whead_l[(DD/2) * VP];

// ---------------- helpers ----------------
__device__ __forceinline__ void cvt2(float x, float y, uint32_t& hi, uint32_t& lo) {
    __nv_bfloat16 hx = __float2bfloat16(x);
    __nv_bfloat16 hy = __float2bfloat16(y);
    __nv_bfloat16 lx = __float2bfloat16(x - __bfloat162float(hx));
    __nv_bfloat16 ly = __float2bfloat16(y - __bfloat162float(hy));
    hi = ((uint32_t)__bfloat16_as_ushort(hy) << 16) | (uint32_t)__bfloat16_as_ushort(hx);
    lo = ((uint32_t)__bfloat16_as_ushort(ly) << 16) | (uint32_t)__bfloat16_as_ushort(lx);
}

__device__ __forceinline__ void mma16816(float* c, const uint32_t* a, const uint32_t* b) {
    asm volatile(
        "mma.sync.aligned.m16n8k16.row.col.f32.bf16.bf16.f32 "
        "{%0,%1,%2,%3}, {%4,%5,%6,%7}, {%8,%9}, {%0,%1,%2,%3};\n"
        : "+f"(c[0]), "+f"(c[1]), "+f"(c[2]), "+f"(c[3])
        : "r"(a[0]), "r"(a[1]), "r"(a[2]), "r"(a[3]), "r"(b[0]), "r"(b[1]));
}

// ---------------- weight packing ----------------
// W [K][N] fp32 -> Hh/Hl [K/2][N] uint32 (bf16 pair over k)
__global__ void pack_w_kernel(const float* __restrict__ W,
                              uint32_t* __restrict__ Hh, uint32_t* __restrict__ Hl,
                              int K2, int N) {
    int idx = blockIdx.x * 256 + threadIdx.x;
    if (idx >= K2 * N) return;
    int kp = idx / N, n = idx - kp * N;
    float x = W[(size_t)(2 * kp) * N + n];
    float y = W[(size_t)(2 * kp + 1) * N + n];
    uint32_t h, l;
    cvt2(x, y, h, l);
    Hh[idx] = h;
    Hl[idx] = l;
}

// head_w [V][D] fp32 -> [D/2][VP] uint32 (transpose + pack), pad zero-filled
__global__ void pack_head_kernel(const float* __restrict__ W,
                                 uint32_t* __restrict__ Hh, uint32_t* __restrict__ Hl) {
    __shared__ uint32_t sh[32][33], sl[32][33];
    int kp0 = blockIdx.x * 32;   // 12 blocks over D/2=384
    int n0  = blockIdx.y * 32;   // 1572 blocks over VP
    int tid = threadIdx.x;
    #pragma unroll
    for (int i = 0; i < 2; i++) {
        int f = tid + i * 256;
        int n = f >> 4, c = f & 15;     // 16 float4 per row (64 floats)
        float4 v = make_float4(0.f, 0.f, 0.f, 0.f);
        if (n0 + n < VV)
            v = *(const float4*)(W + (size_t)(n0 + n) * DD + kp0 * 2 + c * 4);
        uint32_t h0, l0, h1, l1;
        cvt2(v.x, v.y, h0, l0);
        cvt2(v.z, v.w, h1, l1);
        sh[n][2 * c] = h0; sh[n][2 * c + 1] = h1;
        sl[n][2 * c] = l0; sl[n][2 * c + 1] = l1;
    }
    __syncthreads();
    #pragma unroll
    for (int i = 0; i < 4; i++) {
        int f = tid + i * 256;
        int kp = f >> 5, n = f & 31;
        Hh[(size_t)(kp0 + kp) * VP + n0 + n] = sh[n][kp];
        Hl[(size_t)(kp0 + kp) * VP + n0 + n] = sl[n][kp];
    }
}

// ---------------- embed ----------------
__global__ void embed_kernel(const int* __restrict__ tok,
                             const float* __restrict__ wte,
                             const float* __restrict__ wpe,
                             float* __restrict__ x) {
    int n = blockIdx.x;
    int tpos = n & (TT - 1);
    int t = tok[n];
    const float* we = wte + (size_t)t * DD;
    const float* wp = wpe + (size_t)tpos * DD;
    float* xr = x + (size_t)n * DD;
    for (int i = threadIdx.x; i < DD; i += blockDim.x)
        xr[i] = we[i] + wp[i];
}

// ---------------- reductions ----------------
__device__ __forceinline__ float blk_sum(float v, float* red) {
    #pragma unroll
    for (int o = 16; o; o >>= 1) v += __shfl_xor_sync(0xffffffffu, v, o);
    int wid = threadIdx.x >> 5, lid = threadIdx.x & 31;
    if (lid == 0) red[wid] = v;
    __syncthreads();
    int nw = blockDim.x >> 5;
    float s = (threadIdx.x < nw) ? red[threadIdx.x] : 0.0f;
    #pragma unroll
    for (int o = 16; o; o >>= 1) s += __shfl_xor_sync(0xffffffffu, s, o);
    if (threadIdx.x == 0) red[0] = s;
    __syncthreads();
    s = red[0];
    __syncthreads();
    return s;
}

__device__ __forceinline__ float blk_max(float v, float* red) {
    #pragma unroll
    for (int o = 16; o; o >>= 1) v = fmaxf(v, __shfl_xor_sync(0xffffffffu, v, o));
    int wid = threadIdx.x >> 5, lid = threadIdx.x & 31;
    if (lid == 0) red[wid] = v;
    __syncthreads();
    int nw = blockDim.x >> 5;
    float s = (threadIdx.x < nw) ? red[threadIdx.x] : -1e30f;
    #pragma unroll
    for (int o = 16; o; o >>= 1) s = fmaxf(s, __shfl_xor_sync(0xffffffffu, s, o));
    if (threadIdx.x == 0) red[0] = s;
    __syncthreads();
    s = red[0];
    __syncthreads();
    return s;
}

// ---------------- layernorm ----------------
__global__ void ln_kernel(const float* __restrict__ x,
                          const float* __restrict__ w,
                          const float* __restrict__ b,
                          float* __restrict__ y) {
    __shared__ float red[32];
    int row = blockIdx.x;
    const float* xr = x + (size_t)row * DD;
    float* yr = y + (size_t)row * DD;
    float v[3];
    float s = 0.f, ss = 0.f;
    #pragma unroll
    for (int i = 0; i < 3; i++) {
        int c = threadIdx.x + i * 256;
        v[i] = xr[c];
        s += v[i];
        ss += v[i] * v[i];
    }
    s  = blk_sum(s,  red);
    ss = blk_sum(ss, red);
    float mu = s * (1.0f / DD);
    float var = ss * (1.0f / DD) - mu * mu;
    float r = rsqrtf(var + 1e-5f);
    #pragma unroll
    for (int i = 0; i < 3; i++) {
        int c = threadIdx.x + i * 256;
        yr[c] = (v[i] - mu) * r * w[c] + b[c];
    }
}

// ---------------- attention (one block per (b,h,q)) ----------------
__global__ void attn_kernel(const float* __restrict__ qkv, float* __restrict__ out) {
    __shared__ float qv[HD];
    __shared__ float sc[TT];
    __shared__ float red[32];
    __shared__ float ppart[128];

    int q = blockIdx.x;
    int h = blockIdx.y;
    int b = blockIdx.z;
    int tid = threadIdx.x;   // 128 threads

    const float* base = qkv + (size_t)b * TT * D3;
    if (tid < HD) qv[tid] = base[(size_t)q * D3 + h * HD + tid];
    __syncthreads();

    float lmax = -1e30f;
    for (int k = tid; k <= q; k += 128) {
        const float* kp = base + (size_t)k * D3 + DD + h * HD;
        float d = 0.f;
        #pragma unroll
        for (int e = 0; e < HD; e++) d += qv[e] * kp[e];
        d *= 0.125f;
        sc[k] = d;
        lmax = fmaxf(lmax, d);
    }
    float mx = blk_max(lmax, red);

    float lsum = 0.f;
    for (int k = tid; k <= q; k += 128) {
        float e = __expf(sc[k] - mx);
        sc[k] = e;
        lsum += e;
    }
    float ssum = blk_sum(lsum, red);
    float inv = 1.0f / ssum;
    __syncthreads();

    int d = tid & (HD - 1);
    int part = tid >> 6;
    float o = 0.f;
    for (int k = part; k <= q; k += 2) {
        o += sc[k] * base[(size_t)k * D3 + 2 * DD + h * HD + d];
    }
    ppart[tid] = o;
    __syncthreads();
    if (tid < HD)
        out[((size_t)b * TT + q) * DD + h * HD + tid] = (ppart[tid] + ppart[tid + HD]) * inv;
}

// ---------------- tensor-core GEMM ----------------
// C[M,N] = A[M,K] (fp32) @ W (pre-packed bf16 hi/lo, [K/2][NS] uint32)
// Block tile 128x128, BK=32, 8 warps of 64x32.
template<bool GELU, bool RESID, bool HASBIAS>
__global__ void __launch_bounds__(256, 1)
gemm_mma(const float* __restrict__ A,
         const uint32_t* __restrict__ BhG, const uint32_t* __restrict__ BlG,
         int NS,
         const float* __restrict__ bias, float* __restrict__ C,
         int M, int N, int K) {
    __shared__ uint32_t Ah[128][20], Al[128][20], Bh[128][20], Bl[128][20];

    int tid = threadIdx.x;
    int w = tid >> 5, l = tid & 31;
    int wr = w >> 2, wc = w & 3;     // warp grid 2x4
    int q = l >> 2, r = l & 3;
    int row0 = blockIdx.x * 128;
    int col0 = blockIdx.y * 128;

    float acc[4][4][4];
    #pragma unroll
    for (int mi = 0; mi < 4; mi++)
        #pragma unroll
        for (int ni = 0; ni < 4; ni++)
            #pragma unroll
            for (int e = 0; e < 4; e++) acc[mi][ni][e] = 0.f;

    for (int k0 = 0; k0 < K; k0 += 32) {
        // --- A tile: fp32 -> bf16 hi/lo, [m][kpair] ---
        #pragma unroll
        for (int i = 0; i < 4; i++) {
            int f = tid + i * 256;
            int m = f >> 3, kg = f & 7;    // 8 float4 per row (32 floats)
            float4 v = *(const float4*)(A + (size_t)(row0 + m) * K + k0 + kg * 4);
            uint32_t h0, l0, h1, l1;
            cvt2(v.x, v.y, h0, l0);
            cvt2(v.z, v.w, h1, l1);
            Ah[m][2 * kg] = h0; Ah[m][2 * kg + 1] = h1;
            Al[m][2 * kg] = l0; Al[m][2 * kg + 1] = l1;
        }
        // --- B tile: pre-packed, [n][kpair] ---
        #pragma unroll
        for (int i = 0; i < 2; i++) {
            int f = tid + i * 256;
            int kp = f >> 5, ng = f & 31;
            size_t off = (size_t)(k0 / 2 + kp) * NS + col0 + 4 * ng;
            uint4 vh = *(const uint4*)(BhG + off);
            uint4 vl = *(const uint4*)(BlG + off);
            Bh[4 * ng][kp] = vh.x; Bh[4 * ng + 1][kp] = vh.y;
            Bh[4 * ng + 2][kp] = vh.z; Bh[4 * ng + 3][kp] = vh.w;
            Bl[4 * ng][kp] = vl.x; Bl[4 * ng + 1][kp] = vl.y;
            Bl[4 * ng + 2][kp] = vl.z; Bl[4 * ng + 3][kp] = vl.w;
        }
        __syncthreads();

        #pragma unroll
        for (int s = 0; s < 2; s++) {
            int kpb = s * 8;
            uint32_t ah[4][4], al[4][4], bh[4][2], bl[4][2];
            #pragma unroll
            for (int mi = 0; mi < 4; mi++) {
                int m = wr * 64 + mi * 16;
                ah[mi][0] = Ah[m + q][kpb + r];
                ah[mi][1] = Ah[m + q + 8][kpb + r];
                ah[mi][2] = Ah[m + q][kpb + 4 + r];
                ah[mi][3] = Ah[m + q + 8][kpb + 4 + r];
                al[mi][0] = Al[m + q][kpb + r];
                al[mi][1] = Al[m + q + 8][kpb + r];
                al[mi][2] = Al[m + q][kpb + 4 + r];
                al[mi][3] = Al[m + q + 8][kpb + 4 + r];
            }
            #pragma unroll
            for (int ni = 0; ni < 4; ni++) {
                int n = wc * 32 + ni * 8;
                bh[ni][0] = Bh[n + q][kpb + r];
                bh[ni][1] = Bh[n + q][kpb + 4 + r];
                bl[ni][0] = Bl[n + q][kpb + r];
                bl[ni][1] = Bl[n + q][kpb + 4 + r];
            }
            #pragma unroll
            for (int mi = 0; mi < 4; mi++)
                #pragma unroll
                for (int ni = 0; ni < 4; ni++) {
                    mma16816(acc[mi][ni], ah[mi], bh[ni]);
                    mma16816(acc[mi][ni], ah[mi], bl[ni]);
                    mma16816(acc[mi][ni], al[mi], bh[ni]);
                }
        }
        __syncthreads();
    }

    // --- epilogue ---
    const float cg = 0.7978845608028654f;  // sqrt(2/pi)
    #pragma unroll
    for (int mi = 0; mi < 4; mi++) {
        int rbase = row0 + wr * 64 + mi * 16 + q;
        #pragma unroll
        for (int ni = 0; ni < 4; ni++) {
            int cbase = col0 + wc * 32 + ni * 8 + 2 * r;
            #pragma unroll
            for (int rg = 0; rg < 2; rg++) {
                int rr = rbase + rg * 8;
                #pragma unroll
                for (int e = 0; e < 2; e++) {
                    int cc = cbase + e;
                    if (cc < N) {
                        float v = acc[mi][ni][rg * 2 + e];
                        if (HASBIAS) v += bias[cc];
                        if (GELU) {
                            float u = cg * (v + 0.044715f * v * v * v);
                            v = 0.5f * v * (1.0f + tanhf(u));
                        }
                        size_t idx = (size_t)rr * N + cc;
                        if (RESID) v += C[idx];
                        C[idx] = v;
                    }
                }
            }
        }
    }
}

// ---------------- host ----------------
extern "C" void kernel_launch(void* const* d_in, const int* in_sizes, int n_in,
                              void* d_out, int out_size) {
    const int*   tok    = (const int*)  d_in[0];
    const float* wte    = (const float*)d_in[1];
    const float* wpe    = (const float*)d_in[2];
    const float* ln1_w  = (const float*)d_in[3];
    const float* ln1_b  = (const float*)d_in[4];
    const float* attn_w = (const float*)d_in[5];
    const float* attn_b = (const float*)d_in[6];
    const float* proj_w = (const float*)d_in[7];
    const float* proj_b = (const float*)d_in[8];
    const float* ln2_w  = (const float*)d_in[9];
    const float* ln2_b  = (const float*)d_in[10];
    const float* fc_w   = (const float*)d_in[11];
    const float* fc_b   = (const float*)d_in[12];
    const float* fc2_w  = (const float*)d_in[13];
    const float* fc2_b  = (const float*)d_in[14];
    const float* lnf_w  = (const float*)d_in[15];
    const float* lnf_b  = (const float*)d_in[16];
    const float* head_w = (const float*)d_in[17];
    float* out = (float*)d_out;

    float *x, *h, *qkv, *att, *ffn;
    cudaGetSymbolAddress((void**)&x,   g_x);
    cudaGetSymbolAddress((void**)&h,   g_h);
    cudaGetSymbolAddress((void**)&qkv, g_qkv);
    cudaGetSymbolAddress((void**)&att, g_att);
    cudaGetSymbolAddress((void**)&ffn, g_ffn);

    uint32_t *wqkv_h, *wqkv_l, *wproj_h, *wproj_l, *wfc_h, *wfc_l,
             *wfc2_h, *wfc2_l, *whead_h, *whead_l;
    cudaGetSymbolAddress((void**)&wqkv_h, g_wqkv_h);
    cudaGetSymbolAddress((void**)&wqkv_l, g_wqkv_l);
    cudaGetSymbolAddress((void**)&wproj_h, g_wproj_h);
    cudaGetSymbolAddress((void**)&wproj_l, g_wproj_l);
    cudaGetSymbolAddress((void**)&wfc_h, g_wfc_h);
    cudaGetSymbolAddress((void**)&wfc_l, g_wfc_l);
    cudaGetSymbolAddress((void**)&wfc2_h, g_wfc2_h);
    cudaGetSymbolAddress((void**)&wfc2_l, g_wfc2_l);
    cudaGetSymbolAddress((void**)&whead_h, g_whead_h);
    cudaGetSymbolAddress((void**)&whead_l, g_whead_l);

    // pack weights (stacked [L*K][N] matrices pack as one call each)
    {
        int n1 = (LL * DD / 2) * D3;
        pack_w_kernel<<<(n1 + 255) / 256, 256>>>(attn_w, wqkv_h, wqkv_l, LL * DD / 2, D3);
        int n2 = (LL * DD / 2) * DD;
        pack_w_kernel<<<(n2 + 255) / 256, 256>>>(proj_w, wproj_h, wproj_l, LL * DD / 2, DD);
        int n3 = (LL * DD / 2) * FF;
        pack_w_kernel<<<(n3 + 255) / 256, 256>>>(fc_w, wfc_h, wfc_l, LL * DD / 2, FF);
        int n4 = (LL * FF / 2) * DD;
        pack_w_kernel<<<(n4 + 255) / 256, 256>>>(fc2_w, wfc2_h, wfc2_l, LL * FF / 2, DD);
        pack_head_kernel<<<dim3(DD / 2 / 32, VP / 32), 256>>>(head_w, whead_h, whead_l);
    }

    embed_kernel<<<NT, 256>>>(tok, wte, wpe, x);

    for (int l = 0; l < LL; l++) {
        size_t oq = (size_t)l * (DD / 2) * D3;
        size_t op = (size_t)l * (DD / 2) * DD;
        size_t of = (size_t)l * (DD / 2) * FF;
        size_t o2 = (size_t)l * (FF / 2) * DD;

        ln_kernel<<<NT, 256>>>(x, ln1_w + l * DD, ln1_b + l * DD, h);
        gemm_mma<false, false, true><<<dim3(NT / 128, D3 / 128), 256>>>(
            h, wqkv_h + oq, wqkv_l + oq, D3, attn_b + l * D3, qkv, NT, D3, DD);
        attn_kernel<<<dim3(TT, HH, 2), 128>>>(qkv, att);
        gemm_mma<false, true, true><<<dim3(NT / 128, DD / 128), 256>>>(
            att, wproj_h + op, wproj_l + op, DD, proj_b + l * DD, x, NT, DD, DD);
        ln_kernel<<<NT, 256>>>(x, ln2_w + l * DD, ln2_b + l * DD, h);
        gemm_mma<true, false, true><<<dim3(NT / 128, FF / 128), 256>>>(
            h, wfc_h + of, wfc_l + of, FF, fc_b + l * FF, ffn, NT, FF, DD);
        gemm_mma<false, true, true><<<dim3(NT / 128, DD / 128), 256>>>(
            ffn, wfc2_h + o2, wfc2_l + o2, DD, fc2_b + l * DD, x, NT, DD, FF);
    }

    ln_kernel<<<NT, 256>>>(x, lnf_w, lnf_b, h);
    gemm_mma<false, false, false><<<dim3(NT / 128, (VV + 127) / 128), 256>>>(
        h, whead_h, whead_l, VP, nullptr, out, NT, VV, DD);
}

// round 3
// speedup vs baseline: 4.1429x; 3.7660x over previous
#include <cuda_runtime.h>
#include <cuda_bf16.h>
#include <math.h>
#include <stdint.h>

// GPT-2 small forward. R3:
//  - GEMMs: bf16 hi/lo 3-term MMA, cp.async double-buffered, packed-A inputs.
//  - Producers (LN / attention / GELU epilogue) emit packed bf16 hi/lo A.
//  - Attention: flash-style thread-per-query, smem-staged K/V tiles.

#define NT   2048
#define TT   1024
#define DD   768
#define FF   3072
#define HH   12
#define HD   64
#define LL   4
#define VV   50257
#define D3   2304
#define VP   50304
#define K2D  384     // DD/2
#define K2F  1536    // FF/2

// ---------------- scratch ----------------
__device__ float    g_x  [NT * DD];
__device__ float    g_qkv[NT * D3];
__device__ uint32_t g_hH [NT * K2D],  g_hL [NT * K2D];
__device__ uint32_t g_atH[NT * K2D],  g_atL[NT * K2D];
__device__ uint32_t g_ffH[NT * K2F],  g_ffL[NT * K2F];

__device__ uint32_t g_wqkv_h[LL * K2D * D3], g_wqkv_l[LL * K2D * D3];
__device__ uint32_t g_wprj_h[LL * K2D * DD], g_wprj_l[LL * K2D * DD];
__device__ uint32_t g_wfc_h [LL * K2D * FF], g_wfc_l [LL * K2D * FF];
__device__ uint32_t g_wfc2_h[LL * K2F * DD], g_wfc2_l[LL * K2F * DD];
__device__ uint32_t g_whd_h [K2D * VP],      g_whd_l [K2D * VP];

// ---------------- helpers ----------------
__device__ __forceinline__ void cvt2(float x, float y, uint32_t& hi, uint32_t& lo) {
    __nv_bfloat16 hx = __float2bfloat16(x);
    __nv_bfloat16 hy = __float2bfloat16(y);
    __nv_bfloat16 lx = __float2bfloat16(x - __bfloat162float(hx));
    __nv_bfloat16 ly = __float2bfloat16(y - __bfloat162float(hy));
    hi = ((uint32_t)__bfloat16_as_ushort(hy) << 16) | (uint32_t)__bfloat16_as_ushort(hx);
    lo = ((uint32_t)__bfloat16_as_ushort(ly) << 16) | (uint32_t)__bfloat16_as_ushort(lx);
}

__device__ __forceinline__ void mma16816(float* c, const uint32_t* a, const uint32_t* b) {
    asm volatile(
        "mma.sync.aligned.m16n8k16.row.col.f32.bf16.bf16.f32 "
        "{%0,%1,%2,%3}, {%4,%5,%6,%7}, {%8,%9}, {%0,%1,%2,%3};\n"
        : "+f"(c[0]), "+f"(c[1]), "+f"(c[2]), "+f"(c[3])
        : "r"(a[0]), "r"(a[1]), "r"(a[2]), "r"(a[3]), "r"(b[0]), "r"(b[1]));
}

__device__ __forceinline__ void cpa16(void* dst, const void* src) {
    uint32_t d = (uint32_t)__cvta_generic_to_shared(dst);
    asm volatile("cp.async.cg.shared.global [%0], [%1], 16;\n" :: "r"(d), "l"(src));
}

// ---------------- weight packing ----------------
__global__ void pack_w_kernel(const float* __restrict__ W,
                              uint32_t* __restrict__ Hh, uint32_t* __restrict__ Hl,
                              int K2, int N) {
    int idx = blockIdx.x * 256 + threadIdx.x;
    if (idx >= K2 * N) return;
    int kp = idx / N, n = idx - kp * N;
    float x = W[(size_t)(2 * kp) * N + n];
    float y = W[(size_t)(2 * kp + 1) * N + n];
    uint32_t h, l;
    cvt2(x, y, h, l);
    Hh[idx] = h;
    Hl[idx] = l;
}

__global__ void pack_head_kernel(const float* __restrict__ W,
                                 uint32_t* __restrict__ Hh, uint32_t* __restrict__ Hl) {
    __shared__ uint32_t sh[32][33], sl[32][33];
    int kp0 = blockIdx.x * 32;
    int n0  = blockIdx.y * 32;
    int tid = threadIdx.x;
    #pragma unroll
    for (int i = 0; i < 2; i++) {
        int f = tid + i * 256;
        int n = f >> 4, c = f & 15;
        float4 v = make_float4(0.f, 0.f, 0.f, 0.f);
        if (n0 + n < VV)
            v = *(const float4*)(W + (size_t)(n0 + n) * DD + kp0 * 2 + c * 4);
        uint32_t h0, l0, h1, l1;
        cvt2(v.x, v.y, h0, l0);
        cvt2(v.z, v.w, h1, l1);
        sh[n][2 * c] = h0; sh[n][2 * c + 1] = h1;
        sl[n][2 * c] = l0; sl[n][2 * c + 1] = l1;
    }
    __syncthreads();
    #pragma unroll
    for (int i = 0; i < 4; i++) {
        int f = tid + i * 256;
        int kp = f >> 5, n = f & 31;
        Hh[(size_t)(kp0 + kp) * VP + n0 + n] = sh[n][kp];
        Hl[(size_t)(kp0 + kp) * VP + n0 + n] = sl[n][kp];
    }
}

// ---------------- embed ----------------
__global__ void embed_kernel(const int* __restrict__ tok,
                             const float* __restrict__ wte,
                             const float* __restrict__ wpe,
                             float* __restrict__ x) {
    int n = blockIdx.x;
    int tpos = n & (TT - 1);
    int t = tok[n];
    const float* we = wte + (size_t)t * DD;
    const float* wp = wpe + (size_t)tpos * DD;
    float* xr = x + (size_t)n * DD;
    for (int i = threadIdx.x; i < DD; i += blockDim.x)
        xr[i] = we[i] + wp[i];
}

// ---------------- reductions ----------------
__device__ __forceinline__ float blk_sum(float v, float* red) {
    #pragma unroll
    for (int o = 16; o; o >>= 1) v += __shfl_xor_sync(0xffffffffu, v, o);
    int wid = threadIdx.x >> 5, lid = threadIdx.x & 31;
    if (lid == 0) red[wid] = v;
    __syncthreads();
    float s = (threadIdx.x < 8) ? red[threadIdx.x] : 0.0f;
    #pragma unroll
    for (int o = 4; o; o >>= 1) s += __shfl_xor_sync(0xffffffffu, s, o);
    if (threadIdx.x == 0) red[0] = s;
    __syncthreads();
    s = red[0];
    __syncthreads();
    return s;
}

// ---------------- layernorm -> packed hi/lo ----------------
__global__ void ln_pack(const float* __restrict__ x,
                        const float* __restrict__ w,
                        const float* __restrict__ b,
                        uint32_t* __restrict__ PH, uint32_t* __restrict__ PL) {
    __shared__ float vb[DD];
    __shared__ float red[32];
    int row = blockIdx.x;
    const float* xr = x + (size_t)row * DD;
    float v[3];
    float s = 0.f, ss = 0.f;
    #pragma unroll
    for (int i = 0; i < 3; i++) {
        int c = threadIdx.x + i * 256;
        v[i] = xr[c];
        s += v[i];
        ss += v[i] * v[i];
    }
    s  = blk_sum(s,  red);
    ss = blk_sum(ss, red);
    float mu = s * (1.0f / DD);
    float var = ss * (1.0f / DD) - mu * mu;
    float r = rsqrtf(var + 1e-5f);
    #pragma unroll
    for (int i = 0; i < 3; i++) {
        int c = threadIdx.x + i * 256;
        vb[c] = (v[i] - mu) * r * w[c] + b[c];
    }
    __syncthreads();
    #pragma unroll
    for (int i = 0; i < 2; i++) {
        int p = threadIdx.x + i * 256;
        if (p < K2D) {
            uint32_t hh, ll;
            cvt2(vb[2 * p], vb[2 * p + 1], hh, ll);
            PH[(size_t)row * K2D + p] = hh;
            PL[(size_t)row * K2D + p] = ll;
        }
    }
}

// ---------------- attention: thread-per-query flash ----------------
// grid (TT/128, H, B), 128 threads. smem: Ks[64*64], Vs[64*64], sc[64*128]
__global__ void __launch_bounds__(128)
attn_kernel(const float* __restrict__ qkv,
            uint32_t* __restrict__ attH, uint32_t* __restrict__ attL) {
    extern __shared__ __align__(16) unsigned sm_dyn[];
    float* Ks = (float*)sm_dyn;
    float* Vs = Ks + 4096;
    float* sc = Vs + 4096;

    int tid = threadIdx.x;
    int qt = blockIdx.x, h = blockIdx.y, b = blockIdx.z;
    int qpos = qt * 128 + tid;
    const float* base = qkv + (size_t)b * TT * D3;

    float qreg[64];
    #pragma unroll
    for (int e = 0; e < 64; e++) qreg[e] = base[(size_t)qpos * D3 + h * HD + e];
    float o[64];
    #pragma unroll
    for (int d = 0; d < 64; d++) o[d] = 0.f;
    float m = -1e30f, ssum = 0.f;

    int nkt = (qt + 1) * 2;
    for (int kt = 0; kt < nkt; kt++) {
        int k0 = kt * 64;
        __syncthreads();
        #pragma unroll
        for (int i = 0; i < 32; i++) {
            int idx = i * 128 + tid;
            int kk = idx >> 6, e = idx & 63;
            Ks[idx] = base[(size_t)(k0 + kk) * D3 + DD + h * HD + e];
            Vs[idx] = base[(size_t)(k0 + kk) * D3 + 2 * DD + h * HD + e];
        }
        __syncthreads();

        float tm = -1e30f;
        for (int kk = 0; kk < 64; kk++) {
            float s0 = 0.f, s1 = 0.f, s2 = 0.f, s3 = 0.f;
            const float* kr = Ks + kk * 64;
            #pragma unroll
            for (int e = 0; e < 64; e += 4) {
                s0 += qreg[e]     * kr[e];
                s1 += qreg[e + 1] * kr[e + 1];
                s2 += qreg[e + 2] * kr[e + 2];
                s3 += qreg[e + 3] * kr[e + 3];
            }
            float sv = ((s0 + s1) + (s2 + s3)) * 0.125f;
            if (k0 + kk > qpos) sv = -1e30f;
            sc[kk * 128 + tid] = sv;
            tm = fmaxf(tm, sv);
        }
        float mn = fmaxf(m, tm);
        float cr = __expf(m - mn);
        m = mn;
        ssum *= cr;
        #pragma unroll
        for (int d = 0; d < 64; d++) o[d] *= cr;
        for (int kk = 0; kk < 64; kk++) {
            float p = __expf(sc[kk * 128 + tid] - m);
            ssum += p;
            const float* vr = Vs + kk * 64;
            #pragma unroll
            for (int d = 0; d < 64; d++) o[d] += p * vr[d];
        }
    }

    float inv = 1.0f / ssum;
    size_t row = (size_t)b * TT + qpos;
    #pragma unroll
    for (int t2 = 0; t2 < 32; t2++) {
        uint32_t hh, ll;
        cvt2(o[2 * t2] * inv, o[2 * t2 + 1] * inv, hh, ll);
        attH[row * K2D + h * 32 + t2] = hh;
        attL[row * K2D + h * 32 + t2] = ll;
    }
}

// ---------------- tensor-core GEMM (cp.async double-buffered) --------
// A packed [M][K/2] uint32 hi/lo; B packed [K/2][NS] uint32 hi/lo.
// Block 128x128, BK=32, 8 warps of 64x32. EPI: 0=store fp32, 1=resid fp32,
// 2=GELU -> packed hi/lo.
#define SA_H(buf,m,k) ((buf)*2560 + (m)*20 + (k))
#define SA_L(buf,m,k) (5120 + (buf)*2560 + (m)*20 + (k))
#define SB_H(buf,kp,n) (10240 + (buf)*2176 + (kp)*136 + (n))
#define SB_L(buf,kp,n) (14592 + (buf)*2176 + (kp)*136 + (n))
#define GEMM_SMEM (18944 * 4)

template<int EPI, bool HASBIAS>
__global__ void __launch_bounds__(256, 1)
gemm_mma(const uint32_t* __restrict__ AhG, const uint32_t* __restrict__ AlG,
         const uint32_t* __restrict__ BhG, const uint32_t* __restrict__ BlG,
         int NS, const float* __restrict__ bias, float* __restrict__ C,
         uint32_t* __restrict__ PH, uint32_t* __restrict__ PL,
         int N, int K) {
    extern __shared__ __align__(16) unsigned sm_dyn[];
    uint32_t* sm = (uint32_t*)sm_dyn;
    const int K2 = K >> 1;
    int tid = threadIdx.x;
    int w = tid >> 5, l = tid & 31;
    int wr = w >> 2, wc = w & 3;
    int q = l >> 2, r = l & 3;
    int row0 = blockIdx.x * 128;
    int col0 = blockIdx.y * 128;

    float acc[4][4][4];
    #pragma unroll
    for (int mi = 0; mi < 4; mi++)
        #pragma unroll
        for (int ni = 0; ni < 4; ni++)
            #pragma unroll
            for (int e = 0; e < 4; e++) acc[mi][ni][e] = 0.f;

    auto loadtile = [&](int t, int buf) {
        int kp0 = t * 16;
        #pragma unroll
        for (int i = 0; i < 2; i++) {
            int c = tid + i * 256;
            int rowm = c >> 2, part = c & 3;
            size_t off = (size_t)(row0 + rowm) * K2 + kp0 + part * 4;
            cpa16(&sm[SA_H(buf, rowm, part * 4)], AhG + off);
            cpa16(&sm[SA_L(buf, rowm, part * 4)], AlG + off);
        }
        #pragma unroll
        for (int i = 0; i < 2; i++) {
            int c = tid + i * 256;
            int br = c >> 5, part = c & 31;
            size_t off = (size_t)(kp0 + br) * NS + col0 + part * 4;
            cpa16(&sm[SB_H(buf, br, part * 4)], BhG + off);
            cpa16(&sm[SB_L(buf, br, part * 4)], BlG + off);
        }
    };

    int ntile = K >> 5;
    loadtile(0, 0);
    asm volatile("cp.async.commit_group;");
    for (int t = 0; t < ntile; t++) {
        int buf = t & 1;
        if (t + 1 < ntile) {
            loadtile(t + 1, buf ^ 1);
            asm volatile("cp.async.commit_group;");
            asm volatile("cp.async.wait_group 1;");
        } else {
            asm volatile("cp.async.wait_group 0;");
        }
        __syncthreads();

        #pragma unroll
        for (int s = 0; s < 2; s++) {
            int kpb = s * 8;
            uint32_t ah[4][4], al[4][4], bh[4][2], bl[4][2];
            #pragma unroll
            for (int mi = 0; mi < 4; mi++) {
                int mm = wr * 64 + mi * 16;
                ah[mi][0] = sm[SA_H(buf, mm + q,     kpb + r)];
                ah[mi][1] = sm[SA_H(buf, mm + q + 8, kpb + r)];
                ah[mi][2] = sm[SA_H(buf, mm + q,     kpb + 4 + r)];
                ah[mi][3] = sm[SA_H(buf, mm + q + 8, kpb + 4 + r)];
                al[mi][0] = sm[SA_L(buf, mm + q,     kpb + r)];
                al[mi][1] = sm[SA_L(buf, mm + q + 8, kpb + r)];
                al[mi][2] = sm[SA_L(buf, mm + q,     kpb + 4 + r)];
                al[mi][3] = sm[SA_L(buf, mm + q + 8, kpb + 4 + r)];
            }
            #pragma unroll
            for (int ni = 0; ni < 4; ni++) {
                int nn = wc * 32 + ni * 8 + q;
                bh[ni][0] = sm[SB_H(buf, kpb + r,     nn)];
                bh[ni][1] = sm[SB_H(buf, kpb + 4 + r, nn)];
                bl[ni][0] = sm[SB_L(buf, kpb + r,     nn)];
                bl[ni][1] = sm[SB_L(buf, kpb + 4 + r, nn)];
            }
            #pragma unroll
            for (int mi = 0; mi < 4; mi++)
                #pragma unroll
                for (int ni = 0; ni < 4; ni++) {
                    mma16816(acc[mi][ni], ah[mi], bh[ni]);
                    mma16816(acc[mi][ni], ah[mi], bl[ni]);
                    mma16816(acc[mi][ni], al[mi], bh[ni]);
                }
        }
        __syncthreads();
    }

    const float cg = 0.7978845608028654f;
    #pragma unroll
    for (int mi = 0; mi < 4; mi++) {
        int rbase = row0 + wr * 64 + mi * 16 + q;
        #pragma unroll
        for (int ni = 0; ni < 4; ni++) {
            int cbase = col0 + wc * 32 + ni * 8 + 2 * r;
            #pragma unroll
            for (int rg = 0; rg < 2; rg++) {
                int rr = rbase + rg * 8;
                float v0 = acc[mi][ni][rg * 2 + 0];
                float v1 = acc[mi][ni][rg * 2 + 1];
                if (HASBIAS) { v0 += bias[cbase]; v1 += bias[cbase + 1]; }
                if (EPI == 2) {
                    float u0 = cg * (v0 + 0.044715f * v0 * v0 * v0);
                    v0 = 0.5f * v0 * (1.0f + tanhf(u0));
                    float u1 = cg * (v1 + 0.044715f * v1 * v1 * v1);
                    v1 = 0.5f * v1 * (1.0f + tanhf(u1));
                    uint32_t hh, ll;
                    cvt2(v0, v1, hh, ll);
                    size_t pidx = (size_t)rr * (N >> 1) + (cbase >> 1);
                    PH[pidx] = hh;
                    PL[pidx] = ll;
                } else {
                    size_t idx = (size_t)rr * N + cbase;
                    if (cbase < N) {
                        if (EPI == 1) v0 += C[idx];
                        C[idx] = v0;
                    }
                    if (cbase + 1 < N) {
                        if (EPI == 1) v1 += C[idx + 1];
                        C[idx + 1] = v1;
                    }
                }
            }
        }
    }
}

// ---------------- host ----------------
extern "C" void kernel_launch(void* const* d_in, const int* in_sizes, int n_in,
                              void* d_out, int out_size) {
    const int*   tok    = (const int*)  d_in[0];
    const float* wte    = (const float*)d_in[1];
    const float* wpe    = (const float*)d_in[2];
    const float* ln1_w  = (const float*)d_in[3];
    const float* ln1_b  = (const float*)d_in[4];
    const float* attn_w = (const float*)d_in[5];
    const float* attn_b = (const float*)d_in[6];
    const float* proj_w = (const float*)d_in[7];
    const float* proj_b = (const float*)d_in[8];
    const float* ln2_w  = (const float*)d_in[9];
    const float* ln2_b  = (const float*)d_in[10];
    const float* fc_w   = (const float*)d_in[11];
    const float* fc_b   = (const float*)d_in[12];
    const float* fc2_w  = (const float*)d_in[13];
    const float* fc2_b  = (const float*)d_in[14];
    const float* lnf_w  = (const float*)d_in[15];
    const float* lnf_b  = (const float*)d_in[16];
    const float* head_w = (const float*)d_in[17];
    float* out = (float*)d_out;

    float *x, *qkv;
    uint32_t *hH, *hL, *atH, *atL, *ffH, *ffL;
    cudaGetSymbolAddress((void**)&x,   g_x);
    cudaGetSymbolAddress((void**)&qkv, g_qkv);
    cudaGetSymbolAddress((void**)&hH,  g_hH);
    cudaGetSymbolAddress((void**)&hL,  g_hL);
    cudaGetSymbolAddress((void**)&atH, g_atH);
    cudaGetSymbolAddress((void**)&atL, g_atL);
    cudaGetSymbolAddress((void**)&ffH, g_ffH);
    cudaGetSymbolAddress((void**)&ffL, g_ffL);

    uint32_t *wq_h, *wq_l, *wp_h, *wp_l, *wf_h, *wf_l, *w2_h, *w2_l, *wh_h, *wh_l;
    cudaGetSymbolAddress((void**)&wq_h, g_wqkv_h);
    cudaGetSymbolAddress((void**)&wq_l, g_wqkv_l);
    cudaGetSymbolAddress((void**)&wp_h, g_wprj_h);
    cudaGetSymbolAddress((void**)&wp_l, g_wprj_l);
    cudaGetSymbolAddress((void**)&wf_h, g_wfc_h);
    cudaGetSymbolAddress((void**)&wf_l, g_wfc_l);
    cudaGetSymbolAddress((void**)&w2_h, g_wfc2_h);
    cudaGetSymbolAddress((void**)&w2_l, g_wfc2_l);
    cudaGetSymbolAddress((void**)&wh_h, g_whd_h);
    cudaGetSymbolAddress((void**)&wh_l, g_whd_l);

    cudaFuncSetAttribute(gemm_mma<0, true>,  cudaFuncAttributeMaxDynamicSharedMemorySize, GEMM_SMEM);
    cudaFuncSetAttribute(gemm_mma<1, true>,  cudaFuncAttributeMaxDynamicSharedMemorySize, GEMM_SMEM);
    cudaFuncSetAttribute(gemm_mma<2, true>,  cudaFuncAttributeMaxDynamicSharedMemorySize, GEMM_SMEM);
    cudaFuncSetAttribute(gemm_mma<0, false>, cudaFuncAttributeMaxDynamicSharedMemorySize, GEMM_SMEM);
    cudaFuncSetAttribute(attn_kernel,        cudaFuncAttributeMaxDynamicSharedMemorySize, 65536);

    // pack weights
    {
        int n1 = (LL * K2D) * D3;
        pack_w_kernel<<<(n1 + 255) / 256, 256>>>(attn_w, wq_h, wq_l, LL * K2D, D3);
        int n2 = (LL * K2D) * DD;
        pack_w_kernel<<<(n2 + 255) / 256, 256>>>(proj_w, wp_h, wp_l, LL * K2D, DD);
        int n3 = (LL * K2D) * FF;
        pack_w_kernel<<<(n3 + 255) / 256, 256>>>(fc_w, wf_h, wf_l, LL * K2D, FF);
        int n4 = (LL * K2F) * DD;
        pack_w_kernel<<<(n4 + 255) / 256, 256>>>(fc2_w, w2_h, w2_l, LL * K2F, DD);
        pack_head_kernel<<<dim3(K2D / 32, VP / 32), 256>>>(head_w, wh_h, wh_l);
    }

    embed_kernel<<<NT, 256>>>(tok, wte, wpe, x);

    for (int l = 0; l < LL; l++) {
        size_t oq = (size_t)l * K2D * D3;
        size_t op = (size_t)l * K2D * DD;
        size_t of = (size_t)l * K2D * FF;
        size_t o2 = (size_t)l * K2F * DD;

        ln_pack<<<NT, 256>>>(x, ln1_w + l * DD, ln1_b + l * DD, hH, hL);
        gemm_mma<0, true><<<dim3(NT / 128, D3 / 128), 256, GEMM_SMEM>>>(
            hH, hL, wq_h + oq, wq_l + oq, D3, attn_b + l * D3, qkv,
            nullptr, nullptr, D3, DD);
        attn_kernel<<<dim3(TT / 128, HH, 2), 128, 65536>>>(qkv, atH, atL);
        gemm_mma<1, true><<<dim3(NT / 128, DD / 128), 256, GEMM_SMEM>>>(
            atH, atL, wp_h + op, wp_l + op, DD, proj_b + l * DD, x,
            nullptr, nullptr, DD, DD);
        ln_pack<<<NT, 256>>>(x, ln2_w + l * DD, ln2_b + l * DD, hH, hL);
        gemm_mma<2, true><<<dim3(NT / 128, FF / 128), 256, GEMM_SMEM>>>(
            hH, hL, wf_h + of, wf_l + of, FF, fc_b + l * FF, nullptr,
            ffH, ffL, FF, DD);
        gemm_mma<1, true><<<dim3(NT / 128, DD / 128), 256, GEMM_SMEM>>>(
            ffH, ffL, w2_h + o2, w2_l + o2, DD, fc2_b + l * DD, x,
            nullptr, nullptr, DD, FF);
    }

    ln_pack<<<NT, 256>>>(x, lnf_w, lnf_b, hH, hL);
    gemm_mma<0, false><<<dim3(NT / 128, (VV + 127) / 128), 256, GEMM_SMEM>>>(
        hH, hL, wh_h, wh_l, VP, nullptr, out, nullptr, nullptr, VV, DD);
}

// round 4
// speedup vs baseline: 4.1585x; 1.0037x over previous
#include <cuda_runtime.h>
#include <cuda_bf16.h>
#include <math.h>
#include <stdint.h>

// GPT-2 small forward. R3:
//  - GEMMs: bf16 hi/lo 3-term MMA, cp.async double-buffered, packed-A inputs.
//  - Producers (LN / attention / GELU epilogue) emit packed bf16 hi/lo A.
//  - Attention: flash-style thread-per-query, smem-staged K/V tiles.

#define NT   2048
#define TT   1024
#define DD   768
#define FF   3072
#define HH   12
#define HD   64
#define LL   4
#define VV   50257
#define D3   2304
#define VP   50304
#define K2D  384     // DD/2
#define K2F  1536    // FF/2

// ---------------- scratch ----------------
__device__ float    g_x  [NT * DD];
__device__ float    g_qkv[NT * D3];
__device__ uint32_t g_hH [NT * K2D],  g_hL [NT * K2D];
__device__ uint32_t g_atH[NT * K2D],  g_atL[NT * K2D];
__device__ uint32_t g_ffH[NT * K2F],  g_ffL[NT * K2F];

__device__ uint32_t g_wqkv_h[LL * K2D * D3], g_wqkv_l[LL * K2D * D3];
__device__ uint32_t g_wprj_h[LL * K2D * DD], g_wprj_l[LL * K2D * DD];
__device__ uint32_t g_wfc_h [LL * K2D * FF], g_wfc_l [LL * K2D * FF];
__device__ uint32_t g_wfc2_h[LL * K2F * DD], g_wfc2_l[LL * K2F * DD];
__device__ uint32_t g_whd_h [K2D * VP],      g_whd_l [K2D * VP];

// ---------------- helpers ----------------
__device__ __forceinline__ void cvt2(float x, float y, uint32_t& hi, uint32_t& lo) {
    __nv_bfloat16 hx = __float2bfloat16(x);
    __nv_bfloat16 hy = __float2bfloat16(y);
    __nv_bfloat16 lx = __float2bfloat16(x - __bfloat162float(hx));
    __nv_bfloat16 ly = __float2bfloat16(y - __bfloat162float(hy));
    hi = ((uint32_t)__bfloat16_as_ushort(hy) << 16) | (uint32_t)__bfloat16_as_ushort(hx);
    lo = ((uint32_t)__bfloat16_as_ushort(ly) << 16) | (uint32_t)__bfloat16_as_ushort(lx);
}

__device__ __forceinline__ void mma16816(float* c, const uint32_t* a, const uint32_t* b) {
    asm volatile(
        "mma.sync.aligned.m16n8k16.row.col.f32.bf16.bf16.f32 "
        "{%0,%1,%2,%3}, {%4,%5,%6,%7}, {%8,%9}, {%0,%1,%2,%3};\n"
        : "+f"(c[0]), "+f"(c[1]), "+f"(c[2]), "+f"(c[3])
        : "r"(a[0]), "r"(a[1]), "r"(a[2]), "r"(a[3]), "r"(b[0]), "r"(b[1]));
}

__device__ __forceinline__ void cpa16(void* dst, const void* src) {
    uint32_t d = (uint32_t)__cvta_generic_to_shared(dst);
    asm volatile("cp.async.cg.shared.global [%0], [%1], 16;\n" :: "r"(d), "l"(src));
}

// ---------------- weight packing ----------------
__global__ void pack_w_kernel(const float* __restrict__ W,
                              uint32_t* __restrict__ Hh, uint32_t* __restrict__ Hl,
                              int K2, int N) {
    int idx = blockIdx.x * 256 + threadIdx.x;
    if (idx >= K2 * N) return;
    int kp = idx / N, n = idx - kp * N;
    float x = W[(size_t)(2 * kp) * N + n];
    float y = W[(size_t)(2 * kp + 1) * N + n];
    uint32_t h, l;
    cvt2(x, y, h, l);
    Hh[idx] = h;
    Hl[idx] = l;
}

__global__ void pack_head_kernel(const float* __restrict__ W,
                                 uint32_t* __restrict__ Hh, uint32_t* __restrict__ Hl) {
    __shared__ uint32_t sh[32][33], sl[32][33];
    int kp0 = blockIdx.x * 32;
    int n0  = blockIdx.y * 32;
    int tid = threadIdx.x;
    #pragma unroll
    for (int i = 0; i < 2; i++) {
        int f = tid + i * 256;
        int n = f >> 4, c = f & 15;
        float4 v = make_float4(0.f, 0.f, 0.f, 0.f);
        if (n0 + n < VV)
            v = *(const float4*)(W + (size_t)(n0 + n) * DD + kp0 * 2 + c * 4);
        uint32_t h0, l0, h1, l1;
        cvt2(v.x, v.y, h0, l0);
        cvt2(v.z, v.w, h1, l1);
        sh[n][2 * c] = h0; sh[n][2 * c + 1] = h1;
        sl[n][2 * c] = l0; sl[n][2 * c + 1] = l1;
    }
    __syncthreads();
    #pragma unroll
    for (int i = 0; i < 4; i++) {
        int f = tid + i * 256;
        int kp = f >> 5, n = f & 31;
        Hh[(size_t)(kp0 + kp) * VP + n0 + n] = sh[n][kp];
        Hl[(size_t)(kp0 + kp) * VP + n0 + n] = sl[n][kp];
    }
}

// ---------------- embed ----------------
__global__ void embed_kernel(const int* __restrict__ tok,
                             const float* __restrict__ wte,
                             const float* __restrict__ wpe,
                             float* __restrict__ x) {
    int n = blockIdx.x;
    int tpos = n & (TT - 1);
    int t = tok[n];
    const float* we = wte + (size_t)t * DD;
    const float* wp = wpe + (size_t)tpos * DD;
    float* xr = x + (size_t)n * DD;
    for (int i = threadIdx.x; i < DD; i += blockDim.x)
        xr[i] = we[i] + wp[i];
}

// ---------------- reductions ----------------
__device__ __forceinline__ float blk_sum(float v, float* red) {
    #pragma unroll
    for (int o = 16; o; o >>= 1) v += __shfl_xor_sync(0xffffffffu, v, o);
    int wid = threadIdx.x >> 5, lid = threadIdx.x & 31;
    if (lid == 0) red[wid] = v;
    __syncthreads();
    float s = (threadIdx.x < 8) ? red[threadIdx.x] : 0.0f;
    #pragma unroll
    for (int o = 4; o; o >>= 1) s += __shfl_xor_sync(0xffffffffu, s, o);
    if (threadIdx.x == 0) red[0] = s;
    __syncthreads();
    s = red[0];
    __syncthreads();
    return s;
}

// ---------------- layernorm -> packed hi/lo ----------------
__global__ void ln_pack(const float* __restrict__ x,
                        const float* __restrict__ w,
                        const float* __restrict__ b,
                        uint32_t* __restrict__ PH, uint32_t* __restrict__ PL) {
    __shared__ float vb[DD];
    __shared__ float red[32];
    int row = blockIdx.x;
    const float* xr = x + (size_t)row * DD;
    float v[3];
    float s = 0.f, ss = 0.f;
    #pragma unroll
    for (int i = 0; i < 3; i++) {
        int c = threadIdx.x + i * 256;
        v[i] = xr[c];
        s += v[i];
        ss += v[i] * v[i];
    }
    s  = blk_sum(s,  red);
    ss = blk_sum(ss, red);
    float mu = s * (1.0f / DD);
    float var = ss * (1.0f / DD) - mu * mu;
    float r = rsqrtf(var + 1e-5f);
    #pragma unroll
    for (int i = 0; i < 3; i++) {
        int c = threadIdx.x + i * 256;
        vb[c] = (v[i] - mu) * r * w[c] + b[c];
    }
    __syncthreads();
    #pragma unroll
    for (int i = 0; i < 2; i++) {
        int p = threadIdx.x + i * 256;
        if (p < K2D) {
            uint32_t hh, ll;
            cvt2(vb[2 * p], vb[2 * p + 1], hh, ll);
            PH[(size_t)row * K2D + p] = hh;
            PL[(size_t)row * K2D + p] = ll;
        }
    }
}

// ---------------- attention: thread-per-query flash ----------------
// grid (TT/128, H, B), 128 threads. smem: Ks[64*64], Vs[64*64], sc[64*128]
__global__ void __launch_bounds__(128)
attn_kernel(const float* __restrict__ qkv,
            uint32_t* __restrict__ attH, uint32_t* __restrict__ attL) {
    extern __shared__ __align__(16) unsigned sm_dyn[];
    float* Ks = (float*)sm_dyn;
    float* Vs = Ks + 4096;
    float* sc = Vs + 4096;

    int tid = threadIdx.x;
    int qt = blockIdx.x, h = blockIdx.y, b = blockIdx.z;
    int qpos = qt * 128 + tid;
    const float* base = qkv + (size_t)b * TT * D3;

    float qreg[64];
    #pragma unroll
    for (int e = 0; e < 64; e++) qreg[e] = base[(size_t)qpos * D3 + h * HD + e];
    float o[64];
    #pragma unroll
    for (int d = 0; d < 64; d++) o[d] = 0.f;
    float m = -1e30f, ssum = 0.f;

    int nkt = (qt + 1) * 2;
    for (int kt = 0; kt < nkt; kt++) {
        int k0 = kt * 64;
        __syncthreads();
        #pragma unroll
        for (int i = 0; i < 32; i++) {
            int idx = i * 128 + tid;
            int kk = idx >> 6, e = idx & 63;
            Ks[idx] = base[(size_t)(k0 + kk) * D3 + DD + h * HD + e];
            Vs[idx] = base[(size_t)(k0 + kk) * D3 + 2 * DD + h * HD + e];
        }
        __syncthreads();

        float tm = -1e30f;
        for (int kk = 0; kk < 64; kk++) {
            float s0 = 0.f, s1 = 0.f, s2 = 0.f, s3 = 0.f;
            const float* kr = Ks + kk * 64;
            #pragma unroll
            for (int e = 0; e < 64; e += 4) {
                s0 += qreg[e]     * kr[e];
                s1 += qreg[e + 1] * kr[e + 1];
                s2 += qreg[e + 2] * kr[e + 2];
                s3 += qreg[e + 3] * kr[e + 3];
            }
            float sv = ((s0 + s1) + (s2 + s3)) * 0.125f;
            if (k0 + kk > qpos) sv = -1e30f;
            sc[kk * 128 + tid] = sv;
            tm = fmaxf(tm, sv);
        }
        float mn = fmaxf(m, tm);
        float cr = __expf(m - mn);
        m = mn;
        ssum *= cr;
        #pragma unroll
        for (int d = 0; d < 64; d++) o[d] *= cr;
        for (int kk = 0; kk < 64; kk++) {
            float p = __expf(sc[kk * 128 + tid] - m);
            ssum += p;
            const float* vr = Vs + kk * 64;
            #pragma unroll
            for (int d = 0; d < 64; d++) o[d] += p * vr[d];
        }
    }

    float inv = 1.0f / ssum;
    size_t row = (size_t)b * TT + qpos;
    #pragma unroll
    for (int t2 = 0; t2 < 32; t2++) {
        uint32_t hh, ll;
        cvt2(o[2 * t2] * inv, o[2 * t2 + 1] * inv, hh, ll);
        attH[row * K2D + h * 32 + t2] = hh;
        attL[row * K2D + h * 32 + t2] = ll;
    }
}

// ---------------- tensor-core GEMM (cp.async double-buffered) --------
// A packed [M][K/2] uint32 hi/lo; B packed [K/2][NS] uint32 hi/lo.
// Block 128x128, BK=32, 8 warps of 64x32. EPI: 0=store fp32, 1=resid fp32,
// 2=GELU -> packed hi/lo.
#define SA_H(buf,m,k) ((buf)*2560 + (m)*20 + (k))
#define SA_L(buf,m,k) (5120 + (buf)*2560 + (m)*20 + (k))
#define SB_H(buf,kp,n) (10240 + (buf)*2176 + (kp)*136 + (n))
#define SB_L(buf,kp,n) (14592 + (buf)*2176 + (kp)*136 + (n))
#define GEMM_SMEM (18944 * 4)

template<int EPI, bool HASBIAS>
__global__ void __launch_bounds__(256, 1)
gemm_mma(const uint32_t* __restrict__ AhG, const uint32_t* __restrict__ AlG,
         const uint32_t* __restrict__ BhG, const uint32_t* __restrict__ BlG,
         int NS, const float* __restrict__ bias, float* __restrict__ C,
         uint32_t* __restrict__ PH, uint32_t* __restrict__ PL,
         int N, int K) {
    extern __shared__ __align__(16) unsigned sm_dyn[];
    uint32_t* sm = (uint32_t*)sm_dyn;
    const int K2 = K >> 1;
    int tid = threadIdx.x;
    int w = tid >> 5, l = tid & 31;
    int wr = w >> 2, wc = w & 3;
    int q = l >> 2, r = l & 3;
    int row0 = blockIdx.x * 128;
    int col0 = blockIdx.y * 128;

    float acc[4][4][4];
    #pragma unroll
    for (int mi = 0; mi < 4; mi++)
        #pragma unroll
        for (int ni = 0; ni < 4; ni++)
            #pragma unroll
            for (int e = 0; e < 4; e++) acc[mi][ni][e] = 0.f;

    auto loadtile = [&](int t, int buf) {
        int kp0 = t * 16;
        #pragma unroll
        for (int i = 0; i < 2; i++) {
            int c = tid + i * 256;
            int rowm = c >> 2, part = c & 3;
            size_t off = (size_t)(row0 + rowm) * K2 + kp0 + part * 4;
            cpa16(&sm[SA_H(buf, rowm, part * 4)], AhG + off);
            cpa16(&sm[SA_L(buf, rowm, part * 4)], AlG + off);
        }
        #pragma unroll
        for (int i = 0; i < 2; i++) {
            int c = tid + i * 256;
            int br = c >> 5, part = c & 31;
            size_t off = (size_t)(kp0 + br) * NS + col0 + part * 4;
            cpa16(&sm[SB_H(buf, br, part * 4)], BhG + off);
            cpa16(&sm[SB_L(buf, br, part * 4)], BlG + off);
        }
    };

    int ntile = K >> 5;
    loadtile(0, 0);
    asm volatile("cp.async.commit_group;");
    for (int t = 0; t < ntile; t++) {
        int buf = t & 1;
        if (t + 1 < ntile) {
            loadtile(t + 1, buf ^ 1);
            asm volatile("cp.async.commit_group;");
            asm volatile("cp.async.wait_group 1;");
        } else {
            asm volatile("cp.async.wait_group 0;");
        }
        __syncthreads();

        #pragma unroll
        for (int s = 0; s < 2; s++) {
            int kpb = s * 8;
            uint32_t ah[4][4], al[4][4], bh[4][2], bl[4][2];
            #pragma unroll
            for (int mi = 0; mi < 4; mi++) {
                int mm = wr * 64 + mi * 16;
                ah[mi][0] = sm[SA_H(buf, mm + q,     kpb + r)];
                ah[mi][1] = sm[SA_H(buf, mm + q + 8, kpb + r)];
                ah[mi][2] = sm[SA_H(buf, mm + q,     kpb + 4 + r)];
                ah[mi][3] = sm[SA_H(buf, mm + q + 8, kpb + 4 + r)];
                al[mi][0] = sm[SA_L(buf, mm + q,     kpb + r)];
                al[mi][1] = sm[SA_L(buf, mm + q + 8, kpb + r)];
                al[mi][2] = sm[SA_L(buf, mm + q,     kpb + 4 + r)];
                al[mi][3] = sm[SA_L(buf, mm + q + 8, kpb + 4 + r)];
            }
            #pragma unroll
            for (int ni = 0; ni < 4; ni++) {
                int nn = wc * 32 + ni * 8 + q;
                bh[ni][0] = sm[SB_H(buf, kpb + r,     nn)];
                bh[ni][1] = sm[SB_H(buf, kpb + 4 + r, nn)];
                bl[ni][0] = sm[SB_L(buf, kpb + r,     nn)];
                bl[ni][1] = sm[SB_L(buf, kpb + 4 + r, nn)];
            }
            #pragma unroll
            for (int mi = 0; mi < 4; mi++)
                #pragma unroll
                for (int ni = 0; ni < 4; ni++) {
                    mma16816(acc[mi][ni], ah[mi], bh[ni]);
                    mma16816(acc[mi][ni], ah[mi], bl[ni]);
                    mma16816(acc[mi][ni], al[mi], bh[ni]);
                }
        }
        __syncthreads();
    }

    const float cg = 0.7978845608028654f;
    #pragma unroll
    for (int mi = 0; mi < 4; mi++) {
        int rbase = row0 + wr * 64 + mi * 16 + q;
        #pragma unroll
        for (int ni = 0; ni < 4; ni++) {
            int cbase = col0 + wc * 32 + ni * 8 + 2 * r;
            #pragma unroll
            for (int rg = 0; rg < 2; rg++) {
                int rr = rbase + rg * 8;
                float v0 = acc[mi][ni][rg * 2 + 0];
                float v1 = acc[mi][ni][rg * 2 + 1];
                if (HASBIAS) { v0 += bias[cbase]; v1 += bias[cbase + 1]; }
                if (EPI == 2) {
                    float u0 = cg * (v0 + 0.044715f * v0 * v0 * v0);
                    v0 = 0.5f * v0 * (1.0f + tanhf(u0));
                    float u1 = cg * (v1 + 0.044715f * v1 * v1 * v1);
                    v1 = 0.5f * v1 * (1.0f + tanhf(u1));
                    uint32_t hh, ll;
                    cvt2(v0, v1, hh, ll);
                    size_t pidx = (size_t)rr * (N >> 1) + (cbase >> 1);
                    PH[pidx] = hh;
                    PL[pidx] = ll;
                } else {
                    size_t idx = (size_t)rr * N + cbase;
                    if (cbase < N) {
                        if (EPI == 1) v0 += C[idx];
                        C[idx] = v0;
                    }
                    if (cbase + 1 < N) {
                        if (EPI == 1) v1 += C[idx + 1];
                        C[idx + 1] = v1;
                    }
                }
            }
        }
    }
}

// ---------------- host ----------------
extern "C" void kernel_launch(void* const* d_in, const int* in_sizes, int n_in,
                              void* d_out, int out_size) {
    const int*   tok    = (const int*)  d_in[0];
    const float* wte    = (const float*)d_in[1];
    const float* wpe    = (const float*)d_in[2];
    const float* ln1_w  = (const float*)d_in[3];
    const float* ln1_b  = (const float*)d_in[4];
    const float* attn_w = (const float*)d_in[5];
    const float* attn_b = (const float*)d_in[6];
    const float* proj_w = (const float*)d_in[7];
    const float* proj_b = (const float*)d_in[8];
    const float* ln2_w  = (const float*)d_in[9];
    const float* ln2_b  = (const float*)d_in[10];
    const float* fc_w   = (const float*)d_in[11];
    const float* fc_b   = (const float*)d_in[12];
    const float* fc2_w  = (const float*)d_in[13];
    const float* fc2_b  = (const float*)d_in[14];
    const float* lnf_w  = (const float*)d_in[15];
    const float* lnf_b  = (const float*)d_in[16];
    const float* head_w = (const float*)d_in[17];
    float* out = (float*)d_out;

    float *x, *qkv;
    uint32_t *hH, *hL, *atH, *atL, *ffH, *ffL;
    cudaGetSymbolAddress((void**)&x,   g_x);
    cudaGetSymbolAddress((void**)&qkv, g_qkv);
    cudaGetSymbolAddress((void**)&hH,  g_hH);
    cudaGetSymbolAddress((void**)&hL,  g_hL);
    cudaGetSymbolAddress((void**)&atH, g_atH);
    cudaGetSymbolAddress((void**)&atL, g_atL);
    cudaGetSymbolAddress((void**)&ffH, g_ffH);
    cudaGetSymbolAddress((void**)&ffL, g_ffL);

    uint32_t *wq_h, *wq_l, *wp_h, *wp_l, *wf_h, *wf_l, *w2_h, *w2_l, *wh_h, *wh_l;
    cudaGetSymbolAddress((void**)&wq_h, g_wqkv_h);
    cudaGetSymbolAddress((void**)&wq_l, g_wqkv_l);
    cudaGetSymbolAddress((void**)&wp_h, g_wprj_h);
    cudaGetSymbolAddress((void**)&wp_l, g_wprj_l);
    cudaGetSymbolAddress((void**)&wf_h, g_wfc_h);
    cudaGetSymbolAddress((void**)&wf_l, g_wfc_l);
    cudaGetSymbolAddress((void**)&w2_h, g_wfc2_h);
    cudaGetSymbolAddress((void**)&w2_l, g_wfc2_l);
    cudaGetSymbolAddress((void**)&wh_h, g_whd_h);
    cudaGetSymbolAddress((void**)&wh_l, g_whd_l);

    cudaFuncSetAttribute(gemm_mma<0, true>,  cudaFuncAttributeMaxDynamicSharedMemorySize, GEMM_SMEM);
    cudaFuncSetAttribute(gemm_mma<1, true>,  cudaFuncAttributeMaxDynamicSharedMemorySize, GEMM_SMEM);
    cudaFuncSetAttribute(gemm_mma<2, true>,  cudaFuncAttributeMaxDynamicSharedMemorySize, GEMM_SMEM);
    cudaFuncSetAttribute(gemm_mma<0, false>, cudaFuncAttributeMaxDynamicSharedMemorySize, GEMM_SMEM);
    cudaFuncSetAttribute(attn_kernel,        cudaFuncAttributeMaxDynamicSharedMemorySize, 65536);

    // pack weights
    {
        int n1 = (LL * K2D) * D3;
        pack_w_kernel<<<(n1 + 255) / 256, 256>>>(attn_w, wq_h, wq_l, LL * K2D, D3);
        int n2 = (LL * K2D) * DD;
        pack_w_kernel<<<(n2 + 255) / 256, 256>>>(proj_w, wp_h, wp_l, LL * K2D, DD);
        int n3 = (LL * K2D) * FF;
        pack_w_kernel<<<(n3 + 255) / 256, 256>>>(fc_w, wf_h, wf_l, LL * K2D, FF);
        int n4 = (LL * K2F) * DD;
        pack_w_kernel<<<(n4 + 255) / 256, 256>>>(fc2_w, w2_h, w2_l, LL * K2F, DD);
        pack_head_kernel<<<dim3(K2D / 32, VP / 32), 256>>>(head_w, wh_h, wh_l);
    }

    embed_kernel<<<NT, 256>>>(tok, wte, wpe, x);

    for (int l = 0; l < LL; l++) {
        size_t oq = (size_t)l * K2D * D3;
        size_t op = (size_t)l * K2D * DD;
        size_t of = (size_t)l * K2D * FF;
        size_t o2 = (size_t)l * K2F * DD;

        ln_pack<<<NT, 256>>>(x, ln1_w + l * DD, ln1_b + l * DD, hH, hL);
        gemm_mma<0, true><<<dim3(NT / 128, D3 / 128), 256, GEMM_SMEM>>>(
            hH, hL, wq_h + oq, wq_l + oq, D3, attn_b + l * D3, qkv,
            nullptr, nullptr, D3, DD);
        attn_kernel<<<dim3(TT / 128, HH, 2), 128, 65536>>>(qkv, atH, atL);
        gemm_mma<1, true><<<dim3(NT / 128, DD / 128), 256, GEMM_SMEM>>>(
            atH, atL, wp_h + op, wp_l + op, DD, proj_b + l * DD, x,
            nullptr, nullptr, DD, DD);
        ln_pack<<<NT, 256>>>(x, ln2_w + l * DD, ln2_b + l * DD, hH, hL);
        gemm_mma<2, true><<<dim3(NT / 128, FF / 128), 256, GEMM_SMEM>>>(
            hH, hL, wf_h + of, wf_l + of, FF, fc_b + l * FF, nullptr,
            ffH, ffL, FF, DD);
        gemm_mma<1, true><<<dim3(NT / 128, DD / 128), 256, GEMM_SMEM>>>(
            ffH, ffL, w2_h + o2, w2_l + o2, DD, fc2_b + l * DD, x,
            nullptr, nullptr, DD, FF);
    }

    ln_pack<<<NT, 256>>>(x, lnf_w, lnf_b, hH, hL);
    gemm_mma<0, false><<<dim3(NT / 128, (VV + 127) / 128), 256, GEMM_SMEM>>>(
        hH, hL, wh_h, wh_l, VP, nullptr, out, nullptr, nullptr, VV, DD);
}

// round 6
// speedup vs baseline: 4.9961x; 1.2014x over previous
#include <cuda_runtime.h>
#include <cuda_bf16.h>
#include <cuda_fp16.h>
#include <math.h>
#include <stdint.h>

#define NT 2048
#define TT 1024
#define DD 768
#define FF 3072
#define HH 12
#define HD 64
#define LL 4
#define VV 50257
#define D3 2304
#define VP 50304
#define K2D 384
#define K2F 1536

// ---------------- scratch ----------------
__device__ float    g_x[NT * DD];
__device__ float    g_qkv[NT * D3];
__device__ uint32_t g_hH[NT * K2D], g_hL[NT * K2D], g_hF[NT * K2D];
__device__ uint32_t g_atH[NT * K2D], g_atL[NT * K2D];
__device__ uint32_t g_ffH[NT * K2F], g_ffL[NT * K2F];
// layer weights n-major [N][K/2] bf16-pair words
__device__ uint32_t g_wq_h[LL * D3 * K2D], g_wq_l[LL * D3 * K2D];
__device__ uint32_t g_wp_h[LL * DD * K2D], g_wp_l[LL * DD * K2D];
__device__ uint32_t g_wf_h[LL * FF * K2D], g_wf_l[LL * FF * K2D];
__device__ uint32_t g_w2_h[LL * DD * K2F], g_w2_l[LL * DD * K2F];
// head weights n-major [VP][K2D] fp16-pair words (scaled x256)
__device__ uint32_t g_wh_h[VP * K2D], g_wh_l[VP * K2D];

// ---------------- helpers ----------------
__device__ __forceinline__ void cvt2(float x, float y, uint32_t& hi, uint32_t& lo) {
    __nv_bfloat16 hx = __float2bfloat16(x), hy = __float2bfloat16(y);
    __nv_bfloat16 lx = __float2bfloat16(x - __bfloat162float(hx));
    __nv_bfloat16 ly = __float2bfloat16(y - __bfloat162float(hy));
    hi = ((uint32_t)__bfloat16_as_ushort(hy) << 16) | (uint32_t)__bfloat16_as_ushort(hx);
    lo = ((uint32_t)__bfloat16_as_ushort(ly) << 16) | (uint32_t)__bfloat16_as_ushort(lx);
}
__device__ __forceinline__ uint32_t pkh(float x, float y) {
    __half hx = __float2half_rn(x), hy = __float2half_rn(y);
    return ((uint32_t)__half_as_ushort(hy) << 16) | (uint32_t)__half_as_ushort(hx);
}
__device__ __forceinline__ void cpa16(uint32_t d, const void* s) {
    asm volatile("cp.async.cg.shared.global [%0], [%1], 16;" :: "r"(d), "l"(s));
}
__device__ __forceinline__ void ldsm4(uint32_t* r, uint32_t a) {
    asm volatile("ldmatrix.sync.aligned.m8n8.x4.shared.b16 {%0,%1,%2,%3}, [%4];"
                 : "=r"(r[0]), "=r"(r[1]), "=r"(r[2]), "=r"(r[3]) : "r"(a));
}
__device__ __forceinline__ void mmabf(float* c, const uint32_t* a, uint32_t b0, uint32_t b1) {
    asm volatile("mma.sync.aligned.m16n8k16.row.col.f32.bf16.bf16.f32 "
                 "{%0,%1,%2,%3}, {%4,%5,%6,%7}, {%8,%9}, {%0,%1,%2,%3};\n"
                 : "+f"(c[0]), "+f"(c[1]), "+f"(c[2]), "+f"(c[3])
                 : "r"(a[0]), "r"(a[1]), "r"(a[2]), "r"(a[3]), "r"(b0), "r"(b1));
}
__device__ __forceinline__ void mmaf16(float* c, const uint32_t* a, uint32_t b0, uint32_t b1) {
    asm volatile("mma.sync.aligned.m16n8k16.row.col.f32.f16.f16.f32 "
                 "{%0,%1,%2,%3}, {%4,%5,%6,%7}, {%8,%9}, {%0,%1,%2,%3};\n"
                 : "+f"(c[0]), "+f"(c[1]), "+f"(c[2]), "+f"(c[3])
                 : "r"(a[0]), "r"(a[1]), "r"(a[2]), "r"(a[3]), "r"(b0), "r"(b1));
}
__device__ __forceinline__ uint64_t f2pk(float x, float y) {
    uint64_t r; asm("mov.b64 %0, {%1,%2};" : "=l"(r) : "f"(x), "f"(y)); return r;
}
__device__ __forceinline__ void f2un(uint64_t v, float& x, float& y) {
    asm("mov.b64 {%0,%1}, %2;" : "=f"(x), "=f"(y) : "l"(v));
}
__device__ __forceinline__ uint64_t fma2(uint64_t a, uint64_t b, uint64_t c) {
    uint64_t d; asm("fma.rn.f32x2 %0, %1, %2, %3;" : "=l"(d) : "l"(a), "l"(b), "l"(c)); return d;
}
__device__ __forceinline__ uint64_t mul2(uint64_t a, uint64_t b) {
    uint64_t d; asm("mul.rn.f32x2 %0, %1, %2;" : "=l"(d) : "l"(a), "l"(b)); return d;
}

// W stacked [L][K][N] -> per-layer n-major [N][K/2] bf16 hi/lo
__global__ void pack_w_t(const float* __restrict__ W, uint32_t* __restrict__ Oh,
                         uint32_t* __restrict__ Ol, int K, int N) {
    __shared__ float s[64][33];
    int K2 = K >> 1;
    const float* Wl = W + (size_t)blockIdx.z * K * N;
    uint32_t* OhL = Oh + (size_t)blockIdx.z * N * K2;
    uint32_t* OlL = Ol + (size_t)blockIdx.z * N * K2;
    int k0 = blockIdx.x * 64, n0 = blockIdx.y * 32;
    int rr = threadIdx.x >> 5, cc = threadIdx.x & 31;
    #pragma unroll
    for (int i = 0; i < 8; i++)
        s[rr + i * 8][cc] = Wl[(size_t)(k0 + rr + i * 8) * N + n0 + cc];
    __syncthreads();
    #pragma unroll
    for (int i = 0; i < 4; i++) {
        int n = rr + i * 8;
        uint32_t h, l;
        cvt2(s[2 * cc][n], s[2 * cc + 1][n], h, l);
        OhL[(size_t)(n0 + n) * K2 + (k0 >> 1) + cc] = h;
        OlL[(size_t)(n0 + n) * K2 + (k0 >> 1) + cc] = l;
    }
}
// head_w [V][D] -> [VP][K2D] fp16 hi/lo, x256, zero-pad
__global__ void pack_headf(const float* __restrict__ W, uint32_t* __restrict__ Oh,
                           uint32_t* __restrict__ Ol) {
    int id = blockIdx.x * 256 + threadIdx.x;
    if (id >= VP * K2D) return;
    int n = id / K2D, kp = id - n * K2D;
    float x = 0.f, y = 0.f;
    if (n < VV) {
        const float* p = W + (size_t)n * DD + 2 * kp;
        x = p[0] * 256.f; y = p[1] * 256.f;
    }
    __half hx = __float2half_rn(x), hy = __float2half_rn(y);
    float lxf = x - __half2float(hx), lyf = y - __half2float(hy);
    Oh[id] = ((uint32_t)__half_as_ushort(hy) << 16) | (uint32_t)__half_as_ushort(hx);
    Ol[id] = pkh(lxf, lyf);
}

__global__ void embed_kernel(const int* __restrict__ tok, const float* __restrict__ wte,
                             const float* __restrict__ wpe, float* __restrict__ x) {
    int n = blockIdx.x, t = tok[n];
    const float* we = wte + (size_t)t * DD;
    const float* wp = wpe + (size_t)(n & (TT - 1)) * DD;
    float* xr = x + (size_t)n * DD;
    for (int i = threadIdx.x; i < DD; i += blockDim.x) xr[i] = we[i] + wp[i];
}

__device__ __forceinline__ float blk_sum(float v, float* red) {
    #pragma unroll
    for (int o = 16; o; o >>= 1) v += __shfl_xor_sync(0xffffffffu, v, o);
    if ((threadIdx.x & 31) == 0) red[threadIdx.x >> 5] = v;
    __syncthreads();
    float s = (threadIdx.x < 8) ? red[threadIdx.x] : 0.0f;
    #pragma unroll
    for (int o = 4; o; o >>= 1) s += __shfl_xor_sync(0xffffffffu, s, o);
    if (threadIdx.x == 0) red[0] = s;
    __syncthreads();
    s = red[0];
    __syncthreads();
    return s;
}

__global__ void ln_pack(const float* __restrict__ x, const float* __restrict__ w,
                        const float* __restrict__ b, uint32_t* __restrict__ PH,
                        uint32_t* __restrict__ PL, uint32_t* __restrict__ PF) {
    __shared__ float vb[DD];
    __shared__ float red[32];
    int row = blockIdx.x;
    const float* xr = x + (size_t)row * DD;
    float v[3], s = 0.f, ss = 0.f;
    #pragma unroll
    for (int i = 0; i < 3; i++) {
        int c = threadIdx.x + i * 256;
        v[i] = xr[c]; s += v[i]; ss += v[i] * v[i];
    }
    s = blk_sum(s, red); ss = blk_sum(ss, red);
    float mu = s * (1.0f / DD);
    float r = rsqrtf(ss * (1.0f / DD) - mu * mu + 1e-5f);
    #pragma unroll
    for (int i = 0; i < 3; i++) {
        int c = threadIdx.x + i * 256;
        vb[c] = (v[i] - mu) * r * w[c] + b[c];
    }
    __syncthreads();
    #pragma unroll
    for (int i = 0; i < 2; i++) {
        int p = threadIdx.x + i * 256;
        if (p < K2D) {
            uint32_t hh, ll;
            cvt2(vb[2 * p], vb[2 * p + 1], hh, ll);
            PH[(size_t)row * K2D + p] = hh;
            PL[(size_t)row * K2D + p] = ll;
            PF[(size_t)row * K2D + p] = pkh(vb[2 * p], vb[2 * p + 1]);
        }
    }
}

// ---------------- attention: thread-per-query, f32x2 ----------------
__global__ void __launch_bounds__(128)
attn_kernel(const float* __restrict__ qkv, uint32_t* __restrict__ attH,
            uint32_t* __restrict__ attL) {
    extern __shared__ __align__(16) unsigned sm_dyn[];
    float* Ks = (float*)sm_dyn;
    float* Vs = Ks + 4096;
    float* sc = Vs + 4096;
    int tid = threadIdx.x;
    int qt = blockIdx.x, h = blockIdx.y, b = blockIdx.z;
    int qpos = qt * 128 + tid;
    const float* base = qkv + (size_t)b * TT * D3;
    uint64_t q2[32], o2[32];
    {
        const float* qp = base + (size_t)qpos * D3 + h * HD;
        #pragma unroll
        for (int j = 0; j < 32; j++) q2[j] = f2pk(qp[2 * j], qp[2 * j + 1]);
    }
    #pragma unroll
    for (int j = 0; j < 32; j++) o2[j] = 0ull;
    float m = -1e30f, ssum = 0.f;
    int nkt = (qt + 1) * 2;
    for (int kt = 0; kt < nkt; kt++) {
        int k0 = kt * 64;
        __syncthreads();
        #pragma unroll
        for (int i = 0; i < 32; i++) {
            int idx = i * 128 + tid;
            int kk = idx >> 6, e = idx & 63;
            Ks[idx] = base[(size_t)(k0 + kk) * D3 + DD + h * HD + e];
            Vs[idx] = base[(size_t)(k0 + kk) * D3 + 2 * DD + h * HD + e];
        }
        __syncthreads();
        float tm = -1e30f;
        for (int kk = 0; kk < 64; kk++) {
            const uint64_t* kr = (const uint64_t*)(Ks + (kk << 6));
            uint64_t a0 = 0ull, a1 = 0ull, a2 = 0ull, a3 = 0ull;
            #pragma unroll
            for (int j = 0; j < 32; j += 4) {
                a0 = fma2(q2[j], kr[j], a0);
                a1 = fma2(q2[j + 1], kr[j + 1], a1);
                a2 = fma2(q2[j + 2], kr[j + 2], a2);
                a3 = fma2(q2[j + 3], kr[j + 3], a3);
            }
            float x0, y0, x1, y1, x2, y2, x3, y3;
            f2un(a0, x0, y0); f2un(a1, x1, y1); f2un(a2, x2, y2); f2un(a3, x3, y3);
            float sv = (((x0 + y0) + (x1 + y1)) + ((x2 + y2) + (x3 + y3))) * 0.125f;
            if (k0 + kk > qpos) sv = -1e30f;
            sc[kk * 128 + tid] = sv;
            tm = fmaxf(tm, sv);
        }
        float mn = fmaxf(m, tm);
        float cr = __expf(m - mn);
        m = mn; ssum *= cr;
        uint64_t cr2 = f2pk(cr, cr);
        #pragma unroll
        for (int j = 0; j < 32; j++) o2[j] = mul2(o2[j], cr2);
        for (int kk = 0; kk < 64; kk++) {
            float p = __expf(sc[kk * 128 + tid] - m);
            ssum += p;
            uint64_t p2 = f2pk(p, p);
            const uint64_t* vr = (const uint64_t*)(Vs + (kk << 6));
            #pragma unroll
            for (int j = 0; j < 32; j++) o2[j] = fma2(p2, vr[j], o2[j]);
        }
    }
    float inv = 1.0f / ssum;
    size_t row = (size_t)b * TT + qpos;
    #pragma unroll
    for (int t2 = 0; t2 < 32; t2++) {
        float ox, oy; f2un(o2[t2], ox, oy);
        uint32_t hh, ll;
        cvt2(ox * inv, oy * inv, hh, ll);
        attH[row * K2D + h * 32 + t2] = hh;
        attL[row * K2D + h * 32 + t2] = ll;
    }
}

// ---------------- MMA GEMM with ldmatrix, 128x128, BK=32 ----------------
// A [M][K/2] packed pairs (bf16 hi/lo, or fp16 single if F16TWO).
// B n-major [N][K/2] packed pairs (bf16 hi/lo, or fp16 hi/lo if F16TWO).
// smem/buffer 32KB: Ah@0(8K) Al@8K Bh@16K Bl@24K; granule swizzle g^=((row>>1)&3)
#define GEMM_SMEM 65536

template<int EPI, bool HASBIAS, bool F16TWO>
__global__ void __launch_bounds__(256, 2)
gemm_lm(const uint32_t* __restrict__ AhG, const uint32_t* __restrict__ AlG,
        const uint32_t* __restrict__ BhG, const uint32_t* __restrict__ BlG,
        const float* __restrict__ bias, float* __restrict__ C,
        uint32_t* __restrict__ PH, uint32_t* __restrict__ PL, int N, int K) {
    extern __shared__ __align__(16) char smem[];
    uint32_t sbase = (uint32_t)__cvta_generic_to_shared(smem);
    const int K2 = K >> 1;
    int tid = threadIdx.x;
    int w = tid >> 5, lane = tid & 31;
    int wr = w >> 2, wc = w & 3;   // warp grid 2x4 -> 64x32 tiles
    int q = lane >> 2, r4 = lane & 3;
    int jrow = ((lane >> 3) & 1) * 8 + (lane & 7);
    int gh = lane >> 4;
    int perm = (jrow >> 1) & 3;
    int row0 = blockIdx.x * 128, col0 = blockIdx.y * 128;

    float acc[4][4][4];
    #pragma unroll
    for (int mi = 0; mi < 4; mi++)
        #pragma unroll
        for (int ni = 0; ni < 4; ni++)
            #pragma unroll
            for (int e = 0; e < 4; e++) acc[mi][ni][e] = 0.f;

    auto loadbuf = [&](int t, int buf) {
        uint32_t base = sbase + buf * 32768;
        int kp0 = t * 16;
        #pragma unroll
        for (int i = 0; i < 2; i++) {
            int id = tid + i * 256;
            int mm = id >> 2, g = id & 3;
            uint32_t dst = base + (mm << 6) + ((g ^ ((mm >> 1) & 3)) << 4);
            size_t off = (size_t)(row0 + mm) * K2 + kp0 + g * 4;
            cpa16(dst, AhG + off);
            if (!F16TWO) cpa16(dst + 8192, AlG + off);
        }
        #pragma unroll
        for (int i = 0; i < 2; i++) {
            int id = tid + i * 256;
            int nn = id >> 2, g = id & 3;
            uint32_t dst = base + 16384 + (nn << 6) + ((g ^ ((nn >> 1) & 3)) << 4);
            size_t off = (size_t)(col0 + nn) * K2 + kp0 + g * 4;
            cpa16(dst, BhG + off);
            cpa16(dst + 8192, BlG + off);
        }
    };

    int ntile = K >> 5;
    loadbuf(0, 0);
    asm volatile("cp.async.commit_group;" ::: "memory");
    for (int t = 0; t < ntile; t++) {
        int buf = t & 1;
        if (t + 1 < ntile) {
            loadbuf(t + 1, buf ^ 1);
            asm volatile("cp.async.commit_group;" ::: "memory");
            asm volatile("cp.async.wait_group 1;" ::: "memory");
        } else {
            asm volatile("cp.async.wait_group 0;" ::: "memory");
        }
        __syncthreads();
        uint32_t base = sbase + buf * 32768;
        #pragma unroll
        for (int s = 0; s < 2; s++) {
            int ks = 2 * s + gh;
            uint32_t ah[4][4], b4[2][4];
            #pragma unroll
            for (int mi = 0; mi < 4; mi++)
                ldsm4(ah[mi], base + ((wr * 64 + mi * 16 + jrow) << 6) + ((ks ^ perm) << 4));
            #pragma unroll
            for (int p = 0; p < 2; p++)
                ldsm4(b4[p], base + 16384 + ((wc * 32 + p * 16 + jrow) << 6) + ((ks ^ perm) << 4));
            #pragma unroll
            for (int mi = 0; mi < 4; mi++)
                #pragma unroll
                for (int ni = 0; ni < 4; ni++) {
                    uint32_t b0 = b4[ni >> 1][ni & 1], b1 = b4[ni >> 1][2 + (ni & 1)];
                    if (F16TWO) mmaf16(acc[mi][ni], ah[mi], b0, b1);
                    else        mmabf (acc[mi][ni], ah[mi], b0, b1);
                }
            uint32_t c4[2][4];
            #pragma unroll
            for (int p = 0; p < 2; p++)
                ldsm4(c4[p], base + 24576 + ((wc * 32 + p * 16 + jrow) << 6) + ((ks ^ perm) << 4));
            #pragma unroll
            for (int mi = 0; mi < 4; mi++)
                #pragma unroll
                for (int ni = 0; ni < 4; ni++) {
                    uint32_t b0 = c4[ni >> 1][ni & 1], b1 = c4[ni >> 1][2 + (ni & 1)];
                    if (F16TWO) mmaf16(acc[mi][ni], ah[mi], b0, b1);
                    else        mmabf (acc[mi][ni], ah[mi], b0, b1);
                }
            if (!F16TWO) {
                uint32_t al[4][4];
                #pragma unroll
                for (int mi = 0; mi < 4; mi++)
                    ldsm4(al[mi], base + 8192 + ((wr * 64 + mi * 16 + jrow) << 6) + ((ks ^ perm) << 4));
                #pragma unroll
                for (int mi = 0; mi < 4; mi++)
                    #pragma unroll
                    for (int ni = 0; ni < 4; ni++)
                        mmabf(acc[mi][ni], al[mi], b4[ni >> 1][ni & 1], b4[ni >> 1][2 + (ni & 1)]);
            }
        }
        __syncthreads();
    }

    const float cg = 0.7978845608028654f;
    #pragma unroll
    for (int mi = 0; mi < 4; mi++) {
        int rbase = row0 + wr * 64 + mi * 16 + q;
        #pragma unroll
        for (int ni = 0; ni < 4; ni++) {
            int cbase = col0 + wc * 32 + ni * 8 + 2 * r4;
            #pragma unroll
            for (int rg = 0; rg < 2; rg++) {
                int rr = rbase + rg * 8;
                float v0 = acc[mi][ni][rg * 2 + 0];
                float v1 = acc[mi][ni][rg * 2 + 1];
                if (F16TWO) { v0 *= 0.00390625f; v1 *= 0.00390625f; }
                if (HASBIAS) { v0 += bias[cbase]; v1 += bias[cbase + 1]; }
                if (EPI == 2) {
                    float u0 = cg * (v0 + 0.044715f * v0 * v0 * v0);
                    v0 = 0.5f * v0 * (1.0f + tanhf(u0));
                    float u1 = cg * (v1 + 0.044715f * v1 * v1 * v1);
                    v1 = 0.5f * v1 * (1.0f + tanhf(u1));
                    uint32_t hh, ll;
                    cvt2(v0, v1, hh, ll);
                    size_t pi = (size_t)rr * (N >> 1) + (cbase >> 1);
                    PH[pi] = hh; PL[pi] = ll;
                } else {
                    size_t idx = (size_t)rr * N + cbase;
                    if (cbase < N) {
                        if (EPI == 1) v0 += C[idx];
                        C[idx] = v0;
                    }
                    if (cbase + 1 < N) {
                        if (EPI == 1) v1 += C[idx + 1];
                        C[idx + 1] = v1;
                    }
                }
            }
        }
    }
}

// ---------------- host ----------------
extern "C" void kernel_launch(void* const* d_in, const int* in_sizes, int n_in,
                              void* d_out, int out_size) {
    const int*   tok    = (const int*)  d_in[0];
    const float* wte    = (const float*)d_in[1];
    const float* wpe    = (const float*)d_in[2];
    const float* ln1_w  = (const float*)d_in[3];
    const float* ln1_b  = (const float*)d_in[4];
    const float* attn_w = (const float*)d_in[5];
    const float* attn_b = (const float*)d_in[6];
    const float* proj_w = (const float*)d_in[7];
    const float* proj_b = (const float*)d_in[8];
    const float* ln2_w  = (const float*)d_in[9];
    const float* ln2_b  = (const float*)d_in[10];
    const float* fc_w   = (const float*)d_in[11];
    const float* fc_b   = (const float*)d_in[12];
    const float* fc2_w  = (const float*)d_in[13];
    const float* fc2_b  = (const float*)d_in[14];
    const float* lnf_w  = (const float*)d_in[15];
    const float* lnf_b  = (const float*)d_in[16];
    const float* head_w = (const float*)d_in[17];
    float* out = (float*)d_out;

    float *x, *qkv;
    uint32_t *hH, *hL, *hF, *atH, *atL, *ffH, *ffL;
    cudaGetSymbolAddress((void**)&x, g_x);
    cudaGetSymbolAddress((void**)&qkv, g_qkv);
    cudaGetSymbolAddress((void**)&hH, g_hH);
    cudaGetSymbolAddress((void**)&hL, g_hL);
    cudaGetSymbolAddress((void**)&hF, g_hF);
    cudaGetSymbolAddress((void**)&atH, g_atH);
    cudaGetSymbolAddress((void**)&atL, g_atL);
    cudaGetSymbolAddress((void**)&ffH, g_ffH);
    cudaGetSymbolAddress((void**)&ffL, g_ffL);
    uint32_t *wq_h, *wq_l, *wp_h, *wp_l, *wf_h, *wf_l, *w2_h, *w2_l, *wh_h, *wh_l;
    cudaGetSymbolAddress((void**)&wq_h, g_wq_h);
    cudaGetSymbolAddress((void**)&wq_l, g_wq_l);
    cudaGetSymbolAddress((void**)&wp_h, g_wp_h);
    cudaGetSymbolAddress((void**)&wp_l, g_wp_l);
    cudaGetSymbolAddress((void**)&wf_h, g_wf_h);
    cudaGetSymbolAddress((void**)&wf_l, g_wf_l);
    cudaGetSymbolAddress((void**)&w2_h, g_w2_h);
    cudaGetSymbolAddress((void**)&w2_l, g_w2_l);
    cudaGetSymbolAddress((void**)&wh_h, g_wh_h);
    cudaGetSymbolAddress((void**)&wh_l, g_wh_l);

    cudaFuncSetAttribute(gemm_lm<0, true,  false>, cudaFuncAttributeMaxDynamicSharedMemorySize, GEMM_SMEM);
    cudaFuncSetAttribute(gemm_lm<1, true,  false>, cudaFuncAttributeMaxDynamicSharedMemorySize, GEMM_SMEM);
    cudaFuncSetAttribute(gemm_lm<2, true,  false>, cudaFuncAttributeMaxDynamicSharedMemorySize, GEMM_SMEM);
    cudaFuncSetAttribute(gemm_lm<0, false, true >, cudaFuncAttributeMaxDynamicSharedMemorySize, GEMM_SMEM);
    cudaFuncSetAttribute(attn_kernel, cudaFuncAttributeMaxDynamicSharedMemorySize, 65536);

    pack_w_t<<<dim3(12, 72, LL), 256>>>(attn_w, wq_h, wq_l, DD, D3);
    pack_w_t<<<dim3(12, 24, LL), 256>>>(proj_w, wp_h, wp_l, DD, DD);
    pack_w_t<<<dim3(12, 96, LL), 256>>>(fc_w,  wf_h, wf_l, DD, FF);
    pack_w_t<<<dim3(48, 24, LL), 256>>>(fc2_w, w2_h, w2_l, FF, DD);
    pack_headf<<<(VP * K2D + 255) / 256, 256>>>(head_w, wh_h, wh_l);

    embed_kernel<<<NT, 256>>>(tok, wte, wpe, x);

    for (int l = 0; l < LL; l++) {
        size_t oq = (size_t)l * D3 * K2D, op = (size_t)l * DD * K2D;
        size_t of = (size_t)l * FF * K2D, o2 = (size_t)l * DD * K2F;
        ln_pack<<<NT, 256>>>(x, ln1_w + l * DD, ln1_b + l * DD, hH, hL, hF);
        gemm_lm<0, true, false><<<dim3(NT / 128, D3 / 128), 256, GEMM_SMEM>>>(
            hH, hL, wq_h + oq, wq_l + oq, attn_b + l * D3, qkv, nullptr, nullptr, D3, DD);
        attn_kernel<<<dim3(TT / 128, HH, 2), 128, 65536>>>(qkv, atH, atL);
        gemm_lm<1, true, false><<<dim3(NT / 128, DD / 128), 256, GEMM_SMEM>>>(
            atH, atL, wp_h + op, wp_l + op, proj_b + l * DD, x, nullptr, nullptr, DD, DD);
        ln_pack<<<NT, 256>>>(x, ln2_w + l * DD, ln2_b + l * DD, hH, hL, hF);
        gemm_lm<2, true, false><<<dim3(NT / 128, FF / 128), 256, GEMM_SMEM>>>(
            hH, hL, wf_h + of, wf_l + of, fc_b + l * FF, nullptr, ffH, ffL, FF, DD);
        gemm_lm<1, true, false><<<dim3(NT / 128, DD / 128), 256, GEMM_SMEM>>>(
            ffH, ffL, w2_h + o2, w2_l + o2, fc2_b + l * DD, x, nullptr, nullptr, DD, FF);
    }
    ln_pack<<<NT, 256>>>(x, lnf_w, lnf_b, hH, hL, hF);
    gemm_lm<0, false, true><<<dim3(NT / 128, VP / 128), 256, GEMM_SMEM>>>(
        hF, nullptr, wh_h, wh_l, nullptr, out, nullptr, nullptr, VV, DD);
}

// round 7
// speedup vs baseline: 5.4099x; 1.0828x over previous
#include <cuda_runtime.h>
#include <cuda_bf16.h>
#include <cuda_fp16.h>
#include <math.h>
#include <stdint.h>

#define NT 2048
#define TT 1024
#define DD 768
#define FF 3072
#define HH 12
#define HD 64
#define LL 4
#define VV 50257
#define D3 2304
#define VP 50304
#define K2D 384
#define K2F 1536

// ---------------- scratch ----------------
__device__ float    g_x[NT * DD];
__device__ float    g_qkv[NT * D3];   // doubles as split-K partial buffer [3][NT][DD]
__device__ uint32_t g_hH[NT * K2D], g_hL[NT * K2D], g_hF[NT * K2D];
__device__ uint32_t g_atH[NT * K2D], g_atL[NT * K2D];
__device__ uint32_t g_ffH[NT * K2F], g_ffL[NT * K2F];
__device__ uint32_t g_wq_h[LL * D3 * K2D], g_wq_l[LL * D3 * K2D];
__device__ uint32_t g_wp_h[LL * DD * K2D], g_wp_l[LL * DD * K2D];
__device__ uint32_t g_wf_h[LL * FF * K2D], g_wf_l[LL * FF * K2D];
__device__ uint32_t g_w2_h[LL * DD * K2F], g_w2_l[LL * DD * K2F];
__device__ uint32_t g_wh_h[VP * K2D], g_wh_l[VP * K2D];

// ---------------- helpers ----------------
__device__ __forceinline__ void cvt2(float x, float y, uint32_t& hi, uint32_t& lo) {
    __nv_bfloat16 hx = __float2bfloat16(x), hy = __float2bfloat16(y);
    __nv_bfloat16 lx = __float2bfloat16(x - __bfloat162float(hx));
    __nv_bfloat16 ly = __float2bfloat16(y - __bfloat162float(hy));
    hi = ((uint32_t)__bfloat16_as_ushort(hy) << 16) | (uint32_t)__bfloat16_as_ushort(hx);
    lo = ((uint32_t)__bfloat16_as_ushort(ly) << 16) | (uint32_t)__bfloat16_as_ushort(lx);
}
__device__ __forceinline__ uint32_t pkh(float x, float y) {
    __half hx = __float2half_rn(x), hy = __float2half_rn(y);
    return ((uint32_t)__half_as_ushort(hy) << 16) | (uint32_t)__half_as_ushort(hx);
}
__device__ __forceinline__ void cpa16(uint32_t d, const void* s) {
    asm volatile("cp.async.cg.shared.global [%0], [%1], 16;" :: "r"(d), "l"(s));
}
__device__ __forceinline__ void ldsm4(uint32_t* r, uint32_t a) {
    asm volatile("ldmatrix.sync.aligned.m8n8.x4.shared.b16 {%0,%1,%2,%3}, [%4];"
                 : "=r"(r[0]), "=r"(r[1]), "=r"(r[2]), "=r"(r[3]) : "r"(a));
}
__device__ __forceinline__ void mmabf(float* c, const uint32_t* a, uint32_t b0, uint32_t b1) {
    asm volatile("mma.sync.aligned.m16n8k16.row.col.f32.bf16.bf16.f32 "
                 "{%0,%1,%2,%3}, {%4,%5,%6,%7}, {%8,%9}, {%0,%1,%2,%3};\n"
                 : "+f"(c[0]), "+f"(c[1]), "+f"(c[2]), "+f"(c[3])
                 : "r"(a[0]), "r"(a[1]), "r"(a[2]), "r"(a[3]), "r"(b0), "r"(b1));
}
__device__ __forceinline__ void mmaf16(float* c, const uint32_t* a, uint32_t b0, uint32_t b1) {
    asm volatile("mma.sync.aligned.m16n8k16.row.col.f32.f16.f16.f32 "
                 "{%0,%1,%2,%3}, {%4,%5,%6,%7}, {%8,%9}, {%0,%1,%2,%3};\n"
                 : "+f"(c[0]), "+f"(c[1]), "+f"(c[2]), "+f"(c[3])
                 : "r"(a[0]), "r"(a[1]), "r"(a[2]), "r"(a[3]), "r"(b0), "r"(b1));
}
__device__ __forceinline__ uint64_t f2pk(float x, float y) {
    uint64_t r; asm("mov.b64 %0, {%1,%2};" : "=l"(r) : "f"(x), "f"(y)); return r;
}
__device__ __forceinline__ void f2un(uint64_t v, float& x, float& y) {
    asm("mov.b64 {%0,%1}, %2;" : "=f"(x), "=f"(y) : "l"(v));
}
__device__ __forceinline__ uint64_t fma2(uint64_t a, uint64_t b, uint64_t c) {
    uint64_t d; asm("fma.rn.f32x2 %0, %1, %2, %3;" : "=l"(d) : "l"(a), "l"(b), "l"(c)); return d;
}
__device__ __forceinline__ uint64_t mul2(uint64_t a, uint64_t b) {
    uint64_t d; asm("mul.rn.f32x2 %0, %1, %2;" : "=l"(d) : "l"(a), "l"(b)); return d;
}

// ---------------- packing ----------------
__global__ void pack_w_t(const float* __restrict__ W, uint32_t* __restrict__ Oh,
                         uint32_t* __restrict__ Ol, int K, int N) {
    __shared__ float s[64][33];
    int K2 = K >> 1;
    const float* Wl = W + (size_t)blockIdx.z * K * N;
    uint32_t* OhL = Oh + (size_t)blockIdx.z * N * K2;
    uint32_t* OlL = Ol + (size_t)blockIdx.z * N * K2;
    int k0 = blockIdx.x * 64, n0 = blockIdx.y * 32;
    int rr = threadIdx.x >> 5, cc = threadIdx.x & 31;
    #pragma unroll
    for (int i = 0; i < 8; i++)
        s[rr + i * 8][cc] = Wl[(size_t)(k0 + rr + i * 8) * N + n0 + cc];
    __syncthreads();
    #pragma unroll
    for (int i = 0; i < 4; i++) {
        int n = rr + i * 8;
        uint32_t h, l;
        cvt2(s[2 * cc][n], s[2 * cc + 1][n], h, l);
        OhL[(size_t)(n0 + n) * K2 + (k0 >> 1) + cc] = h;
        OlL[(size_t)(n0 + n) * K2 + (k0 >> 1) + cc] = l;
    }
}
__global__ void pack_headf(const float* __restrict__ W, uint32_t* __restrict__ Oh,
                           uint32_t* __restrict__ Ol) {
    int id = blockIdx.x * 256 + threadIdx.x;
    if (id >= VP * K2D) return;
    int n = id / K2D, kp = id - n * K2D;
    float x = 0.f, y = 0.f;
    if (n < VV) { const float* p = W + (size_t)n * DD + 2 * kp; x = p[0] * 256.f; y = p[1] * 256.f; }
    __half hx = __float2half_rn(x), hy = __float2half_rn(y);
    Oh[id] = ((uint32_t)__half_as_ushort(hy) << 16) | (uint32_t)__half_as_ushort(hx);
    Ol[id] = pkh(x - __half2float(hx), y - __half2float(hy));
}

// ---------------- LN machinery ----------------
__device__ __forceinline__ float blk_sum(float v, float* red) {
    #pragma unroll
    for (int o = 16; o; o >>= 1) v += __shfl_xor_sync(0xffffffffu, v, o);
    if ((threadIdx.x & 31) == 0) red[threadIdx.x >> 5] = v;
    __syncthreads();
    float s = (threadIdx.x < 8) ? red[threadIdx.x] : 0.0f;
    #pragma unroll
    for (int o = 4; o; o >>= 1) s += __shfl_xor_sync(0xffffffffu, s, o);
    if (threadIdx.x == 0) red[0] = s;
    __syncthreads();
    s = red[0];
    __syncthreads();
    return s;
}

__device__ __forceinline__ void ln_body(float* v, float s, float ss, float* vb, float* red,
                                        const float* w, const float* b, int row,
                                        uint32_t* PH, uint32_t* PL, uint32_t* PF) {
    float mu = s * (1.0f / DD);
    float r = rsqrtf(ss * (1.0f / DD) - mu * mu + 1e-5f);
    #pragma unroll
    for (int i = 0; i < 3; i++) {
        int c = threadIdx.x + i * 256;
        vb[c] = (v[i] - mu) * r * w[c] + b[c];
    }
    __syncthreads();
    #pragma unroll
    for (int i = 0; i < 2; i++) {
        int p = threadIdx.x + i * 256;
        if (p < K2D) {
            uint32_t hh, ll;
            cvt2(vb[2 * p], vb[2 * p + 1], hh, ll);
            PH[(size_t)row * K2D + p] = hh;
            PL[(size_t)row * K2D + p] = ll;
            PF[(size_t)row * K2D + p] = pkh(vb[2 * p], vb[2 * p + 1]);
        }
    }
}

// embedding + ln1(layer0) + pack
__global__ void embed_ln_pack(const int* __restrict__ tok, const float* __restrict__ wte,
                              const float* __restrict__ wpe, float* __restrict__ x,
                              const float* __restrict__ w, const float* __restrict__ b,
                              uint32_t* __restrict__ PH, uint32_t* __restrict__ PL,
                              uint32_t* __restrict__ PF) {
    __shared__ float vb[DD];
    __shared__ float red[32];
    int row = blockIdx.x, t = tok[row];
    const float* we = wte + (size_t)t * DD;
    const float* wp = wpe + (size_t)(row & (TT - 1)) * DD;
    float v[3], s = 0.f, ss = 0.f;
    #pragma unroll
    for (int i = 0; i < 3; i++) {
        int c = threadIdx.x + i * 256;
        v[i] = we[c] + wp[c];
        x[(size_t)row * DD + c] = v[i];
        s += v[i]; ss += v[i] * v[i];
    }
    s = blk_sum(s, red); ss = blk_sum(ss, red);
    ln_body(v, s, ss, vb, red, w, b, row, PH, PL, PF);
}

// split-K reduce + bias + residual + LN + pack
__global__ void red_ln_pack(const float* __restrict__ P, const float* __restrict__ bias,
                            float* __restrict__ x, const float* __restrict__ w,
                            const float* __restrict__ b, uint32_t* __restrict__ PH,
                            uint32_t* __restrict__ PL, uint32_t* __restrict__ PF) {
    __shared__ float vb[DD];
    __shared__ float red[32];
    int row = blockIdx.x;
    float v[3], s = 0.f, ss = 0.f;
    #pragma unroll
    for (int i = 0; i < 3; i++) {
        int c = threadIdx.x + i * 256;
        size_t idx = (size_t)row * DD + c;
        float t = x[idx] + bias[c] + P[idx] + P[(size_t)NT * DD + idx] + P[2 * (size_t)NT * DD + idx];
        x[idx] = t;
        v[i] = t; s += t; ss += t * t;
    }
    s = blk_sum(s, red); ss = blk_sum(ss, red);
    ln_body(v, s, ss, vb, red, w, b, row, PH, PL, PF);
}

// ---------------- attention ----------------
__global__ void __launch_bounds__(128)
attn_kernel(const float* __restrict__ qkv, uint32_t* __restrict__ attH,
            uint32_t* __restrict__ attL) {
    extern __shared__ __align__(16) unsigned sm_dyn[];
    float* Ks = (float*)sm_dyn;
    float* Vs = Ks + 4096;
    float* sc = Vs + 4096;
    int tid = threadIdx.x;
    int qt = blockIdx.x, h = blockIdx.y, b = blockIdx.z;
    int qpos = qt * 128 + tid;
    const float* base = qkv + (size_t)b * TT * D3;
    uint64_t q2[32], o2[32];
    {
        const float* qp = base + (size_t)qpos * D3 + h * HD;
        #pragma unroll
        for (int j = 0; j < 32; j++) q2[j] = f2pk(qp[2 * j], qp[2 * j + 1]);
    }
    #pragma unroll
    for (int j = 0; j < 32; j++) o2[j] = 0ull;
    float m = -1e30f, ssum = 0.f;
    int nkt = (qt + 1) * 2;
    for (int kt = 0; kt < nkt; kt++) {
        int k0 = kt * 64;
        __syncthreads();
        #pragma unroll
        for (int i = 0; i < 32; i++) {
            int idx = i * 128 + tid;
            int kk = idx >> 6, e = idx & 63;
            Ks[idx] = base[(size_t)(k0 + kk) * D3 + DD + h * HD + e];
            Vs[idx] = base[(size_t)(k0 + kk) * D3 + 2 * DD + h * HD + e];
        }
        __syncthreads();
        float tm = -1e30f;
        for (int kk = 0; kk < 64; kk++) {
            const uint64_t* kr = (const uint64_t*)(Ks + (kk << 6));
            uint64_t a0 = 0ull, a1 = 0ull, a2 = 0ull, a3 = 0ull;
            #pragma unroll
            for (int j = 0; j < 32; j += 4) {
                a0 = fma2(q2[j], kr[j], a0);
                a1 = fma2(q2[j + 1], kr[j + 1], a1);
                a2 = fma2(q2[j + 2], kr[j + 2], a2);
                a3 = fma2(q2[j + 3], kr[j + 3], a3);
            }
            float x0, y0, x1, y1, x2, y2, x3, y3;
            f2un(a0, x0, y0); f2un(a1, x1, y1); f2un(a2, x2, y2); f2un(a3, x3, y3);
            float sv = (((x0 + y0) + (x1 + y1)) + ((x2 + y2) + (x3 + y3))) * 0.125f;
            if (k0 + kk > qpos) sv = -1e30f;
            sc[kk * 128 + tid] = sv;
            tm = fmaxf(tm, sv);
        }
        float mn = fmaxf(m, tm);
        float cr = __expf(m - mn);
        m = mn; ssum *= cr;
        uint64_t cr2 = f2pk(cr, cr);
        #pragma unroll
        for (int j = 0; j < 32; j++) o2[j] = mul2(o2[j], cr2);
        for (int kk = 0; kk < 64; kk++) {
            float p = __expf(sc[kk * 128 + tid] - m);
            ssum += p;
            uint64_t p2 = f2pk(p, p);
            const uint64_t* vr = (const uint64_t*)(Vs + (kk << 6));
            #pragma unroll
            for (int j = 0; j < 32; j++) o2[j] = fma2(p2, vr[j], o2[j]);
        }
    }
    float inv = 1.0f / ssum;
    size_t row = (size_t)b * TT + qpos;
    #pragma unroll
    for (int t2 = 0; t2 < 32; t2++) {
        float ox, oy; f2un(o2[t2], ox, oy);
        uint32_t hh, ll;
        cvt2(ox * inv, oy * inv, hh, ll);
        attH[row * K2D + h * 32 + t2] = hh;
        attL[row * K2D + h * 32 + t2] = ll;
    }
}

// ---------------- MMA GEMM (ldmatrix), 128x128, BK=32 ----------------
// EPI: 0 store fp32 (+bias), 2 bias+GELU->pack, 3 split-K partial store.
#define GEMM_SMEM 65536

template<int EPI, bool HASBIAS, bool F16TWO>
__global__ void __launch_bounds__(256, 2)
gemm_lm(const uint32_t* __restrict__ AhG, const uint32_t* __restrict__ AlG,
        const uint32_t* __restrict__ BhG, const uint32_t* __restrict__ BlG,
        const float* __restrict__ bias, float* __restrict__ C,
        uint32_t* __restrict__ PH, uint32_t* __restrict__ PL,
        int N, int Kslice, int K2s) {
    extern __shared__ __align__(16) char smem[];
    uint32_t sbase = (uint32_t)__cvta_generic_to_shared(smem);
    int tid = threadIdx.x;
    int w = tid >> 5, lane = tid & 31;
    int wr = w >> 2, wc = w & 3;
    int q = lane >> 2, r4 = lane & 3;
    int jrow = ((lane >> 3) & 1) * 8 + (lane & 7);
    int gh = lane >> 4;
    int perm = (jrow >> 1) & 3;
    int row0 = blockIdx.x * 128, col0 = blockIdx.y * 128;
    int kofs = blockIdx.z * (Kslice >> 1);

    float acc[4][4][4];
    #pragma unroll
    for (int mi = 0; mi < 4; mi++)
        #pragma unroll
        for (int ni = 0; ni < 4; ni++)
            #pragma unroll
            for (int e = 0; e < 4; e++) acc[mi][ni][e] = 0.f;

    auto loadbuf = [&](int t, int buf) {
        uint32_t base = sbase + buf * 32768;
        int kp0 = kofs + t * 16;
        #pragma unroll
        for (int i = 0; i < 2; i++) {
            int id = tid + i * 256;
            int mm = id >> 2, g = id & 3;
            uint32_t dst = base + (mm << 6) + ((g ^ ((mm >> 1) & 3)) << 4);
            size_t off = (size_t)(row0 + mm) * K2s + kp0 + g * 4;
            cpa16(dst, AhG + off);
            if (!F16TWO) cpa16(dst + 8192, AlG + off);
        }
        #pragma unroll
        for (int i = 0; i < 2; i++) {
            int id = tid + i * 256;
            int nn = id >> 2, g = id & 3;
            uint32_t dst = base + 16384 + (nn << 6) + ((g ^ ((nn >> 1) & 3)) << 4);
            size_t off = (size_t)(col0 + nn) * K2s + kp0 + g * 4;
            cpa16(dst, BhG + off);
            cpa16(dst + 8192, BlG + off);
        }
    };

    int ntile = Kslice >> 5;
    loadbuf(0, 0);
    asm volatile("cp.async.commit_group;" ::: "memory");
    for (int t = 0; t < ntile; t++) {
        int buf = t & 1;
        if (t + 1 < ntile) {
            loadbuf(t + 1, buf ^ 1);
            asm volatile("cp.async.commit_group;" ::: "memory");
            asm volatile("cp.async.wait_group 1;" ::: "memory");
        } else {
            asm volatile("cp.async.wait_group 0;" ::: "memory");
        }
        __syncthreads();
        uint32_t base = sbase + buf * 32768;
        #pragma unroll
        for (int s = 0; s < 2; s++) {
            int ks = 2 * s + gh;
            uint32_t ah[4][4], b4[2][4];
            #pragma unroll
            for (int mi = 0; mi < 4; mi++)
                ldsm4(ah[mi], base + ((wr * 64 + mi * 16 + jrow) << 6) + ((ks ^ perm) << 4));
            #pragma unroll
            for (int p = 0; p < 2; p++)
                ldsm4(b4[p], base + 16384 + ((wc * 32 + p * 16 + jrow) << 6) + ((ks ^ perm) << 4));
            #pragma unroll
            for (int mi = 0; mi < 4; mi++)
                #pragma unroll
                for (int ni = 0; ni < 4; ni++) {
                    uint32_t b0 = b4[ni >> 1][ni & 1], b1 = b4[ni >> 1][2 + (ni & 1)];
                    if (F16TWO) mmaf16(acc[mi][ni], ah[mi], b0, b1);
                    else        mmabf (acc[mi][ni], ah[mi], b0, b1);
                }
            uint32_t c4[2][4];
            #pragma unroll
            for (int p = 0; p < 2; p++)
                ldsm4(c4[p], base + 24576 + ((wc * 32 + p * 16 + jrow) << 6) + ((ks ^ perm) << 4));
            #pragma unroll
            for (int mi = 0; mi < 4; mi++)
                #pragma unroll
                for (int ni = 0; ni < 4; ni++) {
                    uint32_t b0 = c4[ni >> 1][ni & 1], b1 = c4[ni >> 1][2 + (ni & 1)];
                    if (F16TWO) mmaf16(acc[mi][ni], ah[mi], b0, b1);
                    else        mmabf (acc[mi][ni], ah[mi], b0, b1);
                }
            if (!F16TWO) {
                uint32_t al[4][4];
                #pragma unroll
                for (int mi = 0; mi < 4; mi++)
                    ldsm4(al[mi], base + 8192 + ((wr * 64 + mi * 16 + jrow) << 6) + ((ks ^ perm) << 4));
                #pragma unroll
                for (int mi = 0; mi < 4; mi++)
                    #pragma unroll
                    for (int ni = 0; ni < 4; ni++)
                        mmabf(acc[mi][ni], al[mi], b4[ni >> 1][ni & 1], b4[ni >> 1][2 + (ni & 1)]);
            }
        }
        __syncthreads();
    }

    const float cg = 0.7978845608028654f;
    #pragma unroll
    for (int mi = 0; mi < 4; mi++) {
        int rbase = row0 + wr * 64 + mi * 16 + q;
        #pragma unroll
        for (int ni = 0; ni < 4; ni++) {
            int cbase = col0 + wc * 32 + ni * 8 + 2 * r4;
            #pragma unroll
            for (int rg = 0; rg < 2; rg++) {
                int rr = rbase + rg * 8;
                float v0 = acc[mi][ni][rg * 2 + 0];
                float v1 = acc[mi][ni][rg * 2 + 1];
                if (F16TWO) { v0 *= 0.00390625f; v1 *= 0.00390625f; }
                if (HASBIAS) { v0 += bias[cbase]; v1 += bias[cbase + 1]; }
                if (EPI == 2) {
                    float u0 = cg * (v0 + 0.044715f * v0 * v0 * v0);
                    v0 = 0.5f * v0 * (1.0f + tanhf(u0));
                    float u1 = cg * (v1 + 0.044715f * v1 * v1 * v1);
                    v1 = 0.5f * v1 * (1.0f + tanhf(u1));
                    uint32_t hh, ll;
                    cvt2(v0, v1, hh, ll);
                    size_t pi = (size_t)rr * (N >> 1) + (cbase >> 1);
                    PH[pi] = hh; PL[pi] = ll;
                } else if (EPI == 3) {
                    size_t idx = ((size_t)blockIdx.z * NT + rr) * N + cbase;
                    C[idx] = v0;
                    C[idx + 1] = v1;
                } else {
                    size_t idx = (size_t)rr * N + cbase;
                    if (cbase < N) C[idx] = v0;
                    if (cbase + 1 < N) C[idx + 1] = v1;
                }
            }
        }
    }
}

// ---------------- host ----------------
extern "C" void kernel_launch(void* const* d_in, const int* in_sizes, int n_in,
                              void* d_out, int out_size) {
    const int*   tok    = (const int*)  d_in[0];
    const float* wte    = (const float*)d_in[1];
    const float* wpe    = (const float*)d_in[2];
    const float* ln1_w  = (const float*)d_in[3];
    const float* ln1_b  = (const float*)d_in[4];
    const float* attn_w = (const float*)d_in[5];
    const float* attn_b = (const float*)d_in[6];
    const float* proj_w = (const float*)d_in[7];
    const float* proj_b = (const float*)d_in[8];
    const float* ln2_w  = (const float*)d_in[9];
    const float* ln2_b  = (const float*)d_in[10];
    const float* fc_w   = (const float*)d_in[11];
    const float* fc_b   = (const float*)d_in[12];
    const float* fc2_w  = (const float*)d_in[13];
    const float* fc2_b  = (const float*)d_in[14];
    const float* lnf_w  = (const float*)d_in[15];
    const float* lnf_b  = (const float*)d_in[16];
    const float* head_w = (const float*)d_in[17];
    float* out = (float*)d_out;

    float *x, *qkv;
    uint32_t *hH, *hL, *hF, *atH, *atL, *ffH, *ffL;
    cudaGetSymbolAddress((void**)&x, g_x);
    cudaGetSymbolAddress((void**)&qkv, g_qkv);
    cudaGetSymbolAddress((void**)&hH, g_hH);
    cudaGetSymbolAddress((void**)&hL, g_hL);
    cudaGetSymbolAddress((void**)&hF, g_hF);
    cudaGetSymbolAddress((void**)&atH, g_atH);
    cudaGetSymbolAddress((void**)&atL, g_atL);
    cudaGetSymbolAddress((void**)&ffH, g_ffH);
    cudaGetSymbolAddress((void**)&ffL, g_ffL);
    uint32_t *wq_h, *wq_l, *wp_h, *wp_l, *wf_h, *wf_l, *w2_h, *w2_l, *wh_h, *wh_l;
    cudaGetSymbolAddress((void**)&wq_h, g_wq_h);
    cudaGetSymbolAddress((void**)&wq_l, g_wq_l);
    cudaGetSymbolAddress((void**)&wp_h, g_wp_h);
    cudaGetSymbolAddress((void**)&wp_l, g_wp_l);
    cudaGetSymbolAddress((void**)&wf_h, g_wf_h);
    cudaGetSymbolAddress((void**)&wf_l, g_wf_l);
    cudaGetSymbolAddress((void**)&w2_h, g_w2_h);
    cudaGetSymbolAddress((void**)&w2_l, g_w2_l);
    cudaGetSymbolAddress((void**)&wh_h, g_wh_h);
    cudaGetSymbolAddress((void**)&wh_l, g_wh_l);

    cudaFuncSetAttribute(gemm_lm<0, true,  false>, cudaFuncAttributeMaxDynamicSharedMemorySize, GEMM_SMEM);
    cudaFuncSetAttribute(gemm_lm<2, true,  false>, cudaFuncAttributeMaxDynamicSharedMemorySize, GEMM_SMEM);
    cudaFuncSetAttribute(gemm_lm<3, false, false>, cudaFuncAttributeMaxDynamicSharedMemorySize, GEMM_SMEM);
    cudaFuncSetAttribute(gemm_lm<0, false, true >, cudaFuncAttributeMaxDynamicSharedMemorySize, GEMM_SMEM);
    cudaFuncSetAttribute(attn_kernel, cudaFuncAttributeMaxDynamicSharedMemorySize, 65536);

    pack_w_t<<<dim3(12, 72, LL), 256>>>(attn_w, wq_h, wq_l, DD, D3);
    pack_w_t<<<dim3(12, 24, LL), 256>>>(proj_w, wp_h, wp_l, DD, DD);
    pack_w_t<<<dim3(12, 96, LL), 256>>>(fc_w,  wf_h, wf_l, DD, FF);
    pack_w_t<<<dim3(48, 24, LL), 256>>>(fc2_w, w2_h, w2_l, FF, DD);
    pack_headf<<<(VP * K2D + 255) / 256, 256>>>(head_w, wh_h, wh_l);

    embed_ln_pack<<<NT, 256>>>(tok, wte, wpe, x, ln1_w, ln1_b, hH, hL, hF);

    for (int l = 0; l < LL; l++) {
        size_t oq = (size_t)l * D3 * K2D, op = (size_t)l * DD * K2D;
        size_t of = (size_t)l * FF * K2D, o2 = (size_t)l * DD * K2F;

        gemm_lm<0, true, false><<<dim3(NT / 128, D3 / 128, 1), 256, GEMM_SMEM>>>(
            hH, hL, wq_h + oq, wq_l + oq, attn_b + l * D3, qkv, nullptr, nullptr,
            D3, DD, K2D);
        attn_kernel<<<dim3(TT / 128, HH, 2), 128, 65536>>>(qkv, atH, atL);
        // proj split-K3 -> partials in qkv buffer
        gemm_lm<3, false, false><<<dim3(NT / 128, DD / 128, 3), 256, GEMM_SMEM>>>(
            atH, atL, wp_h + op, wp_l + op, nullptr, qkv, nullptr, nullptr,
            DD, DD / 3, K2D);
        red_ln_pack<<<NT, 256>>>(qkv, proj_b + l * DD, x, ln2_w + l * DD, ln2_b + l * DD,
                                 hH, hL, hF);
        gemm_lm<2, true, false><<<dim3(NT / 128, FF / 128, 1), 256, GEMM_SMEM>>>(
            hH, hL, wf_h + of, wf_l + of, fc_b + l * FF, nullptr, ffH, ffL,
            FF, DD, K2D);
        // fc2 split-K3 -> partials in qkv buffer
        gemm_lm<3, false, false><<<dim3(NT / 128, DD / 128, 3), 256, GEMM_SMEM>>>(
            ffH, ffL, w2_h + o2, w2_l + o2, nullptr, qkv, nullptr, nullptr,
            DD, FF / 3, K2F);
        const float* nw = (l < LL - 1) ? ln1_w + (l + 1) * DD : lnf_w;
        const float* nb = (l < LL - 1) ? ln1_b + (l + 1) * DD : lnf_b;
        red_ln_pack<<<NT, 256>>>(qkv, fc2_b + l * DD, x, nw, nb, hH, hL, hF);
    }

    gemm_lm<0, false, true><<<dim3(NT / 128, VP / 128, 1), 256, GEMM_SMEM>>>(
        hF, nullptr, wh_h, wh_l, nullptr, out, nullptr, nullptr, VV, DD, K2D);
}

// round 8
// speedup vs baseline: 5.9191x; 1.0941x over previous
#include <cuda_runtime.h>
#include <cuda_bf16.h>
#include <cuda_fp16.h>
#include <math.h>
#include <stdint.h>

#define NT 2048
#define TT 1024
#define DD 768
#define FF 3072
#define HH 12
#define HD 64
#define LL 4
#define VV 50257
#define D3 2304
#define VP 50304
#define K2D 384
#define K2F 1536

// ---------------- scratch ----------------
__device__ float    g_x[NT * DD];
__device__ float    g_qkv[NT * D3];   // also split-K partial buffer [3][NT][DD]
__device__ uint32_t g_hF[NT * K2D];   // LN out, fp16 pairs
__device__ uint32_t g_atF[NT * K2D];  // attn out, fp16 pairs
__device__ uint32_t g_ffF[NT * K2F];  // GELU out, fp16 pairs
// weights n-major [N][K/2] fp16-pair words, scaled x256, hi/lo
__device__ uint32_t g_wq_h[LL * D3 * K2D], g_wq_l[LL * D3 * K2D];
__device__ uint32_t g_wp_h[LL * DD * K2D], g_wp_l[LL * DD * K2D];
__device__ uint32_t g_wf_h[LL * FF * K2D], g_wf_l[LL * FF * K2D];
__device__ uint32_t g_w2_h[LL * DD * K2F], g_w2_l[LL * DD * K2F];
__device__ uint32_t g_wh_h[VP * K2D], g_wh_l[VP * K2D];

// ---------------- helpers ----------------
__device__ __forceinline__ uint32_t pkh(float x, float y) {
    __half hx = __float2half_rn(x), hy = __float2half_rn(y);
    return ((uint32_t)__half_as_ushort(hy) << 16) | (uint32_t)__half_as_ushort(hx);
}
__device__ __forceinline__ void cvt2h(float x, float y, uint32_t& hi, uint32_t& lo) {
    __half hx = __float2half_rn(x), hy = __float2half_rn(y);
    hi = ((uint32_t)__half_as_ushort(hy) << 16) | (uint32_t)__half_as_ushort(hx);
    lo = pkh(x - __half2float(hx), y - __half2float(hy));
}
__device__ __forceinline__ void cpa16(uint32_t d, const void* s) {
    asm volatile("cp.async.cg.shared.global [%0], [%1], 16;" :: "r"(d), "l"(s));
}
__device__ __forceinline__ void ldsm4(uint32_t* r, uint32_t a) {
    asm volatile("ldmatrix.sync.aligned.m8n8.x4.shared.b16 {%0,%1,%2,%3}, [%4];"
                 : "=r"(r[0]), "=r"(r[1]), "=r"(r[2]), "=r"(r[3]) : "r"(a));
}
__device__ __forceinline__ void mmaf16(float* c, const uint32_t* a, uint32_t b0, uint32_t b1) {
    asm volatile("mma.sync.aligned.m16n8k16.row.col.f32.f16.f16.f32 "
                 "{%0,%1,%2,%3}, {%4,%5,%6,%7}, {%8,%9}, {%0,%1,%2,%3};\n"
                 : "+f"(c[0]), "+f"(c[1]), "+f"(c[2]), "+f"(c[3])
                 : "r"(a[0]), "r"(a[1]), "r"(a[2]), "r"(a[3]), "r"(b0), "r"(b1));
}
__device__ __forceinline__ uint64_t f2pk(float x, float y) {
    uint64_t r; asm("mov.b64 %0, {%1,%2};" : "=l"(r) : "f"(x), "f"(y)); return r;
}
__device__ __forceinline__ void f2un(uint64_t v, float& x, float& y) {
    asm("mov.b64 {%0,%1}, %2;" : "=f"(x), "=f"(y) : "l"(v));
}
__device__ __forceinline__ uint64_t fma2(uint64_t a, uint64_t b, uint64_t c) {
    uint64_t d; asm("fma.rn.f32x2 %0, %1, %2, %3;" : "=l"(d) : "l"(a), "l"(b), "l"(c)); return d;
}
__device__ __forceinline__ uint64_t mul2(uint64_t a, uint64_t b) {
    uint64_t d; asm("mul.rn.f32x2 %0, %1, %2;" : "=l"(d) : "l"(a), "l"(b)); return d;
}

// ---------------- packing: W [L][K][N] -> [N][K/2] fp16 hi/lo x256 ------
__global__ void pack_w_t(const float* __restrict__ W, uint32_t* __restrict__ Oh,
                         uint32_t* __restrict__ Ol, int K, int N) {
    __shared__ float s[64][33];
    int K2 = K >> 1;
    const float* Wl = W + (size_t)blockIdx.z * K * N;
    uint32_t* OhL = Oh + (size_t)blockIdx.z * N * K2;
    uint32_t* OlL = Ol + (size_t)blockIdx.z * N * K2;
    int k0 = blockIdx.x * 64, n0 = blockIdx.y * 32;
    int rr = threadIdx.x >> 5, cc = threadIdx.x & 31;
    #pragma unroll
    for (int i = 0; i < 8; i++)
        s[rr + i * 8][cc] = Wl[(size_t)(k0 + rr + i * 8) * N + n0 + cc];
    __syncthreads();
    #pragma unroll
    for (int i = 0; i < 4; i++) {
        int n = rr + i * 8;
        uint32_t h, l;
        cvt2h(s[2 * cc][n] * 256.f, s[2 * cc + 1][n] * 256.f, h, l);
        OhL[(size_t)(n0 + n) * K2 + (k0 >> 1) + cc] = h;
        OlL[(size_t)(n0 + n) * K2 + (k0 >> 1) + cc] = l;
    }
}
__global__ void pack_headf(const float* __restrict__ W, uint32_t* __restrict__ Oh,
                           uint32_t* __restrict__ Ol) {
    int id = blockIdx.x * 256 + threadIdx.x;
    if (id >= VP * K2D) return;
    int n = id / K2D, kp = id - n * K2D;
    float x = 0.f, y = 0.f;
    if (n < VV) { const float* p = W + (size_t)n * DD + 2 * kp; x = p[0] * 256.f; y = p[1] * 256.f; }
    uint32_t h, l;
    cvt2h(x, y, h, l);
    Oh[id] = h; Ol[id] = l;
}

// ---------------- LN machinery ----------------
__device__ __forceinline__ float blk_sum(float v, float* red) {
    #pragma unroll
    for (int o = 16; o; o >>= 1) v += __shfl_xor_sync(0xffffffffu, v, o);
    if ((threadIdx.x & 31) == 0) red[threadIdx.x >> 5] = v;
    __syncthreads();
    float s = (threadIdx.x < 8) ? red[threadIdx.x] : 0.0f;
    #pragma unroll
    for (int o = 4; o; o >>= 1) s += __shfl_xor_sync(0xffffffffu, s, o);
    if (threadIdx.x == 0) red[0] = s;
    __syncthreads();
    s = red[0];
    __syncthreads();
    return s;
}

__device__ __forceinline__ void ln_body(float* v, float s, float ss, float* vb,
                                        const float* w, const float* b, int row,
                                        uint32_t* PF) {
    float mu = s * (1.0f / DD);
    float r = rsqrtf(ss * (1.0f / DD) - mu * mu + 1e-5f);
    #pragma unroll
    for (int i = 0; i < 3; i++) {
        int c = threadIdx.x + i * 256;
        vb[c] = (v[i] - mu) * r * w[c] + b[c];
    }
    __syncthreads();
    #pragma unroll
    for (int i = 0; i < 2; i++) {
        int p = threadIdx.x + i * 256;
        if (p < K2D)
            PF[(size_t)row * K2D + p] = pkh(vb[2 * p], vb[2 * p + 1]);
    }
}

__global__ void embed_ln_pack(const int* __restrict__ tok, const float* __restrict__ wte,
                              const float* __restrict__ wpe, float* __restrict__ x,
                              const float* __restrict__ w, const float* __restrict__ b,
                              uint32_t* __restrict__ PF) {
    __shared__ float vb[DD];
    __shared__ float red[32];
    int row = blockIdx.x, t = tok[row];
    const float* we = wte + (size_t)t * DD;
    const float* wp = wpe + (size_t)(row & (TT - 1)) * DD;
    float v[3], s = 0.f, ss = 0.f;
    #pragma unroll
    for (int i = 0; i < 3; i++) {
        int c = threadIdx.x + i * 256;
        v[i] = we[c] + wp[c];
        x[(size_t)row * DD + c] = v[i];
        s += v[i]; ss += v[i] * v[i];
    }
    s = blk_sum(s, red); ss = blk_sum(ss, red);
    ln_body(v, s, ss, vb, w, b, row, PF);
}

__global__ void red_ln_pack(const float* __restrict__ P, const float* __restrict__ bias,
                            float* __restrict__ x, const float* __restrict__ w,
                            const float* __restrict__ b, uint32_t* __restrict__ PF) {
    __shared__ float vb[DD];
    __shared__ float red[32];
    int row = blockIdx.x;
    float v[3], s = 0.f, ss = 0.f;
    #pragma unroll
    for (int i = 0; i < 3; i++) {
        int c = threadIdx.x + i * 256;
        size_t idx = (size_t)row * DD + c;
        float t = x[idx] + bias[c] + P[idx] + P[(size_t)NT * DD + idx] + P[2 * (size_t)NT * DD + idx];
        x[idx] = t;
        v[i] = t; s += t; ss += t * t;
    }
    s = blk_sum(s, red); ss = blk_sum(ss, red);
    ln_body(v, s, ss, vb, w, b, row, PF);
}

// ---------------- attention ----------------
__global__ void __launch_bounds__(128)
attn_kernel(const float* __restrict__ qkv, uint32_t* __restrict__ attF) {
    extern __shared__ __align__(16) unsigned sm_dyn[];
    float* Ks = (float*)sm_dyn;
    float* Vs = Ks + 4096;
    float* sc = Vs + 4096;
    int tid = threadIdx.x;
    int qt = blockIdx.x, h = blockIdx.y, b = blockIdx.z;
    int qpos = qt * 128 + tid;
    const float* base = qkv + (size_t)b * TT * D3;
    uint64_t q2[32], o2[32];
    {
        const float* qp = base + (size_t)qpos * D3 + h * HD;
        #pragma unroll
        for (int j = 0; j < 32; j++) q2[j] = f2pk(qp[2 * j], qp[2 * j + 1]);
    }
    #pragma unroll
    for (int j = 0; j < 32; j++) o2[j] = 0ull;
    float m = -1e30f, ssum = 0.f;
    int nkt = (qt + 1) * 2;
    for (int kt = 0; kt < nkt; kt++) {
        int k0 = kt * 64;
        __syncthreads();
        #pragma unroll
        for (int i = 0; i < 32; i++) {
            int idx = i * 128 + tid;
            int kk = idx >> 6, e = idx & 63;
            Ks[idx] = base[(size_t)(k0 + kk) * D3 + DD + h * HD + e];
            Vs[idx] = base[(size_t)(k0 + kk) * D3 + 2 * DD + h * HD + e];
        }
        __syncthreads();
        float tm = -1e30f;
        for (int kk = 0; kk < 64; kk++) {
            const uint64_t* kr = (const uint64_t*)(Ks + (kk << 6));
            uint64_t a0 = 0ull, a1 = 0ull, a2 = 0ull, a3 = 0ull;
            #pragma unroll
            for (int j = 0; j < 32; j += 4) {
                a0 = fma2(q2[j], kr[j], a0);
                a1 = fma2(q2[j + 1], kr[j + 1], a1);
                a2 = fma2(q2[j + 2], kr[j + 2], a2);
                a3 = fma2(q2[j + 3], kr[j + 3], a3);
            }
            float x0, y0, x1, y1, x2, y2, x3, y3;
            f2un(a0, x0, y0); f2un(a1, x1, y1); f2un(a2, x2, y2); f2un(a3, x3, y3);
            float sv = (((x0 + y0) + (x1 + y1)) + ((x2 + y2) + (x3 + y3))) * 0.125f;
            if (k0 + kk > qpos) sv = -1e30f;
            sc[kk * 128 + tid] = sv;
            tm = fmaxf(tm, sv);
        }
        float mn = fmaxf(m, tm);
        float cr = __expf(m - mn);
        m = mn; ssum *= cr;
        uint64_t cr2 = f2pk(cr, cr);
        #pragma unroll
        for (int j = 0; j < 32; j++) o2[j] = mul2(o2[j], cr2);
        for (int kk = 0; kk < 64; kk++) {
            float p = __expf(sc[kk * 128 + tid] - m);
            ssum += p;
            uint64_t p2 = f2pk(p, p);
            const uint64_t* vr = (const uint64_t*)(Vs + (kk << 6));
            #pragma unroll
            for (int j = 0; j < 32; j++) o2[j] = fma2(p2, vr[j], o2[j]);
        }
    }
    float inv = 1.0f / ssum;
    size_t row = (size_t)b * TT + qpos;
    #pragma unroll
    for (int t2 = 0; t2 < 32; t2++) {
        float ox, oy; f2un(o2[t2], ox, oy);
        attF[row * K2D + h * 32 + t2] = pkh(ox * inv, oy * inv);
    }
}

// ---------------- fp16 2-term MMA GEMM (ldmatrix), 128x128, BK=32 ------
// A fp16 pairs [M][K/2]; B fp16 hi/lo n-major [N][K/2] (x256).
// EPI: 0 store fp32 (+bias), 2 bias+GELU->fp16 pack, 3 split-K partial.
#define BUFS 24576
#define GEMM_SMEM 49152

template<int EPI, bool HASBIAS>
__global__ void __launch_bounds__(256, 2)
gemm_lm(const uint32_t* __restrict__ AF, const uint32_t* __restrict__ BhG,
        const uint32_t* __restrict__ BlG, const float* __restrict__ bias,
        float* __restrict__ C, uint32_t* __restrict__ PF,
        int N, int Kslice, int K2s) {
    extern __shared__ __align__(16) char smem[];
    uint32_t sbase = (uint32_t)__cvta_generic_to_shared(smem);
    int tid = threadIdx.x;
    int w = tid >> 5, lane = tid & 31;
    int wr = w >> 2, wc = w & 3;
    int q = lane >> 2, r4 = lane & 3;
    int jrow = ((lane >> 3) & 1) * 8 + (lane & 7);
    int gh = lane >> 4;
    int perm = (jrow >> 1) & 3;
    int row0 = blockIdx.x * 128, col0 = blockIdx.y * 128;
    int kofs = blockIdx.z * (Kslice >> 1);

    float acc[4][4][4];
    #pragma unroll
    for (int mi = 0; mi < 4; mi++)
        #pragma unroll
        for (int ni = 0; ni < 4; ni++)
            #pragma unroll
            for (int e = 0; e < 4; e++) acc[mi][ni][e] = 0.f;

    auto loadbuf = [&](int t, int buf) {
        uint32_t base = sbase + buf * BUFS;
        int kp0 = kofs + t * 16;
        #pragma unroll
        for (int i = 0; i < 2; i++) {
            int id = tid + i * 256;
            int mm = id >> 2, g = id & 3;
            uint32_t dst = base + (mm << 6) + ((g ^ ((mm >> 1) & 3)) << 4);
            cpa16(dst, AF + (size_t)(row0 + mm) * K2s + kp0 + g * 4);
        }
        #pragma unroll
        for (int i = 0; i < 2; i++) {
            int id = tid + i * 256;
            int nn = id >> 2, g = id & 3;
            uint32_t dst = base + 8192 + (nn << 6) + ((g ^ ((nn >> 1) & 3)) << 4);
            size_t off = (size_t)(col0 + nn) * K2s + kp0 + g * 4;
            cpa16(dst, BhG + off);
            cpa16(dst + 8192, BlG + off);
        }
    };

    int ntile = Kslice >> 5;
    loadbuf(0, 0);
    asm volatile("cp.async.commit_group;" ::: "memory");
    for (int t = 0; t < ntile; t++) {
        int buf = t & 1;
        if (t + 1 < ntile) {
            loadbuf(t + 1, buf ^ 1);
            asm volatile("cp.async.commit_group;" ::: "memory");
            asm volatile("cp.async.wait_group 1;" ::: "memory");
        } else {
            asm volatile("cp.async.wait_group 0;" ::: "memory");
        }
        __syncthreads();
        uint32_t base = sbase + buf * BUFS;
        #pragma unroll
        for (int s = 0; s < 2; s++) {
            int ks = 2 * s + gh;
            uint32_t ah[4][4], bh[2][4], bl[2][4];
            #pragma unroll
            for (int mi = 0; mi < 4; mi++)
                ldsm4(ah[mi], base + ((wr * 64 + mi * 16 + jrow) << 6) + ((ks ^ perm) << 4));
            #pragma unroll
            for (int p = 0; p < 2; p++) {
                uint32_t baddr = base + 8192 + ((wc * 32 + p * 16 + jrow) << 6) + ((ks ^ perm) << 4);
                ldsm4(bh[p], baddr);
                ldsm4(bl[p], baddr + 8192);
            }
            #pragma unroll
            for (int mi = 0; mi < 4; mi++)
                #pragma unroll
                for (int ni = 0; ni < 4; ni++) {
                    mmaf16(acc[mi][ni], ah[mi], bh[ni >> 1][ni & 1], bh[ni >> 1][2 + (ni & 1)]);
                    mmaf16(acc[mi][ni], ah[mi], bl[ni >> 1][ni & 1], bl[ni >> 1][2 + (ni & 1)]);
                }
        }
        __syncthreads();
    }

    const float cg = 0.7978845608028654f;
    #pragma unroll
    for (int mi = 0; mi < 4; mi++) {
        int rbase = row0 + wr * 64 + mi * 16 + q;
        #pragma unroll
        for (int ni = 0; ni < 4; ni++) {
            int cbase = col0 + wc * 32 + ni * 8 + 2 * r4;
            #pragma unroll
            for (int rg = 0; rg < 2; rg++) {
                int rr = rbase + rg * 8;
                float v0 = acc[mi][ni][rg * 2 + 0] * 0.00390625f;
                float v1 = acc[mi][ni][rg * 2 + 1] * 0.00390625f;
                if (HASBIAS) { v0 += bias[cbase]; v1 += bias[cbase + 1]; }
                if (EPI == 2) {
                    float u0 = cg * (v0 + 0.044715f * v0 * v0 * v0);
                    v0 = 0.5f * v0 * (1.0f + tanhf(u0));
                    float u1 = cg * (v1 + 0.044715f * v1 * v1 * v1);
                    v1 = 0.5f * v1 * (1.0f + tanhf(u1));
                    PF[(size_t)rr * (N >> 1) + (cbase >> 1)] = pkh(v0, v1);
                } else if (EPI == 3) {
                    size_t idx = ((size_t)blockIdx.z * NT + rr) * N + cbase;
                    C[idx] = v0;
                    C[idx + 1] = v1;
                } else {
                    size_t idx = (size_t)rr * N + cbase;
                    if (cbase < N) C[idx] = v0;
                    if (cbase + 1 < N) C[idx + 1] = v1;
                }
            }
        }
    }
}

// ---------------- host ----------------
extern "C" void kernel_launch(void* const* d_in, const int* in_sizes, int n_in,
                              void* d_out, int out_size) {
    const int*   tok    = (const int*)  d_in[0];
    const float* wte    = (const float*)d_in[1];
    const float* wpe    = (const float*)d_in[2];
    const float* ln1_w  = (const float*)d_in[3];
    const float* ln1_b  = (const float*)d_in[4];
    const float* attn_w = (const float*)d_in[5];
    const float* attn_b = (const float*)d_in[6];
    const float* proj_w = (const float*)d_in[7];
    const float* proj_b = (const float*)d_in[8];
    const float* ln2_w  = (const float*)d_in[9];
    const float* ln2_b  = (const float*)d_in[10];
    const float* fc_w   = (const float*)d_in[11];
    const float* fc_b   = (const float*)d_in[12];
    const float* fc2_w  = (const float*)d_in[13];
    const float* fc2_b  = (const float*)d_in[14];
    const float* lnf_w  = (const float*)d_in[15];
    const float* lnf_b  = (const float*)d_in[16];
    const float* head_w = (const float*)d_in[17];
    float* out = (float*)d_out;

    float *x, *qkv;
    uint32_t *hF, *atF, *ffF;
    cudaGetSymbolAddress((void**)&x, g_x);
    cudaGetSymbolAddress((void**)&qkv, g_qkv);
    cudaGetSymbolAddress((void**)&hF, g_hF);
    cudaGetSymbolAddress((void**)&atF, g_atF);
    cudaGetSymbolAddress((void**)&ffF, g_ffF);
    uint32_t *wq_h, *wq_l, *wp_h, *wp_l, *wf_h, *wf_l, *w2_h, *w2_l, *wh_h, *wh_l;
    cudaGetSymbolAddress((void**)&wq_h, g_wq_h);
    cudaGetSymbolAddress((void**)&wq_l, g_wq_l);
    cudaGetSymbolAddress((void**)&wp_h, g_wp_h);
    cudaGetSymbolAddress((void**)&wp_l, g_wp_l);
    cudaGetSymbolAddress((void**)&wf_h, g_wf_h);
    cudaGetSymbolAddress((void**)&wf_l, g_wf_l);
    cudaGetSymbolAddress((void**)&w2_h, g_w2_h);
    cudaGetSymbolAddress((void**)&w2_l, g_w2_l);
    cudaGetSymbolAddress((void**)&wh_h, g_wh_h);
    cudaGetSymbolAddress((void**)&wh_l, g_wh_l);

    cudaFuncSetAttribute(gemm_lm<0, true >, cudaFuncAttributeMaxDynamicSharedMemorySize, GEMM_SMEM);
    cudaFuncSetAttribute(gemm_lm<2, true >, cudaFuncAttributeMaxDynamicSharedMemorySize, GEMM_SMEM);
    cudaFuncSetAttribute(gemm_lm<3, false>, cudaFuncAttributeMaxDynamicSharedMemorySize, GEMM_SMEM);
    cudaFuncSetAttribute(gemm_lm<0, false>, cudaFuncAttributeMaxDynamicSharedMemorySize, GEMM_SMEM);
    cudaFuncSetAttribute(attn_kernel, cudaFuncAttributeMaxDynamicSharedMemorySize, 65536);

    pack_w_t<<<dim3(12, 72, LL), 256>>>(attn_w, wq_h, wq_l, DD, D3);
    pack_w_t<<<dim3(12, 24, LL), 256>>>(proj_w, wp_h, wp_l, DD, DD);
    pack_w_t<<<dim3(12, 96, LL), 256>>>(fc_w,  wf_h, wf_l, DD, FF);
    pack_w_t<<<dim3(48, 24, LL), 256>>>(fc2_w, w2_h, w2_l, FF, DD);
    pack_headf<<<(VP * K2D + 255) / 256, 256>>>(head_w, wh_h, wh_l);

    embed_ln_pack<<<NT, 256>>>(tok, wte, wpe, x, ln1_w, ln1_b, hF);

    for (int l = 0; l < LL; l++) {
        size_t oq = (size_t)l * D3 * K2D, op = (size_t)l * DD * K2D;
        size_t of = (size_t)l * FF * K2D, o2 = (size_t)l * DD * K2F;

        gemm_lm<0, true><<<dim3(NT / 128, D3 / 128, 1), 256, GEMM_SMEM>>>(
            hF, wq_h + oq, wq_l + oq, attn_b + l * D3, qkv, nullptr, D3, DD, K2D);
        attn_kernel<<<dim3(TT / 128, HH, 2), 128, 65536>>>(qkv, atF);
        gemm_lm<3, false><<<dim3(NT / 128, DD / 128, 3), 256, GEMM_SMEM>>>(
            atF, wp_h + op, wp_l + op, nullptr, qkv, nullptr, DD, DD / 3, K2D);
        red_ln_pack<<<NT, 256>>>(qkv, proj_b + l * DD, x, ln2_w + l * DD, ln2_b + l * DD, hF);
        gemm_lm<2, true><<<dim3(NT / 128, FF / 128, 1), 256, GEMM_SMEM>>>(
            hF, wf_h + of, wf_l + of, fc_b + l * FF, nullptr, ffF, FF, DD, K2D);
        gemm_lm<3, false><<<dim3(NT / 128, DD / 128, 3), 256, GEMM_SMEM>>>(
            ffF, w2_h + o2, w2_l + o2, nullptr, qkv, nullptr, DD, FF / 3, K2F);
        const float* nw = (l < LL - 1) ? ln1_w + (l + 1) * DD : lnf_w;
        const float* nb = (l < LL - 1) ? ln1_b + (l + 1) * DD : lnf_b;
        red_ln_pack<<<NT, 256>>>(qkv, fc2_b + l * DD, x, nw, nb, hF);
    }

    gemm_lm<0, false><<<dim3(NT / 128, VP / 128, 1), 256, GEMM_SMEM>>>(
        hF, wh_h, wh_l, nullptr, out, nullptr, VV, DD, K2D);
}

// round 9
// speedup vs baseline: 6.4557x; 1.0907x over previous
#include <cuda_runtime.h>
#include <cuda_bf16.h>
#include <cuda_fp16.h>
#include <math.h>
#include <stdint.h>

#define NT 2048
#define TT 1024
#define DD 768
#define FF 3072
#define HH 12
#define HD 64
#define LL 4
#define VV 50257
#define D3 2304
#define VP 50304
#define K2D 384
#define K2F 1536

// ---------------- scratch ----------------
__device__ float    g_x[NT * DD];
__device__ float    g_qkv[NT * D3];   // also split-K partial buffer [3][NT][DD]
__device__ uint32_t g_hF[NT * K2D];
__device__ uint32_t g_atF[NT * K2D];
__device__ uint32_t g_ffF[NT * K2F];
// weights n-major [N][K/2] fp16-pair words, scaled x256, hi/lo
__device__ uint32_t g_wq_h[LL * D3 * K2D], g_wq_l[LL * D3 * K2D];
__device__ uint32_t g_wp_h[LL * DD * K2D], g_wp_l[LL * DD * K2D];
__device__ uint32_t g_wf_h[LL * FF * K2D], g_wf_l[LL * FF * K2D];
__device__ uint32_t g_w2_h[LL * DD * K2F], g_w2_l[LL * DD * K2F];
__device__ uint32_t g_wh_h[VP * K2D], g_wh_l[VP * K2D];

// ---------------- helpers ----------------
__device__ __forceinline__ uint32_t pkh(float x, float y) {
    __half hx = __float2half_rn(x), hy = __float2half_rn(y);
    return ((uint32_t)__half_as_ushort(hy) << 16) | (uint32_t)__half_as_ushort(hx);
}
__device__ __forceinline__ void cvt2h(float x, float y, uint32_t& hi, uint32_t& lo) {
    __half hx = __float2half_rn(x), hy = __float2half_rn(y);
    hi = ((uint32_t)__half_as_ushort(hy) << 16) | (uint32_t)__half_as_ushort(hx);
    lo = pkh(x - __half2float(hx), y - __half2float(hy));
}
__device__ __forceinline__ void cpa16(uint32_t d, const void* s) {
    asm volatile("cp.async.cg.shared.global [%0], [%1], 16;" :: "r"(d), "l"(s));
}
__device__ __forceinline__ void ldsm4(uint32_t* r, uint32_t a) {
    asm volatile("ldmatrix.sync.aligned.m8n8.x4.shared.b16 {%0,%1,%2,%3}, [%4];"
                 : "=r"(r[0]), "=r"(r[1]), "=r"(r[2]), "=r"(r[3]) : "r"(a));
}
__device__ __forceinline__ void mmaf16(float* c, const uint32_t* a, uint32_t b0, uint32_t b1) {
    asm volatile("mma.sync.aligned.m16n8k16.row.col.f32.f16.f16.f32 "
                 "{%0,%1,%2,%3}, {%4,%5,%6,%7}, {%8,%9}, {%0,%1,%2,%3};\n"
                 : "+f"(c[0]), "+f"(c[1]), "+f"(c[2]), "+f"(c[3])
                 : "r"(a[0]), "r"(a[1]), "r"(a[2]), "r"(a[3]), "r"(b0), "r"(b1));
}
__device__ __forceinline__ uint64_t f2pk(float x, float y) {
    uint64_t r; asm("mov.b64 %0, {%1,%2};" : "=l"(r) : "f"(x), "f"(y)); return r;
}
__device__ __forceinline__ void f2un(uint64_t v, float& x, float& y) {
    asm("mov.b64 {%0,%1}, %2;" : "=f"(x), "=f"(y) : "l"(v));
}
__device__ __forceinline__ uint64_t fma2(uint64_t a, uint64_t b, uint64_t c) {
    uint64_t d; asm("fma.rn.f32x2 %0, %1, %2, %3;" : "=l"(d) : "l"(a), "l"(b), "l"(c)); return d;
}
__device__ __forceinline__ uint64_t mul2(uint64_t a, uint64_t b) {
    uint64_t d; asm("mul.rn.f32x2 %0, %1, %2;" : "=l"(d) : "l"(a), "l"(b)); return d;
}

// ---------------- packing: W [L][K][N] -> [N][K/2] fp16 hi/lo x256 ------
__global__ void pack_w_t(const float* __restrict__ W, uint32_t* __restrict__ Oh,
                         uint32_t* __restrict__ Ol, int K, int N) {
    __shared__ float s[64][33];
    int K2 = K >> 1;
    const float* Wl = W + (size_t)blockIdx.z * K * N;
    uint32_t* OhL = Oh + (size_t)blockIdx.z * N * K2;
    uint32_t* OlL = Ol + (size_t)blockIdx.z * N * K2;
    int k0 = blockIdx.x * 64, n0 = blockIdx.y * 32;
    int rr = threadIdx.x >> 5, cc = threadIdx.x & 31;
    #pragma unroll
    for (int i = 0; i < 8; i++)
        s[rr + i * 8][cc] = Wl[(size_t)(k0 + rr + i * 8) * N + n0 + cc];
    __syncthreads();
    #pragma unroll
    for (int i = 0; i < 4; i++) {
        int n = rr + i * 8;
        uint32_t h, l;
        cvt2h(s[2 * cc][n] * 256.f, s[2 * cc + 1][n] * 256.f, h, l);
        OhL[(size_t)(n0 + n) * K2 + (k0 >> 1) + cc] = h;
        OlL[(size_t)(n0 + n) * K2 + (k0 >> 1) + cc] = l;
    }
}
__global__ void pack_headf(const float* __restrict__ W, uint32_t* __restrict__ Oh,
                           uint32_t* __restrict__ Ol) {
    int id = blockIdx.x * 256 + threadIdx.x;
    if (id >= VP * K2D) return;
    int n = id / K2D, kp = id - n * K2D;
    float x = 0.f, y = 0.f;
    if (n < VV) { const float* p = W + (size_t)n * DD + 2 * kp; x = p[0] * 256.f; y = p[1] * 256.f; }
    uint32_t h, l;
    cvt2h(x, y, h, l);
    Oh[id] = h; Ol[id] = l;
}

// ---------------- LN machinery ----------------
__device__ __forceinline__ float blk_sum(float v, float* red) {
    #pragma unroll
    for (int o = 16; o; o >>= 1) v += __shfl_xor_sync(0xffffffffu, v, o);
    if ((threadIdx.x & 31) == 0) red[threadIdx.x >> 5] = v;
    __syncthreads();
    float s = (threadIdx.x < 8) ? red[threadIdx.x] : 0.0f;
    #pragma unroll
    for (int o = 4; o; o >>= 1) s += __shfl_xor_sync(0xffffffffu, s, o);
    if (threadIdx.x == 0) red[0] = s;
    __syncthreads();
    s = red[0];
    __syncthreads();
    return s;
}

__device__ __forceinline__ void ln_body(float* v, float s, float ss, float* vb,
                                        const float* w, const float* b, int row,
                                        uint32_t* PF) {
    float mu = s * (1.0f / DD);
    float r = rsqrtf(ss * (1.0f / DD) - mu * mu + 1e-5f);
    #pragma unroll
    for (int i = 0; i < 3; i++) {
        int c = threadIdx.x + i * 256;
        vb[c] = (v[i] - mu) * r * w[c] + b[c];
    }
    __syncthreads();
    #pragma unroll
    for (int i = 0; i < 2; i++) {
        int p = threadIdx.x + i * 256;
        if (p < K2D)
            PF[(size_t)row * K2D + p] = pkh(vb[2 * p], vb[2 * p + 1]);
    }
}

__global__ void embed_ln_pack(const int* __restrict__ tok, const float* __restrict__ wte,
                              const float* __restrict__ wpe, float* __restrict__ x,
                              const float* __restrict__ w, const float* __restrict__ b,
                              uint32_t* __restrict__ PF) {
    __shared__ float vb[DD];
    __shared__ float red[32];
    int row = blockIdx.x, t = tok[row];
    const float* we = wte + (size_t)t * DD;
    const float* wp = wpe + (size_t)(row & (TT - 1)) * DD;
    float v[3], s = 0.f, ss = 0.f;
    #pragma unroll
    for (int i = 0; i < 3; i++) {
        int c = threadIdx.x + i * 256;
        v[i] = we[c] + wp[c];
        x[(size_t)row * DD + c] = v[i];
        s += v[i]; ss += v[i] * v[i];
    }
    s = blk_sum(s, red); ss = blk_sum(ss, red);
    ln_body(v, s, ss, vb, w, b, row, PF);
}

__global__ void red_ln_pack(const float* __restrict__ P, const float* __restrict__ bias,
                            float* __restrict__ x, const float* __restrict__ w,
                            const float* __restrict__ b, uint32_t* __restrict__ PF) {
    __shared__ float vb[DD];
    __shared__ float red[32];
    int row = blockIdx.x;
    float v[3], s = 0.f, ss = 0.f;
    #pragma unroll
    for (int i = 0; i < 3; i++) {
        int c = threadIdx.x + i * 256;
        size_t idx = (size_t)row * DD + c;
        float t = x[idx] + bias[c] + P[idx] + P[(size_t)NT * DD + idx] + P[2 * (size_t)NT * DD + idx];
        x[idx] = t;
        v[i] = t; s += t; ss += t * t;
    }
    s = blk_sum(s, red); ss = blk_sum(ss, red);
    ln_body(v, s, ss, vb, w, b, row, PF);
}

// ---------------- attention ----------------
__global__ void __launch_bounds__(128)
attn_kernel(const float* __restrict__ qkv, uint32_t* __restrict__ attF) {
    extern __shared__ __align__(16) unsigned sm_dyn[];
    float* Ks = (float*)sm_dyn;
    float* Vs = Ks + 4096;
    float* sc = Vs + 4096;
    int tid = threadIdx.x;
    int qt = blockIdx.x, h = blockIdx.y, b = blockIdx.z;
    int qpos = qt * 128 + tid;
    const float* base = qkv + (size_t)b * TT * D3;
    uint64_t q2[32], o2[32];
    {
        const float* qp = base + (size_t)qpos * D3 + h * HD;
        #pragma unroll
        for (int j = 0; j < 32; j++) q2[j] = f2pk(qp[2 * j], qp[2 * j + 1]);
    }
    #pragma unroll
    for (int j = 0; j < 32; j++) o2[j] = 0ull;
    float m = -1e30f, ssum = 0.f;
    int nkt = (qt + 1) * 2;
    for (int kt = 0; kt < nkt; kt++) {
        int k0 = kt * 64;
        __syncthreads();
        #pragma unroll
        for (int i = 0; i < 32; i++) {
            int idx = i * 128 + tid;
            int kk = idx >> 6, e = idx & 63;
            Ks[idx] = base[(size_t)(k0 + kk) * D3 + DD + h * HD + e];
            Vs[idx] = base[(size_t)(k0 + kk) * D3 + 2 * DD + h * HD + e];
        }
        __syncthreads();
        float tm = -1e30f;
        for (int kk = 0; kk < 64; kk++) {
            const uint64_t* kr = (const uint64_t*)(Ks + (kk << 6));
            uint64_t a0 = 0ull, a1 = 0ull, a2 = 0ull, a3 = 0ull;
            #pragma unroll
            for (int j = 0; j < 32; j += 4) {
                a0 = fma2(q2[j], kr[j], a0);
                a1 = fma2(q2[j + 1], kr[j + 1], a1);
                a2 = fma2(q2[j + 2], kr[j + 2], a2);
                a3 = fma2(q2[j + 3], kr[j + 3], a3);
            }
            float x0, y0, x1, y1, x2, y2, x3, y3;
            f2un(a0, x0, y0); f2un(a1, x1, y1); f2un(a2, x2, y2); f2un(a3, x3, y3);
            float sv = (((x0 + y0) + (x1 + y1)) + ((x2 + y2) + (x3 + y3))) * 0.125f;
            if (k0 + kk > qpos) sv = -1e30f;
            sc[kk * 128 + tid] = sv;
            tm = fmaxf(tm, sv);
        }
        float mn = fmaxf(m, tm);
        float cr = __expf(m - mn);
        m = mn; ssum *= cr;
        uint64_t cr2 = f2pk(cr, cr);
        #pragma unroll
        for (int j = 0; j < 32; j++) o2[j] = mul2(o2[j], cr2);
        for (int kk = 0; kk < 64; kk++) {
            float p = __expf(sc[kk * 128 + tid] - m);
            ssum += p;
            uint64_t p2 = f2pk(p, p);
            const uint64_t* vr = (const uint64_t*)(Vs + (kk << 6));
            #pragma unroll
            for (int j = 0; j < 32; j++) o2[j] = fma2(p2, vr[j], o2[j]);
        }
    }
    float inv = 1.0f / ssum;
    size_t row = (size_t)b * TT + qpos;
    #pragma unroll
    for (int t2 = 0; t2 < 32; t2++) {
        float ox, oy; f2un(o2[t2], ox, oy);
        attF[row * K2D + h * 32 + t2] = pkh(ox * inv, oy * inv);
    }
}

// ---------------- fp16 MMA GEMM (ldmatrix), 128x128, BK=32 --------------
// A fp16 pairs [M][K/2]; B fp16 n-major [N][K/2] (x256), TERMS=1 hi only,
// TERMS=2 hi+lo. EPI: 0 store fp32 (+bias), 2 bias+GELU->fp16, 3 split-K.
#define BUFS 24576
#define GEMM_SMEM 49152

template<int EPI, bool HASBIAS, int TERMS>
__global__ void __launch_bounds__(256, 2)
gemm_lm(const uint32_t* __restrict__ AF, const uint32_t* __restrict__ BhG,
        const uint32_t* __restrict__ BlG, const float* __restrict__ bias,
        float* __restrict__ C, uint32_t* __restrict__ PF,
        int N, int Kslice, int K2s) {
    extern __shared__ __align__(16) char smem[];
    uint32_t sbase = (uint32_t)__cvta_generic_to_shared(smem);
    int tid = threadIdx.x;
    int w = tid >> 5, lane = tid & 31;
    int wr = w >> 2, wc = w & 3;
    int q = lane >> 2, r4 = lane & 3;
    int jrow = ((lane >> 3) & 1) * 8 + (lane & 7);
    int gh = lane >> 4;
    int perm = (jrow >> 1) & 3;
    int row0 = blockIdx.x * 128, col0 = blockIdx.y * 128;
    int kofs = blockIdx.z * (Kslice >> 1);

    float acc[4][4][4];
    #pragma unroll
    for (int mi = 0; mi < 4; mi++)
        #pragma unroll
        for (int ni = 0; ni < 4; ni++)
            #pragma unroll
            for (int e = 0; e < 4; e++) acc[mi][ni][e] = 0.f;

    auto loadbuf = [&](int t, int buf) {
        uint32_t base = sbase + buf * BUFS;
        int kp0 = kofs + t * 16;
        #pragma unroll
        for (int i = 0; i < 2; i++) {
            int id = tid + i * 256;
            int mm = id >> 2, g = id & 3;
            uint32_t dst = base + (mm << 6) + ((g ^ ((mm >> 1) & 3)) << 4);
            cpa16(dst, AF + (size_t)(row0 + mm) * K2s + kp0 + g * 4);
        }
        #pragma unroll
        for (int i = 0; i < 2; i++) {
            int id = tid + i * 256;
            int nn = id >> 2, g = id & 3;
            uint32_t dst = base + 8192 + (nn << 6) + ((g ^ ((nn >> 1) & 3)) << 4);
            size_t off = (size_t)(col0 + nn) * K2s + kp0 + g * 4;
            cpa16(dst, BhG + off);
            if (TERMS == 2) cpa16(dst + 8192, BlG + off);
        }
    };

    int ntile = Kslice >> 5;
    loadbuf(0, 0);
    asm volatile("cp.async.commit_group;" ::: "memory");
    for (int t = 0; t < ntile; t++) {
        int buf = t & 1;
        if (t + 1 < ntile) {
            loadbuf(t + 1, buf ^ 1);
            asm volatile("cp.async.commit_group;" ::: "memory");
            asm volatile("cp.async.wait_group 1;" ::: "memory");
        } else {
            asm volatile("cp.async.wait_group 0;" ::: "memory");
        }
        __syncthreads();
        uint32_t base = sbase + buf * BUFS;
        #pragma unroll
        for (int s = 0; s < 2; s++) {
            int ks = 2 * s + gh;
            uint32_t ah[4][4], bh[2][4];
            #pragma unroll
            for (int mi = 0; mi < 4; mi++)
                ldsm4(ah[mi], base + ((wr * 64 + mi * 16 + jrow) << 6) + ((ks ^ perm) << 4));
            #pragma unroll
            for (int p = 0; p < 2; p++)
                ldsm4(bh[p], base + 8192 + ((wc * 32 + p * 16 + jrow) << 6) + ((ks ^ perm) << 4));
            #pragma unroll
            for (int mi = 0; mi < 4; mi++)
                #pragma unroll
                for (int ni = 0; ni < 4; ni++)
                    mmaf16(acc[mi][ni], ah[mi], bh[ni >> 1][ni & 1], bh[ni >> 1][2 + (ni & 1)]);
            if (TERMS == 2) {
                uint32_t bl[2][4];
                #pragma unroll
                for (int p = 0; p < 2; p++)
                    ldsm4(bl[p], base + 16384 + ((wc * 32 + p * 16 + jrow) << 6) + ((ks ^ perm) << 4));
                #pragma unroll
                for (int mi = 0; mi < 4; mi++)
                    #pragma unroll
                    for (int ni = 0; ni < 4; ni++)
                        mmaf16(acc[mi][ni], ah[mi], bl[ni >> 1][ni & 1], bl[ni >> 1][2 + (ni & 1)]);
            }
        }
        __syncthreads();
    }

    const float cg = 0.7978845608028654f;
    #pragma unroll
    for (int mi = 0; mi < 4; mi++) {
        int rbase = row0 + wr * 64 + mi * 16 + q;
        #pragma unroll
        for (int ni = 0; ni < 4; ni++) {
            int cbase = col0 + wc * 32 + ni * 8 + 2 * r4;
            #pragma unroll
            for (int rg = 0; rg < 2; rg++) {
                int rr = rbase + rg * 8;
                float v0 = acc[mi][ni][rg * 2 + 0] * 0.00390625f;
                float v1 = acc[mi][ni][rg * 2 + 1] * 0.00390625f;
                if (HASBIAS) { v0 += bias[cbase]; v1 += bias[cbase + 1]; }
                if (EPI == 2) {
                    float u0 = cg * (v0 + 0.044715f * v0 * v0 * v0);
                    v0 = 0.5f * v0 * (1.0f + tanhf(u0));
                    float u1 = cg * (v1 + 0.044715f * v1 * v1 * v1);
                    v1 = 0.5f * v1 * (1.0f + tanhf(u1));
                    PF[(size_t)rr * (N >> 1) + (cbase >> 1)] = pkh(v0, v1);
                } else if (EPI == 3) {
                    size_t idx = ((size_t)blockIdx.z * NT + rr) * N + cbase;
                    C[idx] = v0;
                    C[idx + 1] = v1;
                } else {
                    size_t idx = (size_t)rr * N + cbase;
                    if (cbase < N) C[idx] = v0;
                    if (cbase + 1 < N) C[idx + 1] = v1;
                }
            }
        }
    }
}

// ---------------- host ----------------
extern "C" void kernel_launch(void* const* d_in, const int* in_sizes, int n_in,
                              void* d_out, int out_size) {
    const int*   tok    = (const int*)  d_in[0];
    const float* wte    = (const float*)d_in[1];
    const float* wpe    = (const float*)d_in[2];
    const float* ln1_w  = (const float*)d_in[3];
    const float* ln1_b  = (const float*)d_in[4];
    const float* attn_w = (const float*)d_in[5];
    const float* attn_b = (const float*)d_in[6];
    const float* proj_w = (const float*)d_in[7];
    const float* proj_b = (const float*)d_in[8];
    const float* ln2_w  = (const float*)d_in[9];
    const float* ln2_b  = (const float*)d_in[10];
    const float* fc_w   = (const float*)d_in[11];
    const float* fc_b   = (const float*)d_in[12];
    const float* fc2_w  = (const float*)d_in[13];
    const float* fc2_b  = (const float*)d_in[14];
    const float* lnf_w  = (const float*)d_in[15];
    const float* lnf_b  = (const float*)d_in[16];
    const float* head_w = (const float*)d_in[17];
    float* out = (float*)d_out;

    float *x, *qkv;
    uint32_t *hF, *atF, *ffF;
    cudaGetSymbolAddress((void**)&x, g_x);
    cudaGetSymbolAddress((void**)&qkv, g_qkv);
    cudaGetSymbolAddress((void**)&hF, g_hF);
    cudaGetSymbolAddress((void**)&atF, g_atF);
    cudaGetSymbolAddress((void**)&ffF, g_ffF);
    uint32_t *wq_h, *wq_l, *wp_h, *wp_l, *wf_h, *wf_l, *w2_h, *w2_l, *wh_h, *wh_l;
    cudaGetSymbolAddress((void**)&wq_h, g_wq_h);
    cudaGetSymbolAddress((void**)&wq_l, g_wq_l);
    cudaGetSymbolAddress((void**)&wp_h, g_wp_h);
    cudaGetSymbolAddress((void**)&wp_l, g_wp_l);
    cudaGetSymbolAddress((void**)&wf_h, g_wf_h);
    cudaGetSymbolAddress((void**)&wf_l, g_wf_l);
    cudaGetSymbolAddress((void**)&w2_h, g_w2_h);
    cudaGetSymbolAddress((void**)&w2_l, g_w2_l);
    cudaGetSymbolAddress((void**)&wh_h, g_wh_h);
    cudaGetSymbolAddress((void**)&wh_l, g_wh_l);

    cudaFuncSetAttribute(gemm_lm<0, true,  1>, cudaFuncAttributeMaxDynamicSharedMemorySize, GEMM_SMEM);
    cudaFuncSetAttribute(gemm_lm<2, true,  1>, cudaFuncAttributeMaxDynamicSharedMemorySize, GEMM_SMEM);
    cudaFuncSetAttribute(gemm_lm<3, false, 1>, cudaFuncAttributeMaxDynamicSharedMemorySize, GEMM_SMEM);
    cudaFuncSetAttribute(gemm_lm<0, false, 2>, cudaFuncAttributeMaxDynamicSharedMemorySize, GEMM_SMEM);
    cudaFuncSetAttribute(attn_kernel, cudaFuncAttributeMaxDynamicSharedMemorySize, 65536);

    pack_w_t<<<dim3(12, 72, LL), 256>>>(attn_w, wq_h, wq_l, DD, D3);
    pack_w_t<<<dim3(12, 24, LL), 256>>>(proj_w, wp_h, wp_l, DD, DD);
    pack_w_t<<<dim3(12, 96, LL), 256>>>(fc_w,  wf_h, wf_l, DD, FF);
    pack_w_t<<<dim3(48, 24, LL), 256>>>(fc2_w, w2_h, w2_l, FF, DD);
    pack_headf<<<(VP * K2D + 255) / 256, 256>>>(head_w, wh_h, wh_l);

    embed_ln_pack<<<NT, 256>>>(tok, wte, wpe, x, ln1_w, ln1_b, hF);

    for (int l = 0; l < LL; l++) {
        size_t oq = (size_t)l * D3 * K2D, op = (size_t)l * DD * K2D;
        size_t of = (size_t)l * FF * K2D, o2 = (size_t)l * DD * K2F;

        gemm_lm<0, true, 1><<<dim3(NT / 128, D3 / 128, 1), 256, GEMM_SMEM>>>(
            hF, wq_h + oq, wq_l + oq, attn_b + l * D3, qkv, nullptr, D3, DD, K2D);
        attn_kernel<<<dim3(TT / 128, HH, 2), 128, 65536>>>(qkv, atF);
        gemm_lm<3, false, 1><<<dim3(NT / 128, DD / 128, 3), 256, GEMM_SMEM>>>(
            atF, wp_h + op, wp_l + op, nullptr, qkv, nullptr, DD, DD / 3, K2D);
        red_ln_pack<<<NT, 256>>>(qkv, proj_b + l * DD, x, ln2_w + l * DD, ln2_b + l * DD, hF);
        gemm_lm<2, true, 1><<<dim3(NT / 128, FF / 128, 1), 256, GEMM_SMEM>>>(
            hF, wf_h + of, wf_l + of, fc_b + l * FF, nullptr, ffF, FF, DD, K2D);
        gemm_lm<3, false, 1><<<dim3(NT / 128, DD / 128, 3), 256, GEMM_SMEM>>>(
            ffF, w2_h + o2, w2_l + o2, nullptr, qkv, nullptr, DD, FF / 3, K2F);
        const float* nw = (l < LL - 1) ? ln1_w + (l + 1) * DD : lnf_w;
        const float* nb = (l < LL - 1) ? ln1_b + (l + 1) * DD : lnf_b;
        red_ln_pack<<<NT, 256>>>(qkv, fc2_b + l * DD, x, nw, nb, hF);
    }

    gemm_lm<0, false, 2><<<dim3(NT / 128, VP / 128, 1), 256, GEMM_SMEM>>>(
        hF, wh_h, wh_l, nullptr, out, nullptr, VV, DD, K2D);
}

// round 10
// speedup vs baseline: 6.6955x; 1.0372x over previous
#include <cuda_runtime.h>
#include <cuda_bf16.h>
#include <cuda_fp16.h>
#include <math.h>
#include <stdint.h>

#define NT 2048
#define TT 1024
#define DD 768
#define FF 3072
#define HH 12
#define HD 64
#define LL 4
#define VV 50257
#define D3 2304
#define VP 50304
#define K2D 384
#define K2F 1536

// ---------------- scratch ----------------
__device__ float    g_x[NT * DD];
__device__ float    g_qkv[NT * D3];   // also split-K partial buffer [3][NT][DD]
__device__ uint32_t g_hF[NT * K2D];
__device__ uint32_t g_atF[NT * K2D];
__device__ uint32_t g_ffF[NT * K2F];
// weights n-major [N][K/2] fp16-pair words, scaled x256, hi/lo
__device__ uint32_t g_wq_h[LL * D3 * K2D], g_wq_l[LL * D3 * K2D];
__device__ uint32_t g_wp_h[LL * DD * K2D], g_wp_l[LL * DD * K2D];
__device__ uint32_t g_wf_h[LL * FF * K2D], g_wf_l[LL * FF * K2D];
__device__ uint32_t g_w2_h[LL * DD * K2F], g_w2_l[LL * DD * K2F];
__device__ uint32_t g_wh_h[VP * K2D], g_wh_l[VP * K2D];

// ---------------- helpers ----------------
__device__ __forceinline__ uint32_t pkh(float x, float y) {
    __half hx = __float2half_rn(x), hy = __float2half_rn(y);
    return ((uint32_t)__half_as_ushort(hy) << 16) | (uint32_t)__half_as_ushort(hx);
}
__device__ __forceinline__ void cvt2h(float x, float y, uint32_t& hi, uint32_t& lo) {
    __half hx = __float2half_rn(x), hy = __float2half_rn(y);
    hi = ((uint32_t)__half_as_ushort(hy) << 16) | (uint32_t)__half_as_ushort(hx);
    lo = pkh(x - __half2float(hx), y - __half2float(hy));
}
__device__ __forceinline__ void cpa16(uint32_t d, const void* s) {
    asm volatile("cp.async.cg.shared.global [%0], [%1], 16;" :: "r"(d), "l"(s));
}
__device__ __forceinline__ void ldsm4(uint32_t* r, uint32_t a) {
    asm volatile("ldmatrix.sync.aligned.m8n8.x4.shared.b16 {%0,%1,%2,%3}, [%4];"
                 : "=r"(r[0]), "=r"(r[1]), "=r"(r[2]), "=r"(r[3]) : "r"(a));
}
__device__ __forceinline__ void mmaf16(float* c, const uint32_t* a, uint32_t b0, uint32_t b1) {
    asm volatile("mma.sync.aligned.m16n8k16.row.col.f32.f16.f16.f32 "
                 "{%0,%1,%2,%3}, {%4,%5,%6,%7}, {%8,%9}, {%0,%1,%2,%3};\n"
                 : "+f"(c[0]), "+f"(c[1]), "+f"(c[2]), "+f"(c[3])
                 : "r"(a[0]), "r"(a[1]), "r"(a[2]), "r"(a[3]), "r"(b0), "r"(b1));
}
__device__ __forceinline__ uint64_t f2pk(float x, float y) {
    uint64_t r; asm("mov.b64 %0, {%1,%2};" : "=l"(r) : "f"(x), "f"(y)); return r;
}
__device__ __forceinline__ void f2un(uint64_t v, float& x, float& y) {
    asm("mov.b64 {%0,%1}, %2;" : "=f"(x), "=f"(y) : "l"(v));
}
__device__ __forceinline__ uint64_t fma2(uint64_t a, uint64_t b, uint64_t c) {
    uint64_t d; asm("fma.rn.f32x2 %0, %1, %2, %3;" : "=l"(d) : "l"(a), "l"(b), "l"(c)); return d;
}
__device__ __forceinline__ uint64_t mul2(uint64_t a, uint64_t b) {
    uint64_t d; asm("mul.rn.f32x2 %0, %1, %2;" : "=l"(d) : "l"(a), "l"(b)); return d;
}

// ---------------- packing: W [L][K][N] -> [N][K/2] fp16 hi/lo x256 ------
__global__ void pack_w_t(const float* __restrict__ W, uint32_t* __restrict__ Oh,
                         uint32_t* __restrict__ Ol, int K, int N) {
    __shared__ float s[64][33];
    int K2 = K >> 1;
    const float* Wl = W + (size_t)blockIdx.z * K * N;
    uint32_t* OhL = Oh + (size_t)blockIdx.z * N * K2;
    uint32_t* OlL = Ol + (size_t)blockIdx.z * N * K2;
    int k0 = blockIdx.x * 64, n0 = blockIdx.y * 32;
    int rr = threadIdx.x >> 5, cc = threadIdx.x & 31;
    #pragma unroll
    for (int i = 0; i < 8; i++)
        s[rr + i * 8][cc] = Wl[(size_t)(k0 + rr + i * 8) * N + n0 + cc];
    __syncthreads();
    #pragma unroll
    for (int i = 0; i < 4; i++) {
        int n = rr + i * 8;
        uint32_t h, l;
        cvt2h(s[2 * cc][n] * 256.f, s[2 * cc + 1][n] * 256.f, h, l);
        OhL[(size_t)(n0 + n) * K2 + (k0 >> 1) + cc] = h;
        OlL[(size_t)(n0 + n) * K2 + (k0 >> 1) + cc] = l;
    }
}
__global__ void pack_headf(const float* __restrict__ W, uint32_t* __restrict__ Oh,
                           uint32_t* __restrict__ Ol) {
    int id = blockIdx.x * 256 + threadIdx.x;
    if (id >= VP * K2D) return;
    int n = id / K2D, kp = id - n * K2D;
    float x = 0.f, y = 0.f;
    if (n < VV) { const float* p = W + (size_t)n * DD + 2 * kp; x = p[0] * 256.f; y = p[1] * 256.f; }
    uint32_t h, l;
    cvt2h(x, y, h, l);
    Oh[id] = h; Ol[id] = l;
}

// ---------------- LN machinery ----------------
__device__ __forceinline__ float blk_sum(float v, float* red) {
    #pragma unroll
    for (int o = 16; o; o >>= 1) v += __shfl_xor_sync(0xffffffffu, v, o);
    if ((threadIdx.x & 31) == 0) red[threadIdx.x >> 5] = v;
    __syncthreads();
    float s = (threadIdx.x < 8) ? red[threadIdx.x] : 0.0f;
    #pragma unroll
    for (int o = 4; o; o >>= 1) s += __shfl_xor_sync(0xffffffffu, s, o);
    if (threadIdx.x == 0) red[0] = s;
    __syncthreads();
    s = red[0];
    __syncthreads();
    return s;
}

__device__ __forceinline__ void ln_body(float* v, float s, float ss, float* vb,
                                        const float* w, const float* b, int row,
                                        uint32_t* PF) {
    float mu = s * (1.0f / DD);
    float r = rsqrtf(ss * (1.0f / DD) - mu * mu + 1e-5f);
    #pragma unroll
    for (int i = 0; i < 3; i++) {
        int c = threadIdx.x + i * 256;
        vb[c] = (v[i] - mu) * r * w[c] + b[c];
    }
    __syncthreads();
    #pragma unroll
    for (int i = 0; i < 2; i++) {
        int p = threadIdx.x + i * 256;
        if (p < K2D)
            PF[(size_t)row * K2D + p] = pkh(vb[2 * p], vb[2 * p + 1]);
    }
}

__global__ void embed_ln_pack(const int* __restrict__ tok, const float* __restrict__ wte,
                              const float* __restrict__ wpe, float* __restrict__ x,
                              const float* __restrict__ w, const float* __restrict__ b,
                              uint32_t* __restrict__ PF) {
    __shared__ float vb[DD];
    __shared__ float red[32];
    int row = blockIdx.x, t = tok[row];
    const float* we = wte + (size_t)t * DD;
    const float* wp = wpe + (size_t)(row & (TT - 1)) * DD;
    float v[3], s = 0.f, ss = 0.f;
    #pragma unroll
    for (int i = 0; i < 3; i++) {
        int c = threadIdx.x + i * 256;
        v[i] = we[c] + wp[c];
        x[(size_t)row * DD + c] = v[i];
        s += v[i]; ss += v[i] * v[i];
    }
    s = blk_sum(s, red); ss = blk_sum(ss, red);
    ln_body(v, s, ss, vb, w, b, row, PF);
}

__global__ void red_ln_pack(const float* __restrict__ P, const float* __restrict__ bias,
                            float* __restrict__ x, const float* __restrict__ w,
                            const float* __restrict__ b, uint32_t* __restrict__ PF) {
    __shared__ float vb[DD];
    __shared__ float red[32];
    int row = blockIdx.x;
    float v[3], s = 0.f, ss = 0.f;
    #pragma unroll
    for (int i = 0; i < 3; i++) {
        int c = threadIdx.x + i * 256;
        size_t idx = (size_t)row * DD + c;
        float t = x[idx] + bias[c] + P[idx] + P[(size_t)NT * DD + idx] + P[2 * (size_t)NT * DD + idx];
        x[idx] = t;
        v[i] = t; s += t; ss += t * t;
    }
    s = blk_sum(s, red); ss = blk_sum(ss, red);
    ln_body(v, s, ss, vb, w, b, row, PF);
}

// ---------------- attention ----------------
__global__ void __launch_bounds__(128)
attn_kernel(const float* __restrict__ qkv, uint32_t* __restrict__ attF) {
    extern __shared__ __align__(16) unsigned sm_dyn[];
    float* Ks = (float*)sm_dyn;
    float* Vs = Ks + 4096;
    float* sc = Vs + 4096;
    int tid = threadIdx.x;
    int qt = blockIdx.x, h = blockIdx.y, b = blockIdx.z;
    int qpos = qt * 128 + tid;
    const float* base = qkv + (size_t)b * TT * D3;
    uint64_t q2[32], o2[32];
    {
        const float* qp = base + (size_t)qpos * D3 + h * HD;
        #pragma unroll
        for (int j = 0; j < 32; j++) q2[j] = f2pk(qp[2 * j], qp[2 * j + 1]);
    }
    #pragma unroll
    for (int j = 0; j < 32; j++) o2[j] = 0ull;
    float m = -1e30f, ssum = 0.f;
    int nkt = (qt + 1) * 2;
    for (int kt = 0; kt < nkt; kt++) {
        int k0 = kt * 64;
        __syncthreads();
        #pragma unroll
        for (int i = 0; i < 32; i++) {
            int idx = i * 128 + tid;
            int kk = idx >> 6, e = idx & 63;
            Ks[idx] = base[(size_t)(k0 + kk) * D3 + DD + h * HD + e];
            Vs[idx] = base[(size_t)(k0 + kk) * D3 + 2 * DD + h * HD + e];
        }
        __syncthreads();
        float tm = -1e30f;
        for (int kk = 0; kk < 64; kk++) {
            const uint64_t* kr = (const uint64_t*)(Ks + (kk << 6));
            uint64_t a0 = 0ull, a1 = 0ull, a2 = 0ull, a3 = 0ull;
            #pragma unroll
            for (int j = 0; j < 32; j += 4) {
                a0 = fma2(q2[j], kr[j], a0);
                a1 = fma2(q2[j + 1], kr[j + 1], a1);
                a2 = fma2(q2[j + 2], kr[j + 2], a2);
                a3 = fma2(q2[j + 3], kr[j + 3], a3);
            }
            float x0, y0, x1, y1, x2, y2, x3, y3;
            f2un(a0, x0, y0); f2un(a1, x1, y1); f2un(a2, x2, y2); f2un(a3, x3, y3);
            float sv = (((x0 + y0) + (x1 + y1)) + ((x2 + y2) + (x3 + y3))) * 0.125f;
            if (k0 + kk > qpos) sv = -1e30f;
            sc[kk * 128 + tid] = sv;
            tm = fmaxf(tm, sv);
        }
        float mn = fmaxf(m, tm);
        float cr = __expf(m - mn);
        m = mn; ssum *= cr;
        uint64_t cr2 = f2pk(cr, cr);
        #pragma unroll
        for (int j = 0; j < 32; j++) o2[j] = mul2(o2[j], cr2);
        for (int kk = 0; kk < 64; kk++) {
            float p = __expf(sc[kk * 128 + tid] - m);
            ssum += p;
            uint64_t p2 = f2pk(p, p);
            const uint64_t* vr = (const uint64_t*)(Vs + (kk << 6));
            #pragma unroll
            for (int j = 0; j < 32; j++) o2[j] = fma2(p2, vr[j], o2[j]);
        }
    }
    float inv = 1.0f / ssum;
    size_t row = (size_t)b * TT + qpos;
    #pragma unroll
    for (int t2 = 0; t2 < 32; t2++) {
        float ox, oy; f2un(o2[t2], ox, oy);
        attF[row * K2D + h * 32 + t2] = pkh(ox * inv, oy * inv);
    }
}

// ---------------- fp16 MMA GEMM (ldmatrix), 128x128, BK=64 --------------
// A fp16 pairs [M][K/2]; B fp16 n-major [N][K/2] (x256), TERMS=1 hi only,
// TERMS=2 hi+lo. EPI: 0 store fp32 (+bias), 2 bias+GELU->fp16, 3 split-K.
// smem per buffer: A 16K @0, Bh 16K @16K, (Bl 16K @32K). Row=128B, 8 granules,
// swizzle g ^ (row&7).
template<int EPI, bool HASBIAS, int TERMS>
__global__ void __launch_bounds__(256, 2)
gemm_lm(const uint32_t* __restrict__ AF, const uint32_t* __restrict__ BhG,
        const uint32_t* __restrict__ BlG, const float* __restrict__ bias,
        float* __restrict__ C, uint32_t* __restrict__ PF,
        int N, int Kslice, int K2s) {
    constexpr int BUFSZ = (TERMS == 2) ? 49152 : 32768;
    extern __shared__ __align__(16) char smem[];
    uint32_t sbase = (uint32_t)__cvta_generic_to_shared(smem);
    int tid = threadIdx.x;
    int w = tid >> 5, lane = tid & 31;
    int wr = w >> 2, wc = w & 3;
    int q = lane >> 2, r4 = lane & 3;
    int jrow = ((lane >> 3) & 1) * 8 + (lane & 7);
    int gh = lane >> 4;
    int perm = jrow & 7;
    int row0 = blockIdx.x * 128, col0 = blockIdx.y * 128;
    int kofs = blockIdx.z * (Kslice >> 1);

    float acc[4][4][4];
    #pragma unroll
    for (int mi = 0; mi < 4; mi++)
        #pragma unroll
        for (int ni = 0; ni < 4; ni++)
            #pragma unroll
            for (int e = 0; e < 4; e++) acc[mi][ni][e] = 0.f;

    auto loadbuf = [&](int t, int buf) {
        uint32_t base = sbase + buf * BUFSZ;
        int kp0 = kofs + t * 32;
        #pragma unroll
        for (int i = 0; i < 4; i++) {
            int id = tid + i * 256;
            int mm = id >> 3, g = id & 7;
            uint32_t dst = base + (mm << 7) + ((g ^ (mm & 7)) << 4);
            cpa16(dst, AF + (size_t)(row0 + mm) * K2s + kp0 + g * 4);
        }
        #pragma unroll
        for (int i = 0; i < 4; i++) {
            int id = tid + i * 256;
            int nn = id >> 3, g = id & 7;
            uint32_t dst = base + 16384 + (nn << 7) + ((g ^ (nn & 7)) << 4);
            size_t off = (size_t)(col0 + nn) * K2s + kp0 + g * 4;
            cpa16(dst, BhG + off);
            if (TERMS == 2) cpa16(dst + 16384, BlG + off);
        }
    };

    int ntile = Kslice >> 6;
    loadbuf(0, 0);
    asm volatile("cp.async.commit_group;" ::: "memory");
    for (int t = 0; t < ntile; t++) {
        int buf = t & 1;
        if (t + 1 < ntile) {
            loadbuf(t + 1, buf ^ 1);
            asm volatile("cp.async.commit_group;" ::: "memory");
            asm volatile("cp.async.wait_group 1;" ::: "memory");
        } else {
            asm volatile("cp.async.wait_group 0;" ::: "memory");
        }
        __syncthreads();
        uint32_t base = sbase + buf * BUFSZ;
        #pragma unroll
        for (int s = 0; s < 4; s++) {
            int ks = 2 * s + gh;
            uint32_t ah[4][4], bh[2][4];
            #pragma unroll
            for (int mi = 0; mi < 4; mi++)
                ldsm4(ah[mi], base + ((wr * 64 + mi * 16 + jrow) << 7) + ((ks ^ perm) << 4));
            #pragma unroll
            for (int p = 0; p < 2; p++)
                ldsm4(bh[p], base + 16384 + ((wc * 32 + p * 16 + jrow) << 7) + ((ks ^ perm) << 4));
            #pragma unroll
            for (int mi = 0; mi < 4; mi++)
                #pragma unroll
                for (int ni = 0; ni < 4; ni++)
                    mmaf16(acc[mi][ni], ah[mi], bh[ni >> 1][ni & 1], bh[ni >> 1][2 + (ni & 1)]);
            if (TERMS == 2) {
                uint32_t bl[2][4];
                #pragma unroll
                for (int p = 0; p < 2; p++)
                    ldsm4(bl[p], base + 32768 + ((wc * 32 + p * 16 + jrow) << 7) + ((ks ^ perm) << 4));
                #pragma unroll
                for (int mi = 0; mi < 4; mi++)
                    #pragma unroll
                    for (int ni = 0; ni < 4; ni++)
                        mmaf16(acc[mi][ni], ah[mi], bl[ni >> 1][ni & 1], bl[ni >> 1][2 + (ni & 1)]);
            }
        }
        __syncthreads();
    }

    const float cg = 0.7978845608028654f;
    #pragma unroll
    for (int mi = 0; mi < 4; mi++) {
        int rbase = row0 + wr * 64 + mi * 16 + q;
        #pragma unroll
        for (int ni = 0; ni < 4; ni++) {
            int cbase = col0 + wc * 32 + ni * 8 + 2 * r4;
            #pragma unroll
            for (int rg = 0; rg < 2; rg++) {
                int rr = rbase + rg * 8;
                float v0 = acc[mi][ni][rg * 2 + 0] * 0.00390625f;
                float v1 = acc[mi][ni][rg * 2 + 1] * 0.00390625f;
                if (HASBIAS) { v0 += bias[cbase]; v1 += bias[cbase + 1]; }
                if (EPI == 2) {
                    float u0 = cg * (v0 + 0.044715f * v0 * v0 * v0);
                    v0 = 0.5f * v0 * (1.0f + tanhf(u0));
                    float u1 = cg * (v1 + 0.044715f * v1 * v1 * v1);
                    v1 = 0.5f * v1 * (1.0f + tanhf(u1));
                    PF[(size_t)rr * (N >> 1) + (cbase >> 1)] = pkh(v0, v1);
                } else if (EPI == 3) {
                    size_t idx = ((size_t)blockIdx.z * NT + rr) * N + cbase;
                    C[idx] = v0;
                    C[idx + 1] = v1;
                } else {
                    size_t idx = (size_t)rr * N + cbase;
                    if (cbase < N) C[idx] = v0;
                    if (cbase + 1 < N) C[idx + 1] = v1;
                }
            }
        }
    }
}

#define GSM1 65536
#define GSM2 98304

// ---------------- host ----------------
extern "C" void kernel_launch(void* const* d_in, const int* in_sizes, int n_in,
                              void* d_out, int out_size) {
    const int*   tok    = (const int*)  d_in[0];
    const float* wte    = (const float*)d_in[1];
    const float* wpe    = (const float*)d_in[2];
    const float* ln1_w  = (const float*)d_in[3];
    const float* ln1_b  = (const float*)d_in[4];
    const float* attn_w = (const float*)d_in[5];
    const float* attn_b = (const float*)d_in[6];
    const float* proj_w = (const float*)d_in[7];
    const float* proj_b = (const float*)d_in[8];
    const float* ln2_w  = (const float*)d_in[9];
    const float* ln2_b  = (const float*)d_in[10];
    const float* fc_w   = (const float*)d_in[11];
    const float* fc_b   = (const float*)d_in[12];
    const float* fc2_w  = (const float*)d_in[13];
    const float* fc2_b  = (const float*)d_in[14];
    const float* lnf_w  = (const float*)d_in[15];
    const float* lnf_b  = (const float*)d_in[16];
    const float* head_w = (const float*)d_in[17];
    float* out = (float*)d_out;

    float *x, *qkv;
    uint32_t *hF, *atF, *ffF;
    cudaGetSymbolAddress((void**)&x, g_x);
    cudaGetSymbolAddress((void**)&qkv, g_qkv);
    cudaGetSymbolAddress((void**)&hF, g_hF);
    cudaGetSymbolAddress((void**)&atF, g_atF);
    cudaGetSymbolAddress((void**)&ffF, g_ffF);
    uint32_t *wq_h, *wq_l, *wp_h, *wp_l, *wf_h, *wf_l, *w2_h, *w2_l, *wh_h, *wh_l;
    cudaGetSymbolAddress((void**)&wq_h, g_wq_h);
    cudaGetSymbolAddress((void**)&wq_l, g_wq_l);
    cudaGetSymbolAddress((void**)&wp_h, g_wp_h);
    cudaGetSymbolAddress((void**)&wp_l, g_wp_l);
    cudaGetSymbolAddress((void**)&wf_h, g_wf_h);
    cudaGetSymbolAddress((void**)&wf_l, g_wf_l);
    cudaGetSymbolAddress((void**)&w2_h, g_w2_h);
    cudaGetSymbolAddress((void**)&w2_l, g_w2_l);
    cudaGetSymbolAddress((void**)&wh_h, g_wh_h);
    cudaGetSymbolAddress((void**)&wh_l, g_wh_l);

    cudaFuncSetAttribute(gemm_lm<0, true,  1>, cudaFuncAttributeMaxDynamicSharedMemorySize, GSM1);
    cudaFuncSetAttribute(gemm_lm<2, true,  1>, cudaFuncAttributeMaxDynamicSharedMemorySize, GSM1);
    cudaFuncSetAttribute(gemm_lm<3, false, 1>, cudaFuncAttributeMaxDynamicSharedMemorySize, GSM1);
    cudaFuncSetAttribute(gemm_lm<0, false, 2>, cudaFuncAttributeMaxDynamicSharedMemorySize, GSM2);
    cudaFuncSetAttribute(attn_kernel, cudaFuncAttributeMaxDynamicSharedMemorySize, 65536);

    pack_w_t<<<dim3(12, 72, LL), 256>>>(attn_w, wq_h, wq_l, DD, D3);
    pack_w_t<<<dim3(12, 24, LL), 256>>>(proj_w, wp_h, wp_l, DD, DD);
    pack_w_t<<<dim3(12, 96, LL), 256>>>(fc_w,  wf_h, wf_l, DD, FF);
    pack_w_t<<<dim3(48, 24, LL), 256>>>(fc2_w, w2_h, w2_l, FF, DD);
    pack_headf<<<(VP * K2D + 255) / 256, 256>>>(head_w, wh_h, wh_l);

    embed_ln_pack<<<NT, 256>>>(tok, wte, wpe, x, ln1_w, ln1_b, hF);

    for (int l = 0; l < LL; l++) {
        size_t oq = (size_t)l * D3 * K2D, op = (size_t)l * DD * K2D;
        size_t of = (size_t)l * FF * K2D, o2 = (size_t)l * DD * K2F;

        gemm_lm<0, true, 1><<<dim3(NT / 128, D3 / 128, 1), 256, GSM1>>>(
            hF, wq_h + oq, wq_l + oq, attn_b + l * D3, qkv, nullptr, D3, DD, K2D);
        attn_kernel<<<dim3(TT / 128, HH, 2), 128, 65536>>>(qkv, atF);
        gemm_lm<3, false, 1><<<dim3(NT / 128, DD / 128, 3), 256, GSM1>>>(
            atF, wp_h + op, wp_l + op, nullptr, qkv, nullptr, DD, DD / 3, K2D);
        red_ln_pack<<<NT, 256>>>(qkv, proj_b + l * DD, x, ln2_w + l * DD, ln2_b + l * DD, hF);
        gemm_lm<2, true, 1><<<dim3(NT / 128, FF / 128, 1), 256, GSM1>>>(
            hF, wf_h + of, wf_l + of, fc_b + l * FF, nullptr, ffF, FF, DD, K2D);
        gemm_lm<3, false, 1><<<dim3(NT / 128, DD / 128, 3), 256, GSM1>>>(
            ffF, w2_h + o2, w2_l + o2, nullptr, qkv, nullptr, DD, FF / 3, K2F);
        const float* nw = (l < LL - 1) ? ln1_w + (l + 1) * DD : lnf_w;
        const float* nb = (l < LL - 1) ? ln1_b + (l + 1) * DD : lnf_b;
        red_ln_pack<<<NT, 256>>>(qkv, fc2_b + l * DD, x, nw, nb, hF);
    }

    gemm_lm<0, false, 2><<<dim3(NT / 128, VP / 128, 1), 256, GSM2>>>(
        hF, wh_h, wh_l, nullptr, out, nullptr, VV, DD, K2D);
}

// round 11
// speedup vs baseline: 7.0428x; 1.0519x over previous
#include <cuda_runtime.h>
#include <cuda_bf16.h>
#include <cuda_fp16.h>
#include <math.h>
#include <stdint.h>

#define NT 2048
#define TT 1024
#define DD 768
#define FF 3072
#define HH 12
#define HD 64
#define LL 4
#define VV 50257
#define D3 2304
#define VP 50304
#define K2D 384
#define K2F 1536

// ---------------- scratch ----------------
__device__ float    g_x[NT * DD];
__device__ float    g_qkv[NT * D3];   // also split-K partial buffer [3][NT][DD]
__device__ uint32_t g_hF[NT * K2D];
__device__ uint32_t g_atF[NT * K2D];
__device__ uint32_t g_ffF[NT * K2F];
// weights n-major [N][K/2] fp16-pair words, scaled x256, hi/lo
__device__ uint32_t g_wq_h[LL * D3 * K2D], g_wq_l[LL * D3 * K2D];
__device__ uint32_t g_wp_h[LL * DD * K2D], g_wp_l[LL * DD * K2D];
__device__ uint32_t g_wf_h[LL * FF * K2D], g_wf_l[LL * FF * K2D];
__device__ uint32_t g_w2_h[LL * DD * K2F], g_w2_l[LL * DD * K2F];
__device__ uint32_t g_wh_h[VP * K2D], g_wh_l[VP * K2D];

// ---------------- helpers ----------------
__device__ __forceinline__ uint32_t pkh(float x, float y) {
    __half hx = __float2half_rn(x), hy = __float2half_rn(y);
    return ((uint32_t)__half_as_ushort(hy) << 16) | (uint32_t)__half_as_ushort(hx);
}
__device__ __forceinline__ void cvt2h(float x, float y, uint32_t& hi, uint32_t& lo) {
    __half hx = __float2half_rn(x), hy = __float2half_rn(y);
    hi = ((uint32_t)__half_as_ushort(hy) << 16) | (uint32_t)__half_as_ushort(hx);
    lo = pkh(x - __half2float(hx), y - __half2float(hy));
}
__device__ __forceinline__ void cpa16(uint32_t d, const void* s) {
    asm volatile("cp.async.cg.shared.global [%0], [%1], 16;" :: "r"(d), "l"(s));
}
__device__ __forceinline__ void ldsm4(uint32_t* r, uint32_t a) {
    asm volatile("ldmatrix.sync.aligned.m8n8.x4.shared.b16 {%0,%1,%2,%3}, [%4];"
                 : "=r"(r[0]), "=r"(r[1]), "=r"(r[2]), "=r"(r[3]) : "r"(a));
}
__device__ __forceinline__ void mmaf16(float* c, const uint32_t* a, uint32_t b0, uint32_t b1) {
    asm volatile("mma.sync.aligned.m16n8k16.row.col.f32.f16.f16.f32 "
                 "{%0,%1,%2,%3}, {%4,%5,%6,%7}, {%8,%9}, {%0,%1,%2,%3};\n"
                 : "+f"(c[0]), "+f"(c[1]), "+f"(c[2]), "+f"(c[3])
                 : "r"(a[0]), "r"(a[1]), "r"(a[2]), "r"(a[3]), "r"(b0), "r"(b1));
}
__device__ __forceinline__ uint64_t f2pk(float x, float y) {
    uint64_t r; asm("mov.b64 %0, {%1,%2};" : "=l"(r) : "f"(x), "f"(y)); return r;
}
__device__ __forceinline__ void f2un(uint64_t v, float& x, float& y) {
    asm("mov.b64 {%0,%1}, %2;" : "=f"(x), "=f"(y) : "l"(v));
}
__device__ __forceinline__ uint64_t fma2(uint64_t a, uint64_t b, uint64_t c) {
    uint64_t d; asm("fma.rn.f32x2 %0, %1, %2, %3;" : "=l"(d) : "l"(a), "l"(b), "l"(c)); return d;
}
__device__ __forceinline__ uint64_t mul2(uint64_t a, uint64_t b) {
    uint64_t d; asm("mul.rn.f32x2 %0, %1, %2;" : "=l"(d) : "l"(a), "l"(b)); return d;
}

// ---------------- packing: W [L][K][N] -> [N][K/2] fp16 hi/lo x256 ------
__global__ void pack_w_t(const float* __restrict__ W, uint32_t* __restrict__ Oh,
                         uint32_t* __restrict__ Ol, int K, int N) {
    __shared__ float s[64][33];
    int K2 = K >> 1;
    const float* Wl = W + (size_t)blockIdx.z * K * N;
    uint32_t* OhL = Oh + (size_t)blockIdx.z * N * K2;
    uint32_t* OlL = Ol + (size_t)blockIdx.z * N * K2;
    int k0 = blockIdx.x * 64, n0 = blockIdx.y * 32;
    int rr = threadIdx.x >> 5, cc = threadIdx.x & 31;
    #pragma unroll
    for (int i = 0; i < 8; i++)
        s[rr + i * 8][cc] = Wl[(size_t)(k0 + rr + i * 8) * N + n0 + cc];
    __syncthreads();
    #pragma unroll
    for (int i = 0; i < 4; i++) {
        int n = rr + i * 8;
        uint32_t h, l;
        cvt2h(s[2 * cc][n] * 256.f, s[2 * cc + 1][n] * 256.f, h, l);
        OhL[(size_t)(n0 + n) * K2 + (k0 >> 1) + cc] = h;
        OlL[(size_t)(n0 + n) * K2 + (k0 >> 1) + cc] = l;
    }
}
__global__ void pack_headf(const float* __restrict__ W, uint32_t* __restrict__ Oh,
                           uint32_t* __restrict__ Ol) {
    int id = blockIdx.x * 256 + threadIdx.x;
    if (id >= VP * K2D) return;
    int n = id / K2D, kp = id - n * K2D;
    float x = 0.f, y = 0.f;
    if (n < VV) { const float* p = W + (size_t)n * DD + 2 * kp; x = p[0] * 256.f; y = p[1] * 256.f; }
    uint32_t h, l;
    cvt2h(x, y, h, l);
    Oh[id] = h; Ol[id] = l;
}

// ---------------- LN machinery ----------------
__device__ __forceinline__ float blk_sum(float v, float* red) {
    #pragma unroll
    for (int o = 16; o; o >>= 1) v += __shfl_xor_sync(0xffffffffu, v, o);
    if ((threadIdx.x & 31) == 0) red[threadIdx.x >> 5] = v;
    __syncthreads();
    float s = (threadIdx.x < 8) ? red[threadIdx.x] : 0.0f;
    #pragma unroll
    for (int o = 4; o; o >>= 1) s += __shfl_xor_sync(0xffffffffu, s, o);
    if (threadIdx.x == 0) red[0] = s;
    __syncthreads();
    s = red[0];
    __syncthreads();
    return s;
}

__device__ __forceinline__ void ln_body(float* v, float s, float ss, float* vb,
                                        const float* w, const float* b, int row,
                                        uint32_t* PF) {
    float mu = s * (1.0f / DD);
    float r = rsqrtf(ss * (1.0f / DD) - mu * mu + 1e-5f);
    #pragma unroll
    for (int i = 0; i < 3; i++) {
        int c = threadIdx.x + i * 256;
        vb[c] = (v[i] - mu) * r * w[c] + b[c];
    }
    __syncthreads();
    #pragma unroll
    for (int i = 0; i < 2; i++) {
        int p = threadIdx.x + i * 256;
        if (p < K2D)
            PF[(size_t)row * K2D + p] = pkh(vb[2 * p], vb[2 * p + 1]);
    }
}

__global__ void embed_ln_pack(const int* __restrict__ tok, const float* __restrict__ wte,
                              const float* __restrict__ wpe, float* __restrict__ x,
                              const float* __restrict__ w, const float* __restrict__ b,
                              uint32_t* __restrict__ PF) {
    __shared__ float vb[DD];
    __shared__ float red[32];
    int row = blockIdx.x, t = tok[row];
    const float* we = wte + (size_t)t * DD;
    const float* wp = wpe + (size_t)(row & (TT - 1)) * DD;
    float v[3], s = 0.f, ss = 0.f;
    #pragma unroll
    for (int i = 0; i < 3; i++) {
        int c = threadIdx.x + i * 256;
        v[i] = we[c] + wp[c];
        x[(size_t)row * DD + c] = v[i];
        s += v[i]; ss += v[i] * v[i];
    }
    s = blk_sum(s, red); ss = blk_sum(ss, red);
    ln_body(v, s, ss, vb, w, b, row, PF);
}

__global__ void red_ln_pack(const float* __restrict__ P, const float* __restrict__ bias,
                            float* __restrict__ x, const float* __restrict__ w,
                            const float* __restrict__ b, uint32_t* __restrict__ PF) {
    __shared__ float vb[DD];
    __shared__ float red[32];
    int row = blockIdx.x;
    float v[3], s = 0.f, ss = 0.f;
    #pragma unroll
    for (int i = 0; i < 3; i++) {
        int c = threadIdx.x + i * 256;
        size_t idx = (size_t)row * DD + c;
        float t = x[idx] + bias[c] + P[idx] + P[(size_t)NT * DD + idx] + P[2 * (size_t)NT * DD + idx];
        x[idx] = t;
        v[i] = t; s += t; ss += t * t;
    }
    s = blk_sum(s, red); ss = blk_sum(ss, red);
    ln_body(v, s, ss, vb, w, b, row, PF);
}

// ---------------- attention (float4-staged K/V) ----------------
__global__ void __launch_bounds__(128)
attn_kernel(const float* __restrict__ qkv, uint32_t* __restrict__ attF) {
    extern __shared__ __align__(16) unsigned sm_dyn[];
    float* Ks = (float*)sm_dyn;
    float* Vs = Ks + 4096;
    float* sc = Vs + 4096;
    int tid = threadIdx.x;
    int qt = blockIdx.x, h = blockIdx.y, b = blockIdx.z;
    int qpos = qt * 128 + tid;
    const float* base = qkv + (size_t)b * TT * D3;
    uint64_t q2[32], o2[32];
    {
        const float* qp = base + (size_t)qpos * D3 + h * HD;
        #pragma unroll
        for (int j = 0; j < 32; j++) q2[j] = f2pk(qp[2 * j], qp[2 * j + 1]);
    }
    #pragma unroll
    for (int j = 0; j < 32; j++) o2[j] = 0ull;
    float m = -1e30f, ssum = 0.f;
    int nkt = (qt + 1) * 2;
    for (int kt = 0; kt < nkt; kt++) {
        int k0 = kt * 64;
        __syncthreads();
        #pragma unroll
        for (int i = 0; i < 8; i++) {
            int idx = (i * 128 + tid) * 4;
            int kk = idx >> 6, e = idx & 63;
            const float* rowp = base + (size_t)(k0 + kk) * D3 + h * HD + e;
            *(float4*)(Ks + idx) = *(const float4*)(rowp + DD);
            *(float4*)(Vs + idx) = *(const float4*)(rowp + 2 * DD);
        }
        __syncthreads();
        float tm = -1e30f;
        for (int kk = 0; kk < 64; kk++) {
            const uint64_t* kr = (const uint64_t*)(Ks + (kk << 6));
            uint64_t a0 = 0ull, a1 = 0ull, a2 = 0ull, a3 = 0ull;
            #pragma unroll
            for (int j = 0; j < 32; j += 4) {
                a0 = fma2(q2[j], kr[j], a0);
                a1 = fma2(q2[j + 1], kr[j + 1], a1);
                a2 = fma2(q2[j + 2], kr[j + 2], a2);
                a3 = fma2(q2[j + 3], kr[j + 3], a3);
            }
            float x0, y0, x1, y1, x2, y2, x3, y3;
            f2un(a0, x0, y0); f2un(a1, x1, y1); f2un(a2, x2, y2); f2un(a3, x3, y3);
            float sv = (((x0 + y0) + (x1 + y1)) + ((x2 + y2) + (x3 + y3))) * 0.125f;
            if (k0 + kk > qpos) sv = -1e30f;
            sc[kk * 128 + tid] = sv;
            tm = fmaxf(tm, sv);
        }
        float mn = fmaxf(m, tm);
        float cr = __expf(m - mn);
        m = mn; ssum *= cr;
        uint64_t cr2 = f2pk(cr, cr);
        #pragma unroll
        for (int j = 0; j < 32; j++) o2[j] = mul2(o2[j], cr2);
        for (int kk = 0; kk < 64; kk++) {
            float p = __expf(sc[kk * 128 + tid] - m);
            ssum += p;
            uint64_t p2 = f2pk(p, p);
            const uint64_t* vr = (const uint64_t*)(Vs + (kk << 6));
            #pragma unroll
            for (int j = 0; j < 32; j++) o2[j] = fma2(p2, vr[j], o2[j]);
        }
    }
    float inv = 1.0f / ssum;
    size_t row = (size_t)b * TT + qpos;
    #pragma unroll
    for (int t2 = 0; t2 < 32; t2++) {
        float ox, oy; f2un(o2[t2], ox, oy);
        attF[row * K2D + h * 32 + t2] = pkh(ox * inv, oy * inv);
    }
}

// ---------------- fp16 MMA GEMM (ldmatrix), 128x128, BK=64 --------------
// A fp16 pairs [M][K/2]; B fp16 n-major [N][K/2] (x256), TERMS=1 hi only
// (3-stage pipeline), TERMS=2 hi+lo (2-stage). EPI: 0 store fp32 (+bias),
// 2 bias+GELU->fp16, 3 split-K. smem/buffer: A 16K @0, Bh 16K @16K,
// (Bl 16K @32K). Row=128B, 8 granules, swizzle g ^ (row&7).
template<int EPI, bool HASBIAS, int TERMS>
__global__ void __launch_bounds__(256, 2)
gemm_lm(const uint32_t* __restrict__ AF, const uint32_t* __restrict__ BhG,
        const uint32_t* __restrict__ BlG, const float* __restrict__ bias,
        float* __restrict__ C, uint32_t* __restrict__ PF,
        int N, int Kslice, int K2s) {
    constexpr int BUFSZ  = (TERMS == 2) ? 49152 : 32768;
    constexpr int STAGES = (TERMS == 2) ? 2 : 3;
    extern __shared__ __align__(16) char smem[];
    uint32_t sbase = (uint32_t)__cvta_generic_to_shared(smem);
    int tid = threadIdx.x;
    int w = tid >> 5, lane = tid & 31;
    int wr = w >> 2, wc = w & 3;
    int q = lane >> 2, r4 = lane & 3;
    int jrow = ((lane >> 3) & 1) * 8 + (lane & 7);
    int gh = lane >> 4;
    int perm = jrow & 7;
    int row0 = blockIdx.x * 128, col0 = blockIdx.y * 128;
    int kofs = blockIdx.z * (Kslice >> 1);

    float acc[4][4][4];
    #pragma unroll
    for (int mi = 0; mi < 4; mi++)
        #pragma unroll
        for (int ni = 0; ni < 4; ni++)
            #pragma unroll
            for (int e = 0; e < 4; e++) acc[mi][ni][e] = 0.f;

    auto loadbuf = [&](int t, int buf) {
        uint32_t base = sbase + buf * BUFSZ;
        int kp0 = kofs + t * 32;
        #pragma unroll
        for (int i = 0; i < 4; i++) {
            int id = tid + i * 256;
            int mm = id >> 3, g = id & 7;
            uint32_t dst = base + (mm << 7) + ((g ^ (mm & 7)) << 4);
            cpa16(dst, AF + (size_t)(row0 + mm) * K2s + kp0 + g * 4);
        }
        #pragma unroll
        for (int i = 0; i < 4; i++) {
            int id = tid + i * 256;
            int nn = id >> 3, g = id & 7;
            uint32_t dst = base + 16384 + (nn << 7) + ((g ^ (nn & 7)) << 4);
            size_t off = (size_t)(col0 + nn) * K2s + kp0 + g * 4;
            cpa16(dst, BhG + off);
            if (TERMS == 2) cpa16(dst + 16384, BlG + off);
        }
    };

    int ntile = Kslice >> 6;
    #pragma unroll
    for (int pt = 0; pt < STAGES - 1; pt++) {
        if (pt < ntile) {
            loadbuf(pt, pt % STAGES);
            asm volatile("cp.async.commit_group;" ::: "memory");
        }
    }
    for (int t = 0; t < ntile; t++) {
        int buf = t % STAGES;
        if (t + STAGES - 1 < ntile) {
            // buffer (t+STAGES-1)%STAGES == (t-1)%STAGES: freed by iter t-1 tail sync
            loadbuf(t + STAGES - 1, (t + STAGES - 1) % STAGES);
            asm volatile("cp.async.commit_group;" ::: "memory");
        }
        // wait until load t complete: allow pending = (#loads issued after t)
        int p = ntile - t;
        if (STAGES == 3) {
            if (p > 2)      asm volatile("cp.async.wait_group 2;" ::: "memory");
            else if (p > 1) asm volatile("cp.async.wait_group 1;" ::: "memory");
            else            asm volatile("cp.async.wait_group 0;" ::: "memory");
        } else {
            if (p > 1)      asm volatile("cp.async.wait_group 1;" ::: "memory");
            else            asm volatile("cp.async.wait_group 0;" ::: "memory");
        }
        __syncthreads();
        uint32_t base = sbase + buf * BUFSZ;
        #pragma unroll
        for (int s = 0; s < 4; s++) {
            int ks = 2 * s + gh;
            uint32_t ah[4][4], bh[2][4];
            #pragma unroll
            for (int mi = 0; mi < 4; mi++)
                ldsm4(ah[mi], base + ((wr * 64 + mi * 16 + jrow) << 7) + ((ks ^ perm) << 4));
            #pragma unroll
            for (int p2 = 0; p2 < 2; p2++)
                ldsm4(bh[p2], base + 16384 + ((wc * 32 + p2 * 16 + jrow) << 7) + ((ks ^ perm) << 4));
            #pragma unroll
            for (int mi = 0; mi < 4; mi++)
                #pragma unroll
                for (int ni = 0; ni < 4; ni++)
                    mmaf16(acc[mi][ni], ah[mi], bh[ni >> 1][ni & 1], bh[ni >> 1][2 + (ni & 1)]);
            if (TERMS == 2) {
                uint32_t bl[2][4];
                #pragma unroll
                for (int p2 = 0; p2 < 2; p2++)
                    ldsm4(bl[p2], base + 32768 + ((wc * 32 + p2 * 16 + jrow) << 7) + ((ks ^ perm) << 4));
                #pragma unroll
                for (int mi = 0; mi < 4; mi++)
                    #pragma unroll
                    for (int ni = 0; ni < 4; ni++)
                        mmaf16(acc[mi][ni], ah[mi], bl[ni >> 1][ni & 1], bl[ni >> 1][2 + (ni & 1)]);
            }
        }
        __syncthreads();
    }

    const float cg = 0.7978845608028654f;
    #pragma unroll
    for (int mi = 0; mi < 4; mi++) {
        int rbase = row0 + wr * 64 + mi * 16 + q;
        #pragma unroll
        for (int ni = 0; ni < 4; ni++) {
            int cbase = col0 + wc * 32 + ni * 8 + 2 * r4;
            #pragma unroll
            for (int rg = 0; rg < 2; rg++) {
                int rr = rbase + rg * 8;
                float v0 = acc[mi][ni][rg * 2 + 0] * 0.00390625f;
                float v1 = acc[mi][ni][rg * 2 + 1] * 0.00390625f;
                if (HASBIAS) { v0 += bias[cbase]; v1 += bias[cbase + 1]; }
                if (EPI == 2) {
                    float u0 = cg * (v0 + 0.044715f * v0 * v0 * v0);
                    v0 = 0.5f * v0 * (1.0f + tanhf(u0));
                    float u1 = cg * (v1 + 0.044715f * v1 * v1 * v1);
                    v1 = 0.5f * v1 * (1.0f + tanhf(u1));
                    PF[(size_t)rr * (N >> 1) + (cbase >> 1)] = pkh(v0, v1);
                } else if (EPI == 3) {
                    size_t idx = ((size_t)blockIdx.z * NT + rr) * N + cbase;
                    C[idx] = v0;
                    C[idx + 1] = v1;
                } else {
                    size_t idx = (size_t)rr * N + cbase;
                    if (cbase < N) C[idx] = v0;
                    if (cbase + 1 < N) C[idx + 1] = v1;
                }
            }
        }
    }
}

#define GSM1 98304   // 3 x 32K
#define GSM2 98304   // 2 x 48K

// ---------------- host ----------------
extern "C" void kernel_launch(void* const* d_in, const int* in_sizes, int n_in,
                              void* d_out, int out_size) {
    const int*   tok    = (const int*)  d_in[0];
    const float* wte    = (const float*)d_in[1];
    const float* wpe    = (const float*)d_in[2];
    const float* ln1_w  = (const float*)d_in[3];
    const float* ln1_b  = (const float*)d_in[4];
    const float* attn_w = (const float*)d_in[5];
    const float* attn_b = (const float*)d_in[6];
    const float* proj_w = (const float*)d_in[7];
    const float* proj_b = (const float*)d_in[8];
    const float* ln2_w  = (const float*)d_in[9];
    const float* ln2_b  = (const float*)d_in[10];
    const float* fc_w   = (const float*)d_in[11];
    const float* fc_b   = (const float*)d_in[12];
    const float* fc2_w  = (const float*)d_in[13];
    const float* fc2_b  = (const float*)d_in[14];
    const float* lnf_w  = (const float*)d_in[15];
    const float* lnf_b  = (const float*)d_in[16];
    const float* head_w = (const float*)d_in[17];
    float* out = (float*)d_out;

    float *x, *qkv;
    uint32_t *hF, *atF, *ffF;
    cudaGetSymbolAddress((void**)&x, g_x);
    cudaGetSymbolAddress((void**)&qkv, g_qkv);
    cudaGetSymbolAddress((void**)&hF, g_hF);
    cudaGetSymbolAddress((void**)&atF, g_atF);
    cudaGetSymbolAddress((void**)&ffF, g_ffF);
    uint32_t *wq_h, *wq_l, *wp_h, *wp_l, *wf_h, *wf_l, *w2_h, *w2_l, *wh_h, *wh_l;
    cudaGetSymbolAddress((void**)&wq_h, g_wq_h);
    cudaGetSymbolAddress((void**)&wq_l, g_wq_l);
    cudaGetSymbolAddress((void**)&wp_h, g_wp_h);
    cudaGetSymbolAddress((void**)&wp_l, g_wp_l);
    cudaGetSymbolAddress((void**)&wf_h, g_wf_h);
    cudaGetSymbolAddress((void**)&wf_l, g_wf_l);
    cudaGetSymbolAddress((void**)&w2_h, g_w2_h);
    cudaGetSymbolAddress((void**)&w2_l, g_w2_l);
    cudaGetSymbolAddress((void**)&wh_h, g_wh_h);
    cudaGetSymbolAddress((void**)&wh_l, g_wh_l);

    cudaFuncSetAttribute(gemm_lm<0, true,  1>, cudaFuncAttributeMaxDynamicSharedMemorySize, GSM1);
    cudaFuncSetAttribute(gemm_lm<2, true,  1>, cudaFuncAttributeMaxDynamicSharedMemorySize, GSM1);
    cudaFuncSetAttribute(gemm_lm<3, false, 1>, cudaFuncAttributeMaxDynamicSharedMemorySize, GSM1);
    cudaFuncSetAttribute(gemm_lm<0, false, 2>, cudaFuncAttributeMaxDynamicSharedMemorySize, GSM2);
    cudaFuncSetAttribute(attn_kernel, cudaFuncAttributeMaxDynamicSharedMemorySize, 65536);

    pack_w_t<<<dim3(12, 72, LL), 256>>>(attn_w, wq_h, wq_l, DD, D3);
    pack_w_t<<<dim3(12, 24, LL), 256>>>(proj_w, wp_h, wp_l, DD, DD);
    pack_w_t<<<dim3(12, 96, LL), 256>>>(fc_w,  wf_h, wf_l, DD, FF);
    pack_w_t<<<dim3(48, 24, LL), 256>>>(fc2_w, w2_h, w2_l, FF, DD);
    pack_headf<<<(VP * K2D + 255) / 256, 256>>>(head_w, wh_h, wh_l);

    embed_ln_pack<<<NT, 256>>>(tok, wte, wpe, x, ln1_w, ln1_b, hF);

    for (int l = 0; l < LL; l++) {
        size_t oq = (size_t)l * D3 * K2D, op = (size_t)l * DD * K2D;
        size_t of = (size_t)l * FF * K2D, o2 = (size_t)l * DD * K2F;

        gemm_lm<0, true, 1><<<dim3(NT / 128, D3 / 128, 1), 256, GSM1>>>(
            hF, wq_h + oq, wq_l + oq, attn_b + l * D3, qkv, nullptr, D3, DD, K2D);
        attn_kernel<<<dim3(TT / 128, HH, 2), 128, 65536>>>(qkv, atF);
        gemm_lm<3, false, 1><<<dim3(NT / 128, DD / 128, 3), 256, GSM1>>>(
            atF, wp_h + op, wp_l + op, nullptr, qkv, nullptr, DD, DD / 3, K2D);
        red_ln_pack<<<NT, 256>>>(qkv, proj_b + l * DD, x, ln2_w + l * DD, ln2_b + l * DD, hF);
        gemm_lm<2, true, 1><<<dim3(NT / 128, FF / 128, 1), 256, GSM1>>>(
            hF, wf_h + of, wf_l + of, fc_b + l * FF, nullptr, ffF, FF, DD, K2D);
        gemm_lm<3, false, 1><<<dim3(NT / 128, DD / 128, 3), 256, GSM1>>>(
            ffF, w2_h + o2, w2_l + o2, nullptr, qkv, nullptr, DD, FF / 3, K2F);
        const float* nw = (l < LL - 1) ? ln1_w + (l + 1) * DD : lnf_w;
        const float* nb = (l < LL - 1) ? ln1_b + (l + 1) * DD : lnf_b;
        red_ln_pack<<<NT, 256>>>(qkv, fc2_b + l * DD, x, nw, nb, hF);
    }

    gemm_lm<0, false, 2><<<dim3(NT / 128, VP / 128, 1), 256, GSM2>>>(
        hF, wh_h, wh_l, nullptr, out, nullptr, VV, DD, K2D);
}

// round 12
// speedup vs baseline: 7.9147x; 1.1238x over previous
#include <cuda_runtime.h>
#include <cuda_bf16.h>
#include <cuda_fp16.h>
#include <math.h>
#include <stdint.h>

#define NT 2048
#define TT 1024
#define DD 768
#define FF 3072
#define HH 12
#define HD 64
#define LL 4
#define VV 50257
#define D3 2304
#define VP 50304
#define K2D 384
#define K2F 1536

// ---------------- scratch ----------------
__device__ float    g_x[NT * DD];
__device__ float    g_qkv[NT * D3];   // also split-K partial buffer [3][NT][DD]
__device__ uint32_t g_hF[NT * K2D];
__device__ uint32_t g_atF[NT * K2D];
__device__ uint32_t g_ffF[NT * K2F];
// weights n-major [N][K/2] fp16-pair words, scaled x256, hi/lo
__device__ uint32_t g_wq_h[LL * D3 * K2D], g_wq_l[LL * D3 * K2D];
__device__ uint32_t g_wp_h[LL * DD * K2D], g_wp_l[LL * DD * K2D];
__device__ uint32_t g_wf_h[LL * FF * K2D], g_wf_l[LL * FF * K2D];
__device__ uint32_t g_w2_h[LL * DD * K2F], g_w2_l[LL * DD * K2F];
__device__ uint32_t g_wh_h[VP * K2D];

// ---------------- helpers ----------------
__device__ __forceinline__ uint32_t pkh(float x, float y) {
    __half hx = __float2half_rn(x), hy = __float2half_rn(y);
    return ((uint32_t)__half_as_ushort(hy) << 16) | (uint32_t)__half_as_ushort(hx);
}
__device__ __forceinline__ void cvt2h(float x, float y, uint32_t& hi, uint32_t& lo) {
    __half hx = __float2half_rn(x), hy = __float2half_rn(y);
    hi = ((uint32_t)__half_as_ushort(hy) << 16) | (uint32_t)__half_as_ushort(hx);
    lo = pkh(x - __half2float(hx), y - __half2float(hy));
}
__device__ __forceinline__ void cpa16(uint32_t d, const void* s) {
    asm volatile("cp.async.cg.shared.global [%0], [%1], 16;" :: "r"(d), "l"(s));
}
__device__ __forceinline__ void ldsm4(uint32_t* r, uint32_t a) {
    asm volatile("ldmatrix.sync.aligned.m8n8.x4.shared.b16 {%0,%1,%2,%3}, [%4];"
                 : "=r"(r[0]), "=r"(r[1]), "=r"(r[2]), "=r"(r[3]) : "r"(a));
}
__device__ __forceinline__ void mmaf16(float* c, const uint32_t* a, uint32_t b0, uint32_t b1) {
    asm volatile("mma.sync.aligned.m16n8k16.row.col.f32.f16.f16.f32 "
                 "{%0,%1,%2,%3}, {%4,%5,%6,%7}, {%8,%9}, {%0,%1,%2,%3};\n"
                 : "+f"(c[0]), "+f"(c[1]), "+f"(c[2]), "+f"(c[3])
                 : "r"(a[0]), "r"(a[1]), "r"(a[2]), "r"(a[3]), "r"(b0), "r"(b1));
}
__device__ __forceinline__ uint64_t f2pk(float x, float y) {
    uint64_t r; asm("mov.b64 %0, {%1,%2};" : "=l"(r) : "f"(x), "f"(y)); return r;
}
__device__ __forceinline__ void f2un(uint64_t v, float& x, float& y) {
    asm("mov.b64 {%0,%1}, %2;" : "=f"(x), "=f"(y) : "l"(v));
}
__device__ __forceinline__ uint64_t fma2(uint64_t a, uint64_t b, uint64_t c) {
    uint64_t d; asm("fma.rn.f32x2 %0, %1, %2, %3;" : "=l"(d) : "l"(a), "l"(b), "l"(c)); return d;
}
__device__ __forceinline__ uint64_t mul2(uint64_t a, uint64_t b) {
    uint64_t d; asm("mul.rn.f32x2 %0, %1, %2;" : "=l"(d) : "l"(a), "l"(b)); return d;
}

// ---------------- packing: W [L][K][N] -> [N][K/2] fp16 hi/lo x256 ------
__global__ void pack_w_t(const float* __restrict__ W, uint32_t* __restrict__ Oh,
                         uint32_t* __restrict__ Ol, int K, int N) {
    __shared__ float s[64][33];
    int K2 = K >> 1;
    const float* Wl = W + (size_t)blockIdx.z * K * N;
    uint32_t* OhL = Oh + (size_t)blockIdx.z * N * K2;
    uint32_t* OlL = Ol + (size_t)blockIdx.z * N * K2;
    int k0 = blockIdx.x * 64, n0 = blockIdx.y * 32;
    int rr = threadIdx.x >> 5, cc = threadIdx.x & 31;
    #pragma unroll
    for (int i = 0; i < 8; i++)
        s[rr + i * 8][cc] = Wl[(size_t)(k0 + rr + i * 8) * N + n0 + cc];
    __syncthreads();
    #pragma unroll
    for (int i = 0; i < 4; i++) {
        int n = rr + i * 8;
        uint32_t h, l;
        cvt2h(s[2 * cc][n] * 256.f, s[2 * cc + 1][n] * 256.f, h, l);
        OhL[(size_t)(n0 + n) * K2 + (k0 >> 1) + cc] = h;
        OlL[(size_t)(n0 + n) * K2 + (k0 >> 1) + cc] = l;
    }
}
__global__ void pack_headf(const float* __restrict__ W, uint32_t* __restrict__ Oh) {
    int id = blockIdx.x * 256 + threadIdx.x;
    if (id >= VP * K2D) return;
    int n = id / K2D, kp = id - n * K2D;
    float x = 0.f, y = 0.f;
    if (n < VV) { const float* p = W + (size_t)n * DD + 2 * kp; x = p[0] * 256.f; y = p[1] * 256.f; }
    Oh[id] = pkh(x, y);
}

// ---------------- LN machinery ----------------
__device__ __forceinline__ float blk_sum(float v, float* red) {
    #pragma unroll
    for (int o = 16; o; o >>= 1) v += __shfl_xor_sync(0xffffffffu, v, o);
    if ((threadIdx.x & 31) == 0) red[threadIdx.x >> 5] = v;
    __syncthreads();
    float s = (threadIdx.x < 8) ? red[threadIdx.x] : 0.0f;
    #pragma unroll
    for (int o = 4; o; o >>= 1) s += __shfl_xor_sync(0xffffffffu, s, o);
    if (threadIdx.x == 0) red[0] = s;
    __syncthreads();
    s = red[0];
    __syncthreads();
    return s;
}

__device__ __forceinline__ void ln_body(float* v, float s, float ss, float* vb,
                                        const float* w, const float* b, int row,
                                        uint32_t* PF) {
    float mu = s * (1.0f / DD);
    float r = rsqrtf(ss * (1.0f / DD) - mu * mu + 1e-5f);
    #pragma unroll
    for (int i = 0; i < 3; i++) {
        int c = threadIdx.x + i * 256;
        vb[c] = (v[i] - mu) * r * w[c] + b[c];
    }
    __syncthreads();
    #pragma unroll
    for (int i = 0; i < 2; i++) {
        int p = threadIdx.x + i * 256;
        if (p < K2D)
            PF[(size_t)row * K2D + p] = pkh(vb[2 * p], vb[2 * p + 1]);
    }
}

__global__ void embed_ln_pack(const int* __restrict__ tok, const float* __restrict__ wte,
                              const float* __restrict__ wpe, float* __restrict__ x,
                              const float* __restrict__ w, const float* __restrict__ b,
                              uint32_t* __restrict__ PF) {
    __shared__ float vb[DD];
    __shared__ float red[32];
    int row = blockIdx.x, t = tok[row];
    const float* we = wte + (size_t)t * DD;
    const float* wp = wpe + (size_t)(row & (TT - 1)) * DD;
    float v[3], s = 0.f, ss = 0.f;
    #pragma unroll
    for (int i = 0; i < 3; i++) {
        int c = threadIdx.x + i * 256;
        v[i] = we[c] + wp[c];
        x[(size_t)row * DD + c] = v[i];
        s += v[i]; ss += v[i] * v[i];
    }
    s = blk_sum(s, red); ss = blk_sum(ss, red);
    ln_body(v, s, ss, vb, w, b, row, PF);
}

__global__ void red_ln_pack(const float* __restrict__ P, const float* __restrict__ bias,
                            float* __restrict__ x, const float* __restrict__ w,
                            const float* __restrict__ b, uint32_t* __restrict__ PF) {
    __shared__ float vb[DD];
    __shared__ float red[32];
    int row = blockIdx.x;
    float v[3], s = 0.f, ss = 0.f;
    #pragma unroll
    for (int i = 0; i < 3; i++) {
        int c = threadIdx.x + i * 256;
        size_t idx = (size_t)row * DD + c;
        float t = x[idx] + bias[c] + P[idx] + P[(size_t)NT * DD + idx] + P[2 * (size_t)NT * DD + idx];
        x[idx] = t;
        v[i] = t; s += t; ss += t * t;
    }
    s = blk_sum(s, red); ss = blk_sum(ss, red);
    ln_body(v, s, ss, vb, w, b, row, PF);
}

// ---------------- attention (float4-staged K/V) ----------------
__global__ void __launch_bounds__(128)
attn_kernel(const float* __restrict__ qkv, uint32_t* __restrict__ attF) {
    extern __shared__ __align__(16) unsigned sm_dyn[];
    float* Ks = (float*)sm_dyn;
    float* Vs = Ks + 4096;
    float* sc = Vs + 4096;
    int tid = threadIdx.x;
    int qt = blockIdx.x, h = blockIdx.y, b = blockIdx.z;
    int qpos = qt * 128 + tid;
    const float* base = qkv + (size_t)b * TT * D3;
    uint64_t q2[32], o2[32];
    {
        const float* qp = base + (size_t)qpos * D3 + h * HD;
        #pragma unroll
        for (int j = 0; j < 32; j++) q2[j] = f2pk(qp[2 * j], qp[2 * j + 1]);
    }
    #pragma unroll
    for (int j = 0; j < 32; j++) o2[j] = 0ull;
    float m = -1e30f, ssum = 0.f;
    int nkt = (qt + 1) * 2;
    for (int kt = 0; kt < nkt; kt++) {
        int k0 = kt * 64;
        __syncthreads();
        #pragma unroll
        for (int i = 0; i < 8; i++) {
            int idx = (i * 128 + tid) * 4;
            int kk = idx >> 6, e = idx & 63;
            const float* rowp = base + (size_t)(k0 + kk) * D3 + h * HD + e;
            *(float4*)(Ks + idx) = *(const float4*)(rowp + DD);
            *(float4*)(Vs + idx) = *(const float4*)(rowp + 2 * DD);
        }
        __syncthreads();
        float tm = -1e30f;
        for (int kk = 0; kk < 64; kk++) {
            const uint64_t* kr = (const uint64_t*)(Ks + (kk << 6));
            uint64_t a0 = 0ull, a1 = 0ull, a2 = 0ull, a3 = 0ull;
            #pragma unroll
            for (int j = 0; j < 32; j += 4) {
                a0 = fma2(q2[j], kr[j], a0);
                a1 = fma2(q2[j + 1], kr[j + 1], a1);
                a2 = fma2(q2[j + 2], kr[j + 2], a2);
                a3 = fma2(q2[j + 3], kr[j + 3], a3);
            }
            float x0, y0, x1, y1, x2, y2, x3, y3;
            f2un(a0, x0, y0); f2un(a1, x1, y1); f2un(a2, x2, y2); f2un(a3, x3, y3);
            float sv = (((x0 + y0) + (x1 + y1)) + ((x2 + y2) + (x3 + y3))) * 0.125f;
            if (k0 + kk > qpos) sv = -1e30f;
            sc[kk * 128 + tid] = sv;
            tm = fmaxf(tm, sv);
        }
        float mn = fmaxf(m, tm);
        float cr = __expf(m - mn);
        m = mn; ssum *= cr;
        uint64_t cr2 = f2pk(cr, cr);
        #pragma unroll
        for (int j = 0; j < 32; j++) o2[j] = mul2(o2[j], cr2);
        for (int kk = 0; kk < 64; kk++) {
            float p = __expf(sc[kk * 128 + tid] - m);
            ssum += p;
            uint64_t p2 = f2pk(p, p);
            const uint64_t* vr = (const uint64_t*)(Vs + (kk << 6));
            #pragma unroll
            for (int j = 0; j < 32; j++) o2[j] = fma2(p2, vr[j], o2[j]);
        }
    }
    float inv = 1.0f / ssum;
    size_t row = (size_t)b * TT + qpos;
    #pragma unroll
    for (int t2 = 0; t2 < 32; t2++) {
        float ox, oy; f2un(o2[t2], ox, oy);
        attF[row * K2D + h * 32 + t2] = pkh(ox * inv, oy * inv);
    }
}

// ---------------- fp16 MMA GEMM (ldmatrix), 128x128, BK=64 --------------
// A fp16 pairs [M][K/2]; B fp16 n-major [N][K/2] (x256), TERMS=1 hi only
// (3-stage pipeline), TERMS=2 hi+lo (2-stage). EPI: 0 store fp32 (+bias),
// 2 bias+GELU->fp16, 3 split-K. smem/buffer: A 16K @0, Bh 16K @16K,
// (Bl 16K @32K). Row=128B, 8 granules, swizzle g ^ (row&7).
template<int EPI, bool HASBIAS, int TERMS>
__global__ void __launch_bounds__(256, 2)
gemm_lm(const uint32_t* __restrict__ AF, const uint32_t* __restrict__ BhG,
        const uint32_t* __restrict__ BlG, const float* __restrict__ bias,
        float* __restrict__ C, uint32_t* __restrict__ PF,
        int N, int Kslice, int K2s) {
    constexpr int BUFSZ  = (TERMS == 2) ? 49152 : 32768;
    constexpr int STAGES = (TERMS == 2) ? 2 : 3;
    extern __shared__ __align__(16) char smem[];
    uint32_t sbase = (uint32_t)__cvta_generic_to_shared(smem);
    int tid = threadIdx.x;
    int w = tid >> 5, lane = tid & 31;
    int wr = w >> 2, wc = w & 3;
    int q = lane >> 2, r4 = lane & 3;
    int jrow = ((lane >> 3) & 1) * 8 + (lane & 7);
    int gh = lane >> 4;
    int perm = jrow & 7;
    int row0 = blockIdx.x * 128, col0 = blockIdx.y * 128;
    int kofs = blockIdx.z * (Kslice >> 1);

    float acc[4][4][4];
    #pragma unroll
    for (int mi = 0; mi < 4; mi++)
        #pragma unroll
        for (int ni = 0; ni < 4; ni++)
            #pragma unroll
            for (int e = 0; e < 4; e++) acc[mi][ni][e] = 0.f;

    auto loadbuf = [&](int t, int buf) {
        uint32_t base = sbase + buf * BUFSZ;
        int kp0 = kofs + t * 32;
        #pragma unroll
        for (int i = 0; i < 4; i++) {
            int id = tid + i * 256;
            int mm = id >> 3, g = id & 7;
            uint32_t dst = base + (mm << 7) + ((g ^ (mm & 7)) << 4);
            cpa16(dst, AF + (size_t)(row0 + mm) * K2s + kp0 + g * 4);
        }
        #pragma unroll
        for (int i = 0; i < 4; i++) {
            int id = tid + i * 256;
            int nn = id >> 3, g = id & 7;
            uint32_t dst = base + 16384 + (nn << 7) + ((g ^ (nn & 7)) << 4);
            size_t off = (size_t)(col0 + nn) * K2s + kp0 + g * 4;
            cpa16(dst, BhG + off);
            if (TERMS == 2) cpa16(dst + 16384, BlG + off);
        }
    };

    int ntile = Kslice >> 6;
    #pragma unroll
    for (int pt = 0; pt < STAGES - 1; pt++) {
        if (pt < ntile) {
            loadbuf(pt, pt % STAGES);
            asm volatile("cp.async.commit_group;" ::: "memory");
        }
    }
    for (int t = 0; t < ntile; t++) {
        int buf = t % STAGES;
        if (t + STAGES - 1 < ntile) {
            loadbuf(t + STAGES - 1, (t + STAGES - 1) % STAGES);
            asm volatile("cp.async.commit_group;" ::: "memory");
        }
        int p = ntile - t;
        if (STAGES == 3) {
            if (p > 2)      asm volatile("cp.async.wait_group 2;" ::: "memory");
            else if (p > 1) asm volatile("cp.async.wait_group 1;" ::: "memory");
            else            asm volatile("cp.async.wait_group 0;" ::: "memory");
        } else {
            if (p > 1)      asm volatile("cp.async.wait_group 1;" ::: "memory");
            else            asm volatile("cp.async.wait_group 0;" ::: "memory");
        }
        __syncthreads();
        uint32_t base = sbase + buf * BUFSZ;
        #pragma unroll
        for (int s = 0; s < 4; s++) {
            int ks = 2 * s + gh;
            uint32_t ah[4][4], bh[2][4];
            #pragma unroll
            for (int mi = 0; mi < 4; mi++)
                ldsm4(ah[mi], base + ((wr * 64 + mi * 16 + jrow) << 7) + ((ks ^ perm) << 4));
            #pragma unroll
            for (int p2 = 0; p2 < 2; p2++)
                ldsm4(bh[p2], base + 16384 + ((wc * 32 + p2 * 16 + jrow) << 7) + ((ks ^ perm) << 4));
            #pragma unroll
            for (int mi = 0; mi < 4; mi++)
                #pragma unroll
                for (int ni = 0; ni < 4; ni++)
                    mmaf16(acc[mi][ni], ah[mi], bh[ni >> 1][ni & 1], bh[ni >> 1][2 + (ni & 1)]);
            if (TERMS == 2) {
                uint32_t bl[2][4];
                #pragma unroll
                for (int p2 = 0; p2 < 2; p2++)
                    ldsm4(bl[p2], base + 32768 + ((wc * 32 + p2 * 16 + jrow) << 7) + ((ks ^ perm) << 4));
                #pragma unroll
                for (int mi = 0; mi < 4; mi++)
                    #pragma unroll
                    for (int ni = 0; ni < 4; ni++)
                        mmaf16(acc[mi][ni], ah[mi], bl[ni >> 1][ni & 1], bl[ni >> 1][2 + (ni & 1)]);
            }
        }
        __syncthreads();
    }

    const float cg = 0.7978845608028654f;
    #pragma unroll
    for (int mi = 0; mi < 4; mi++) {
        int rbase = row0 + wr * 64 + mi * 16 + q;
        #pragma unroll
        for (int ni = 0; ni < 4; ni++) {
            int cbase = col0 + wc * 32 + ni * 8 + 2 * r4;
            #pragma unroll
            for (int rg = 0; rg < 2; rg++) {
                int rr = rbase + rg * 8;
                float v0 = acc[mi][ni][rg * 2 + 0] * 0.00390625f;
                float v1 = acc[mi][ni][rg * 2 + 1] * 0.00390625f;
                if (HASBIAS) { v0 += bias[cbase]; v1 += bias[cbase + 1]; }
                if (EPI == 2) {
                    float u0 = cg * (v0 + 0.044715f * v0 * v0 * v0);
                    v0 = 0.5f * v0 * (1.0f + tanhf(u0));
                    float u1 = cg * (v1 + 0.044715f * v1 * v1 * v1);
                    v1 = 0.5f * v1 * (1.0f + tanhf(u1));
                    PF[(size_t)rr * (N >> 1) + (cbase >> 1)] = pkh(v0, v1);
                } else if (EPI == 3) {
                    size_t idx = ((size_t)blockIdx.z * NT + rr) * N + cbase;
                    C[idx] = v0;
                    C[idx + 1] = v1;
                } else {
                    size_t idx = (size_t)rr * N + cbase;
                    if (cbase < N) C[idx] = v0;
                    if (cbase + 1 < N) C[idx + 1] = v1;
                }
            }
        }
    }
}

#define GSM1 98304   // 3 x 32K

// ---------------- host ----------------
extern "C" void kernel_launch(void* const* d_in, const int* in_sizes, int n_in,
                              void* d_out, int out_size) {
    const int*   tok    = (const int*)  d_in[0];
    const float* wte    = (const float*)d_in[1];
    const float* wpe    = (const float*)d_in[2];
    const float* ln1_w  = (const float*)d_in[3];
    const float* ln1_b  = (const float*)d_in[4];
    const float* attn_w = (const float*)d_in[5];
    const float* attn_b = (const float*)d_in[6];
    const float* proj_w = (const float*)d_in[7];
    const float* proj_b = (const float*)d_in[8];
    const float* ln2_w  = (const float*)d_in[9];
    const float* ln2_b  = (const float*)d_in[10];
    const float* fc_w   = (const float*)d_in[11];
    const float* fc_b   = (const float*)d_in[12];
    const float* fc2_w  = (const float*)d_in[13];
    const float* fc2_b  = (const float*)d_in[14];
    const float* lnf_w  = (const float*)d_in[15];
    const float* lnf_b  = (const float*)d_in[16];
    const float* head_w = (const float*)d_in[17];
    float* out = (float*)d_out;

    float *x, *qkv;
    uint32_t *hF, *atF, *ffF;
    cudaGetSymbolAddress((void**)&x, g_x);
    cudaGetSymbolAddress((void**)&qkv, g_qkv);
    cudaGetSymbolAddress((void**)&hF, g_hF);
    cudaGetSymbolAddress((void**)&atF, g_atF);
    cudaGetSymbolAddress((void**)&ffF, g_ffF);
    uint32_t *wq_h, *wq_l, *wp_h, *wp_l, *wf_h, *wf_l, *w2_h, *w2_l, *wh_h;
    cudaGetSymbolAddress((void**)&wq_h, g_wq_h);
    cudaGetSymbolAddress((void**)&wq_l, g_wq_l);
    cudaGetSymbolAddress((void**)&wp_h, g_wp_h);
    cudaGetSymbolAddress((void**)&wp_l, g_wp_l);
    cudaGetSymbolAddress((void**)&wf_h, g_wf_h);
    cudaGetSymbolAddress((void**)&wf_l, g_wf_l);
    cudaGetSymbolAddress((void**)&w2_h, g_w2_h);
    cudaGetSymbolAddress((void**)&w2_l, g_w2_l);
    cudaGetSymbolAddress((void**)&wh_h, g_wh_h);

    cudaFuncSetAttribute(gemm_lm<0, true,  1>, cudaFuncAttributeMaxDynamicSharedMemorySize, GSM1);
    cudaFuncSetAttribute(gemm_lm<2, true,  1>, cudaFuncAttributeMaxDynamicSharedMemorySize, GSM1);
    cudaFuncSetAttribute(gemm_lm<3, false, 1>, cudaFuncAttributeMaxDynamicSharedMemorySize, GSM1);
    cudaFuncSetAttribute(gemm_lm<0, false, 1>, cudaFuncAttributeMaxDynamicSharedMemorySize, GSM1);
    cudaFuncSetAttribute(attn_kernel, cudaFuncAttributeMaxDynamicSharedMemorySize, 65536);

    pack_w_t<<<dim3(12, 72, LL), 256>>>(attn_w, wq_h, wq_l, DD, D3);
    pack_w_t<<<dim3(12, 24, LL), 256>>>(proj_w, wp_h, wp_l, DD, DD);
    pack_w_t<<<dim3(12, 96, LL), 256>>>(fc_w,  wf_h, wf_l, DD, FF);
    pack_w_t<<<dim3(48, 24, LL), 256>>>(fc2_w, w2_h, w2_l, FF, DD);
    pack_headf<<<(VP * K2D + 255) / 256, 256>>>(head_w, wh_h);

    embed_ln_pack<<<NT, 256>>>(tok, wte, wpe, x, ln1_w, ln1_b, hF);

    for (int l = 0; l < LL; l++) {
        size_t oq = (size_t)l * D3 * K2D, op = (size_t)l * DD * K2D;
        size_t of = (size_t)l * FF * K2D, o2 = (size_t)l * DD * K2F;

        gemm_lm<0, true, 1><<<dim3(NT / 128, D3 / 128, 1), 256, GSM1>>>(
            hF, wq_h + oq, wq_l + oq, attn_b + l * D3, qkv, nullptr, D3, DD, K2D);
        attn_kernel<<<dim3(TT / 128, HH, 2), 128, 65536>>>(qkv, atF);
        gemm_lm<3, false, 1><<<dim3(NT / 128, DD / 128, 3), 256, GSM1>>>(
            atF, wp_h + op, wp_l + op, nullptr, qkv, nullptr, DD, DD / 3, K2D);
        red_ln_pack<<<NT, 256>>>(qkv, proj_b + l * DD, x, ln2_w + l * DD, ln2_b + l * DD, hF);
        gemm_lm<2, true, 1><<<dim3(NT / 128, FF / 128, 1), 256, GSM1>>>(
            hF, wf_h + of, wf_l + of, fc_b + l * FF, nullptr, ffF, FF, DD, K2D);
        gemm_lm<3, false, 1><<<dim3(NT / 128, DD / 128, 3), 256, GSM1>>>(
            ffF, w2_h + o2, w2_l + o2, nullptr, qkv, nullptr, DD, FF / 3, K2F);
        const float* nw = (l < LL - 1) ? ln1_w + (l + 1) * DD : lnf_w;
        const float* nb = (l < LL - 1) ? ln1_b + (l + 1) * DD : lnf_b;
        red_ln_pack<<<NT, 256>>>(qkv, fc2_b + l * DD, x, nw, nb, hF);
    }

    gemm_lm<0, false, 1><<<dim3(NT / 128, VP / 128, 1), 256, GSM1>>>(
        hF, wh_h, nullptr, nullptr, out, nullptr, VV, DD, K2D);
}

// round 13
// speedup vs baseline: 9.4792x; 1.1977x over previous
#include <cuda_runtime.h>
#include <cuda_bf16.h>
#include <cuda_fp16.h>
#include <math.h>
#include <stdint.h>

#define NT 2048
#define TT 1024
#define DD 768
#define FF 3072
#define HH 12
#define HD 64
#define LL 4
#define VV 50257
#define D3 2304
#define VP 50304
#define K2D 384
#define K2F 1536

// ---------------- scratch ----------------
__device__ float    g_x[NT * DD];
__device__ float    g_qkv[NT * D3];   // also split-K partial buffer [3][NT][DD]
__device__ uint32_t g_hF[NT * K2D];
__device__ uint32_t g_atF[NT * K2D];
__device__ uint32_t g_ffF[NT * K2F];  // GELU out; aliased as attention o-partials
__device__ float2   g_attms[4 * TT * HH];   // (m, ssum) per split/b/q/h
// weights n-major [N][K/2] fp16-pair words, scaled x256, hi/lo
__device__ uint32_t g_wq_h[LL * D3 * K2D], g_wq_l[LL * D3 * K2D];
__device__ uint32_t g_wp_h[LL * DD * K2D], g_wp_l[LL * DD * K2D];
__device__ uint32_t g_wf_h[LL * FF * K2D], g_wf_l[LL * FF * K2D];
__device__ uint32_t g_w2_h[LL * DD * K2F], g_w2_l[LL * DD * K2F];
__device__ uint32_t g_wh_h[VP * K2D];

// ---------------- helpers ----------------
__device__ __forceinline__ uint32_t pkh(float x, float y) {
    __half hx = __float2half_rn(x), hy = __float2half_rn(y);
    return ((uint32_t)__half_as_ushort(hy) << 16) | (uint32_t)__half_as_ushort(hx);
}
__device__ __forceinline__ void cvt2h(float x, float y, uint32_t& hi, uint32_t& lo) {
    __half hx = __float2half_rn(x), hy = __float2half_rn(y);
    hi = ((uint32_t)__half_as_ushort(hy) << 16) | (uint32_t)__half_as_ushort(hx);
    lo = pkh(x - __half2float(hx), y - __half2float(hy));
}
__device__ __forceinline__ void cpa16(uint32_t d, const void* s) {
    asm volatile("cp.async.cg.shared.global [%0], [%1], 16;" :: "r"(d), "l"(s));
}
__device__ __forceinline__ void ldsm4(uint32_t* r, uint32_t a) {
    asm volatile("ldmatrix.sync.aligned.m8n8.x4.shared.b16 {%0,%1,%2,%3}, [%4];"
                 : "=r"(r[0]), "=r"(r[1]), "=r"(r[2]), "=r"(r[3]) : "r"(a));
}
__device__ __forceinline__ void mmaf16(float* c, const uint32_t* a, uint32_t b0, uint32_t b1) {
    asm volatile("mma.sync.aligned.m16n8k16.row.col.f32.f16.f16.f32 "
                 "{%0,%1,%2,%3}, {%4,%5,%6,%7}, {%8,%9}, {%0,%1,%2,%3};\n"
                 : "+f"(c[0]), "+f"(c[1]), "+f"(c[2]), "+f"(c[3])
                 : "r"(a[0]), "r"(a[1]), "r"(a[2]), "r"(a[3]), "r"(b0), "r"(b1));
}
__device__ __forceinline__ uint64_t f2pk(float x, float y) {
    uint64_t r; asm("mov.b64 %0, {%1,%2};" : "=l"(r) : "f"(x), "f"(y)); return r;
}
__device__ __forceinline__ void f2un(uint64_t v, float& x, float& y) {
    asm("mov.b64 {%0,%1}, %2;" : "=f"(x), "=f"(y) : "l"(v));
}
__device__ __forceinline__ uint64_t fma2(uint64_t a, uint64_t b, uint64_t c) {
    uint64_t d; asm("fma.rn.f32x2 %0, %1, %2, %3;" : "=l"(d) : "l"(a), "l"(b), "l"(c)); return d;
}
__device__ __forceinline__ uint64_t mul2(uint64_t a, uint64_t b) {
    uint64_t d; asm("mul.rn.f32x2 %0, %1, %2;" : "=l"(d) : "l"(a), "l"(b)); return d;
}

// ---------------- packing ----------------
__global__ void pack_w_t(const float* __restrict__ W, uint32_t* __restrict__ Oh,
                         uint32_t* __restrict__ Ol, int K, int N) {
    __shared__ float s[64][33];
    int K2 = K >> 1;
    const float* Wl = W + (size_t)blockIdx.z * K * N;
    uint32_t* OhL = Oh + (size_t)blockIdx.z * N * K2;
    uint32_t* OlL = Ol + (size_t)blockIdx.z * N * K2;
    int k0 = blockIdx.x * 64, n0 = blockIdx.y * 32;
    int rr = threadIdx.x >> 5, cc = threadIdx.x & 31;
    #pragma unroll
    for (int i = 0; i < 8; i++)
        s[rr + i * 8][cc] = Wl[(size_t)(k0 + rr + i * 8) * N + n0 + cc];
    __syncthreads();
    #pragma unroll
    for (int i = 0; i < 4; i++) {
        int n = rr + i * 8;
        uint32_t h, l;
        cvt2h(s[2 * cc][n] * 256.f, s[2 * cc + 1][n] * 256.f, h, l);
        OhL[(size_t)(n0 + n) * K2 + (k0 >> 1) + cc] = h;
        OlL[(size_t)(n0 + n) * K2 + (k0 >> 1) + cc] = l;
    }
}
__global__ void pack_headf(const float* __restrict__ W, uint32_t* __restrict__ Oh) {
    int id = blockIdx.x * 256 + threadIdx.x;
    if (id >= VP * K2D) return;
    int n = id / K2D, kp = id - n * K2D;
    float x = 0.f, y = 0.f;
    if (n < VV) { const float* p = W + (size_t)n * DD + 2 * kp; x = p[0] * 256.f; y = p[1] * 256.f; }
    Oh[id] = pkh(x, y);
}

// ---------------- LN machinery ----------------
__device__ __forceinline__ float blk_sum(float v, float* red) {
    #pragma unroll
    for (int o = 16; o; o >>= 1) v += __shfl_xor_sync(0xffffffffu, v, o);
    if ((threadIdx.x & 31) == 0) red[threadIdx.x >> 5] = v;
    __syncthreads();
    float s = (threadIdx.x < 8) ? red[threadIdx.x] : 0.0f;
    #pragma unroll
    for (int o = 4; o; o >>= 1) s += __shfl_xor_sync(0xffffffffu, s, o);
    if (threadIdx.x == 0) red[0] = s;
    __syncthreads();
    s = red[0];
    __syncthreads();
    return s;
}

__device__ __forceinline__ void ln_body(float* v, float s, float ss, float* vb,
                                        const float* w, const float* b, int row,
                                        uint32_t* PF) {
    float mu = s * (1.0f / DD);
    float r = rsqrtf(ss * (1.0f / DD) - mu * mu + 1e-5f);
    #pragma unroll
    for (int i = 0; i < 3; i++) {
        int c = threadIdx.x + i * 256;
        vb[c] = (v[i] - mu) * r * w[c] + b[c];
    }
    __syncthreads();
    #pragma unroll
    for (int i = 0; i < 2; i++) {
        int p = threadIdx.x + i * 256;
        if (p < K2D)
            PF[(size_t)row * K2D + p] = pkh(vb[2 * p], vb[2 * p + 1]);
    }
}

__global__ void embed_ln_pack(const int* __restrict__ tok, const float* __restrict__ wte,
                              const float* __restrict__ wpe, float* __restrict__ x,
                              const float* __restrict__ w, const float* __restrict__ b,
                              uint32_t* __restrict__ PF) {
    __shared__ float vb[DD];
    __shared__ float red[32];
    int row = blockIdx.x, t = tok[row];
    const float* we = wte + (size_t)t * DD;
    const float* wp = wpe + (size_t)(row & (TT - 1)) * DD;
    float v[3], s = 0.f, ss = 0.f;
    #pragma unroll
    for (int i = 0; i < 3; i++) {
        int c = threadIdx.x + i * 256;
        v[i] = we[c] + wp[c];
        x[(size_t)row * DD + c] = v[i];
        s += v[i]; ss += v[i] * v[i];
    }
    s = blk_sum(s, red); ss = blk_sum(ss, red);
    ln_body(v, s, ss, vb, w, b, row, PF);
}

__global__ void red_ln_pack(const float* __restrict__ P, const float* __restrict__ bias,
                            float* __restrict__ x, const float* __restrict__ w,
                            const float* __restrict__ b, uint32_t* __restrict__ PF) {
    __shared__ float vb[DD];
    __shared__ float red[32];
    int row = blockIdx.x;
    float v[3], s = 0.f, ss = 0.f;
    #pragma unroll
    for (int i = 0; i < 3; i++) {
        int c = threadIdx.x + i * 256;
        size_t idx = (size_t)row * DD + c;
        float t = x[idx] + bias[c] + P[idx] + P[(size_t)NT * DD + idx] + P[2 * (size_t)NT * DD + idx];
        x[idx] = t;
        v[i] = t; s += t; ss += t * t;
    }
    s = blk_sum(s, red); ss = blk_sum(ss, red);
    ln_body(v, s, ss, vb, w, b, row, PF);
}

// ---------------- attention: split-KV (2-way), partials ----------------
// grid (TT/128, HH*2, 2): blockIdx.y = h*2 + split. Each split takes
// alternating 64-key tiles, keeps own online softmax, stores unnormalized
// o + (m, ssum). Merge kernel combines.
__global__ void __launch_bounds__(128)
attn_split(const float* __restrict__ qkv, float* __restrict__ oP,
           float2* __restrict__ msP) {
    extern __shared__ __align__(16) unsigned sm_dyn[];
    float* Ks = (float*)sm_dyn;
    float* Vs = Ks + 4096;
    float* sc = Vs + 4096;
    int tid = threadIdx.x;
    int qt = blockIdx.x;
    int h = blockIdx.y >> 1, split = blockIdx.y & 1;
    int b = blockIdx.z;
    int qpos = qt * 128 + tid;
    const float* base = qkv + (size_t)b * TT * D3;
    uint64_t q2[32], o2[32];
    {
        const float* qp = base + (size_t)qpos * D3 + h * HD;
        #pragma unroll
        for (int j = 0; j < 32; j++) q2[j] = f2pk(qp[2 * j], qp[2 * j + 1]);
    }
    #pragma unroll
    for (int j = 0; j < 32; j++) o2[j] = 0ull;
    float m = -1e30f, ssum = 0.f;
    int nkt = (qt + 1) * 2;
    for (int kt = split; kt < nkt; kt += 2) {
        int k0 = kt * 64;
        __syncthreads();
        #pragma unroll
        for (int i = 0; i < 8; i++) {
            int idx = (i * 128 + tid) * 4;
            int kk = idx >> 6, e = idx & 63;
            const float* rowp = base + (size_t)(k0 + kk) * D3 + h * HD + e;
            *(float4*)(Ks + idx) = *(const float4*)(rowp + DD);
            *(float4*)(Vs + idx) = *(const float4*)(rowp + 2 * DD);
        }
        __syncthreads();
        float tm = -1e30f;
        for (int kk = 0; kk < 64; kk++) {
            const uint64_t* kr = (const uint64_t*)(Ks + (kk << 6));
            uint64_t a0 = 0ull, a1 = 0ull, a2 = 0ull, a3 = 0ull;
            #pragma unroll
            for (int j = 0; j < 32; j += 4) {
                a0 = fma2(q2[j], kr[j], a0);
                a1 = fma2(q2[j + 1], kr[j + 1], a1);
                a2 = fma2(q2[j + 2], kr[j + 2], a2);
                a3 = fma2(q2[j + 3], kr[j + 3], a3);
            }
            float x0, y0, x1, y1, x2, y2, x3, y3;
            f2un(a0, x0, y0); f2un(a1, x1, y1); f2un(a2, x2, y2); f2un(a3, x3, y3);
            float sv = (((x0 + y0) + (x1 + y1)) + ((x2 + y2) + (x3 + y3))) * 0.125f;
            if (k0 + kk > qpos) sv = -1e30f;
            sc[kk * 128 + tid] = sv;
            tm = fmaxf(tm, sv);
        }
        float mn = fmaxf(m, tm);
        if (mn < -1e29f) continue;   // tile fully masked & no prior keys
        float cr = __expf(m - mn);
        m = mn; ssum *= cr;
        uint64_t cr2 = f2pk(cr, cr);
        #pragma unroll
        for (int j = 0; j < 32; j++) o2[j] = mul2(o2[j], cr2);
        for (int kk = 0; kk < 64; kk++) {
            float p = __expf(sc[kk * 128 + tid] - m);
            ssum += p;
            uint64_t p2 = f2pk(p, p);
            const uint64_t* vr = (const uint64_t*)(Vs + (kk << 6));
            #pragma unroll
            for (int j = 0; j < 32; j++) o2[j] = fma2(p2, vr[j], o2[j]);
        }
    }
    size_t u = (((size_t)(split * 2 + b) * TT + qpos) * HH + h);
    float* op = oP + u * 64;
    #pragma unroll
    for (int j = 0; j < 16; j++) {
        float4 v;
        f2un(o2[2 * j], v.x, v.y);
        f2un(o2[2 * j + 1], v.z, v.w);
        *(float4*)(op + 4 * j) = v;
    }
    msP[u] = make_float2(m, ssum);
}

// merge two softmax partials -> packed fp16 attn out
__global__ void attn_merge(const float* __restrict__ oP, const float2* __restrict__ msP,
                           uint32_t* __restrict__ attF) {
    int gid = blockIdx.x * 8 + (threadIdx.x >> 5);
    int lane = threadIdx.x & 31;
    int row = gid / HH, h = gid - row * HH;
    int b = row >> 10, q = row & 1023;
    size_t u0 = (((size_t)b * TT + q) * HH + h);
    size_t u1 = (((size_t)(2 + b) * TT + q) * HH + h);
    float2 ms0 = msP[u0], ms1 = msP[u1];
    float m0 = (ms0.y > 0.f) ? ms0.x : -1e30f;
    float m1 = (ms1.y > 0.f) ? ms1.x : -1e30f;
    float M = fmaxf(m0, m1);
    float w0 = (ms0.y > 0.f) ? __expf(ms0.x - M) : 0.f;
    float w1 = (ms1.y > 0.f) ? __expf(ms1.x - M) : 0.f;
    float inv = 1.0f / (ms0.y * w0 + ms1.y * w1);
    float2 a = ((const float2*)(oP + u0 * 64))[lane];
    float2 c = ((const float2*)(oP + u1 * 64))[lane];
    float v0 = (a.x * w0 + c.x * w1) * inv;
    float v1 = (a.y * w0 + c.y * w1) * inv;
    attF[(size_t)row * K2D + h * 32 + lane] = pkh(v0, v1);
}

// ---------------- fp16 MMA GEMM (ldmatrix), 128x128, BK=64 --------------
template<int EPI, bool HASBIAS, int TERMS>
__global__ void __launch_bounds__(256, 2)
gemm_lm(const uint32_t* __restrict__ AF, const uint32_t* __restrict__ BhG,
        const uint32_t* __restrict__ BlG, const float* __restrict__ bias,
        float* __restrict__ C, uint32_t* __restrict__ PF,
        int N, int Kslice, int K2s) {
    constexpr int BUFSZ  = (TERMS == 2) ? 49152 : 32768;
    constexpr int STAGES = (TERMS == 2) ? 2 : 3;
    extern __shared__ __align__(16) char smem[];
    uint32_t sbase = (uint32_t)__cvta_generic_to_shared(smem);
    int tid = threadIdx.x;
    int w = tid >> 5, lane = tid & 31;
    int wr = w >> 2, wc = w & 3;
    int q = lane >> 2, r4 = lane & 3;
    int jrow = ((lane >> 3) & 1) * 8 + (lane & 7);
    int gh = lane >> 4;
    int perm = jrow & 7;
    int row0 = blockIdx.x * 128, col0 = blockIdx.y * 128;
    int kofs = blockIdx.z * (Kslice >> 1);

    float acc[4][4][4];
    #pragma unroll
    for (int mi = 0; mi < 4; mi++)
        #pragma unroll
        for (int ni = 0; ni < 4; ni++)
            #pragma unroll
            for (int e = 0; e < 4; e++) acc[mi][ni][e] = 0.f;

    auto loadbuf = [&](int t, int buf) {
        uint32_t base = sbase + buf * BUFSZ;
        int kp0 = kofs + t * 32;
        #pragma unroll
        for (int i = 0; i < 4; i++) {
            int id = tid + i * 256;
            int mm = id >> 3, g = id & 7;
            uint32_t dst = base + (mm << 7) + ((g ^ (mm & 7)) << 4);
            cpa16(dst, AF + (size_t)(row0 + mm) * K2s + kp0 + g * 4);
        }
        #pragma unroll
        for (int i = 0; i < 4; i++) {
            int id = tid + i * 256;
            int nn = id >> 3, g = id & 7;
            uint32_t dst = base + 16384 + (nn << 7) + ((g ^ (nn & 7)) << 4);
            size_t off = (size_t)(col0 + nn) * K2s + kp0 + g * 4;
            cpa16(dst, BhG + off);
            if (TERMS == 2) cpa16(dst + 16384, BlG + off);
        }
    };

    int ntile = Kslice >> 6;
    #pragma unroll
    for (int pt = 0; pt < STAGES - 1; pt++) {
        if (pt < ntile) {
            loadbuf(pt, pt % STAGES);
            asm volatile("cp.async.commit_group;" ::: "memory");
        }
    }
    for (int t = 0; t < ntile; t++) {
        int buf = t % STAGES;
        if (t + STAGES - 1 < ntile) {
            loadbuf(t + STAGES - 1, (t + STAGES - 1) % STAGES);
            asm volatile("cp.async.commit_group;" ::: "memory");
        }
        int p = ntile - t;
        if (STAGES == 3) {
            if (p > 2)      asm volatile("cp.async.wait_group 2;" ::: "memory");
            else if (p > 1) asm volatile("cp.async.wait_group 1;" ::: "memory");
            else            asm volatile("cp.async.wait_group 0;" ::: "memory");
        } else {
            if (p > 1)      asm volatile("cp.async.wait_group 1;" ::: "memory");
            else            asm volatile("cp.async.wait_group 0;" ::: "memory");
        }
        __syncthreads();
        uint32_t base = sbase + buf * BUFSZ;
        #pragma unroll
        for (int s = 0; s < 4; s++) {
            int ks = 2 * s + gh;
            uint32_t ah[4][4], bh[2][4];
            #pragma unroll
            for (int mi = 0; mi < 4; mi++)
                ldsm4(ah[mi], base + ((wr * 64 + mi * 16 + jrow) << 7) + ((ks ^ perm) << 4));
            #pragma unroll
            for (int p2 = 0; p2 < 2; p2++)
                ldsm4(bh[p2], base + 16384 + ((wc * 32 + p2 * 16 + jrow) << 7) + ((ks ^ perm) << 4));
            #pragma unroll
            for (int mi = 0; mi < 4; mi++)
                #pragma unroll
                for (int ni = 0; ni < 4; ni++)
                    mmaf16(acc[mi][ni], ah[mi], bh[ni >> 1][ni & 1], bh[ni >> 1][2 + (ni & 1)]);
            if (TERMS == 2) {
                uint32_t bl[2][4];
                #pragma unroll
                for (int p2 = 0; p2 < 2; p2++)
                    ldsm4(bl[p2], base + 32768 + ((wc * 32 + p2 * 16 + jrow) << 7) + ((ks ^ perm) << 4));
                #pragma unroll
                for (int mi = 0; mi < 4; mi++)
                    #pragma unroll
                    for (int ni = 0; ni < 4; ni++)
                        mmaf16(acc[mi][ni], ah[mi], bl[ni >> 1][ni & 1], bl[ni >> 1][2 + (ni & 1)]);
            }
        }
        __syncthreads();
    }

    const float cg = 0.7978845608028654f;
    #pragma unroll
    for (int mi = 0; mi < 4; mi++) {
        int rbase = row0 + wr * 64 + mi * 16 + q;
        #pragma unroll
        for (int ni = 0; ni < 4; ni++) {
            int cbase = col0 + wc * 32 + ni * 8 + 2 * r4;
            #pragma unroll
            for (int rg = 0; rg < 2; rg++) {
                int rr = rbase + rg * 8;
                float v0 = acc[mi][ni][rg * 2 + 0] * 0.00390625f;
                float v1 = acc[mi][ni][rg * 2 + 1] * 0.00390625f;
                if (HASBIAS) { v0 += bias[cbase]; v1 += bias[cbase + 1]; }
                if (EPI == 2) {
                    float u0 = cg * (v0 + 0.044715f * v0 * v0 * v0);
                    v0 = 0.5f * v0 * (1.0f + tanhf(u0));
                    float u1 = cg * (v1 + 0.044715f * v1 * v1 * v1);
                    v1 = 0.5f * v1 * (1.0f + tanhf(u1));
                    PF[(size_t)rr * (N >> 1) + (cbase >> 1)] = pkh(v0, v1);
                } else if (EPI == 3) {
                    size_t idx = ((size_t)blockIdx.z * NT + rr) * N + cbase;
                    C[idx] = v0;
                    C[idx + 1] = v1;
                } else {
                    size_t idx = (size_t)rr * N + cbase;
                    if (cbase < N) C[idx] = v0;
                    if (cbase + 1 < N) C[idx + 1] = v1;
                }
            }
        }
    }
}

#define GSM1 98304

// ---------------- host ----------------
extern "C" void kernel_launch(void* const* d_in, const int* in_sizes, int n_in,
                              void* d_out, int out_size) {
    const int*   tok    = (const int*)  d_in[0];
    const float* wte    = (const float*)d_in[1];
    const float* wpe    = (const float*)d_in[2];
    const float* ln1_w  = (const float*)d_in[3];
    const float* ln1_b  = (const float*)d_in[4];
    const float* attn_w = (const float*)d_in[5];
    const float* attn_b = (const float*)d_in[6];
    const float* proj_w = (const float*)d_in[7];
    const float* proj_b = (const float*)d_in[8];
    const float* ln2_w  = (const float*)d_in[9];
    const float* ln2_b  = (const float*)d_in[10];
    const float* fc_w   = (const float*)d_in[11];
    const float* fc_b   = (const float*)d_in[12];
    const float* fc2_w  = (const float*)d_in[13];
    const float* fc2_b  = (const float*)d_in[14];
    const float* lnf_w  = (const float*)d_in[15];
    const float* lnf_b  = (const float*)d_in[16];
    const float* head_w = (const float*)d_in[17];
    float* out = (float*)d_out;

    float *x, *qkv;
    uint32_t *hF, *atF, *ffF;
    float2* attms;
    cudaGetSymbolAddress((void**)&x, g_x);
    cudaGetSymbolAddress((void**)&qkv, g_qkv);
    cudaGetSymbolAddress((void**)&hF, g_hF);
    cudaGetSymbolAddress((void**)&atF, g_atF);
    cudaGetSymbolAddress((void**)&ffF, g_ffF);
    cudaGetSymbolAddress((void**)&attms, g_attms);
    uint32_t *wq_h, *wq_l, *wp_h, *wp_l, *wf_h, *wf_l, *w2_h, *w2_l, *wh_h;
    cudaGetSymbolAddress((void**)&wq_h, g_wq_h);
    cudaGetSymbolAddress((void**)&wq_l, g_wq_l);
    cudaGetSymbolAddress((void**)&wp_h, g_wp_h);
    cudaGetSymbolAddress((void**)&wp_l, g_wp_l);
    cudaGetSymbolAddress((void**)&wf_h, g_wf_h);
    cudaGetSymbolAddress((void**)&wf_l, g_wf_l);
    cudaGetSymbolAddress((void**)&w2_h, g_w2_h);
    cudaGetSymbolAddress((void**)&w2_l, g_w2_l);
    cudaGetSymbolAddress((void**)&wh_h, g_wh_h);

    cudaFuncSetAttribute(gemm_lm<0, true,  1>, cudaFuncAttributeMaxDynamicSharedMemorySize, GSM1);
    cudaFuncSetAttribute(gemm_lm<2, true,  1>, cudaFuncAttributeMaxDynamicSharedMemorySize, GSM1);
    cudaFuncSetAttribute(gemm_lm<3, false, 1>, cudaFuncAttributeMaxDynamicSharedMemorySize, GSM1);
    cudaFuncSetAttribute(gemm_lm<0, false, 1>, cudaFuncAttributeMaxDynamicSharedMemorySize, GSM1);
    cudaFuncSetAttribute(attn_split, cudaFuncAttributeMaxDynamicSharedMemorySize, 65536);

    pack_w_t<<<dim3(12, 72, LL), 256>>>(attn_w, wq_h, wq_l, DD, D3);
    pack_w_t<<<dim3(12, 24, LL), 256>>>(proj_w, wp_h, wp_l, DD, DD);
    pack_w_t<<<dim3(12, 96, LL), 256>>>(fc_w,  wf_h, wf_l, DD, FF);
    pack_w_t<<<dim3(48, 24, LL), 256>>>(fc2_w, w2_h, w2_l, FF, DD);
    pack_headf<<<(VP * K2D + 255) / 256, 256>>>(head_w, wh_h);

    embed_ln_pack<<<NT, 256>>>(tok, wte, wpe, x, ln1_w, ln1_b, hF);

    for (int l = 0; l < LL; l++) {
        size_t oq = (size_t)l * D3 * K2D, op = (size_t)l * DD * K2D;
        size_t of = (size_t)l * FF * K2D, o2 = (size_t)l * DD * K2F;

        gemm_lm<0, true, 1><<<dim3(NT / 128, D3 / 128, 1), 256, GSM1>>>(
            hF, wq_h + oq, wq_l + oq, attn_b + l * D3, qkv, nullptr, D3, DD, K2D);
        attn_split<<<dim3(TT / 128, HH * 2, 2), 128, 65536>>>(qkv, (float*)ffF, attms);
        attn_merge<<<NT * HH / 8, 256>>>((const float*)ffF, attms, atF);
        gemm_lm<3, false, 1><<<dim3(NT / 128, DD / 128, 3), 256, GSM1>>>(
            atF, wp_h + op, wp_l + op, nullptr, qkv, nullptr, DD, DD / 3, K2D);
        red_ln_pack<<<NT, 256>>>(qkv, proj_b + l * DD, x, ln2_w + l * DD, ln2_b + l * DD, hF);
        gemm_lm<2, true, 1><<<dim3(NT / 128, FF / 128, 1), 256, GSM1>>>(
            hF, wf_h + of, wf_l + of, fc_b + l * FF, nullptr, ffF, FF, DD, K2D);
        gemm_lm<3, false, 1><<<dim3(NT / 128, DD / 128, 3), 256, GSM1>>>(
            ffF, w2_h + o2, w2_l + o2, nullptr, qkv, nullptr, DD, FF / 3, K2F);
        const float* nw = (l < LL - 1) ? ln1_w + (l + 1) * DD : lnf_w;
        const float* nb = (l < LL - 1) ? ln1_b + (l + 1) * DD : lnf_b;
        red_ln_pack<<<NT, 256>>>(qkv, fc2_b + l * DD, x, nw, nb, hF);
    }

    gemm_lm<0, false, 1><<<dim3(NT / 128, VP / 128, 1), 256, GSM1>>>(
        hF, wh_h, nullptr, nullptr, out, nullptr, VV, DD, K2D);
}

// round 14
// speedup vs baseline: 10.0214x; 1.0572x over previous
#include <cuda_runtime.h>
#include <cuda_bf16.h>
#include <cuda_fp16.h>
#include <math.h>
#include <stdint.h>

#define NT 2048
#define TT 1024
#define DD 768
#define FF 3072
#define HH 12
#define HD 64
#define LL 4
#define VV 50257
#define D3 2304
#define VP 50304
#define K2D 384
#define K2F 1536
#define NSPL 4

// ---------------- scratch ----------------
__device__ float    g_x[NT * DD];
__device__ float    g_qkv[NT * D3];   // also split-K partial buffer [3][NT][DD]
__device__ uint32_t g_hF[NT * K2D];
__device__ uint32_t g_atF[NT * K2D];
__device__ uint32_t g_ffF[NT * K2F];
__device__ float    g_oP[NSPL * NT * HH * 64];      // attention o-partials
__device__ float2   g_attms[NSPL * NT * HH];        // (m, ssum)
// weights n-major [N][K/2] fp16-pair words, scaled x256, hi/lo
__device__ uint32_t g_wq_h[LL * D3 * K2D], g_wq_l[LL * D3 * K2D];
__device__ uint32_t g_wp_h[LL * DD * K2D], g_wp_l[LL * DD * K2D];
__device__ uint32_t g_wf_h[LL * FF * K2D], g_wf_l[LL * FF * K2D];
__device__ uint32_t g_w2_h[LL * DD * K2F], g_w2_l[LL * DD * K2F];
__device__ uint32_t g_wh_h[VP * K2D];

// ---------------- helpers ----------------
__device__ __forceinline__ uint32_t pkh(float x, float y) {
    __half hx = __float2half_rn(x), hy = __float2half_rn(y);
    return ((uint32_t)__half_as_ushort(hy) << 16) | (uint32_t)__half_as_ushort(hx);
}
__device__ __forceinline__ void cvt2h(float x, float y, uint32_t& hi, uint32_t& lo) {
    __half hx = __float2half_rn(x), hy = __float2half_rn(y);
    hi = ((uint32_t)__half_as_ushort(hy) << 16) | (uint32_t)__half_as_ushort(hx);
    lo = pkh(x - __half2float(hx), y - __half2float(hy));
}
__device__ __forceinline__ void cpa16(uint32_t d, const void* s) {
    asm volatile("cp.async.cg.shared.global [%0], [%1], 16;" :: "r"(d), "l"(s));
}
__device__ __forceinline__ void ldsm4(uint32_t* r, uint32_t a) {
    asm volatile("ldmatrix.sync.aligned.m8n8.x4.shared.b16 {%0,%1,%2,%3}, [%4];"
                 : "=r"(r[0]), "=r"(r[1]), "=r"(r[2]), "=r"(r[3]) : "r"(a));
}
__device__ __forceinline__ void mmaf16(float* c, const uint32_t* a, uint32_t b0, uint32_t b1) {
    asm volatile("mma.sync.aligned.m16n8k16.row.col.f32.f16.f16.f32 "
                 "{%0,%1,%2,%3}, {%4,%5,%6,%7}, {%8,%9}, {%0,%1,%2,%3};\n"
                 : "+f"(c[0]), "+f"(c[1]), "+f"(c[2]), "+f"(c[3])
                 : "r"(a[0]), "r"(a[1]), "r"(a[2]), "r"(a[3]), "r"(b0), "r"(b1));
}
__device__ __forceinline__ uint64_t f2pk(float x, float y) {
    uint64_t r; asm("mov.b64 %0, {%1,%2};" : "=l"(r) : "f"(x), "f"(y)); return r;
}
__device__ __forceinline__ void f2un(uint64_t v, float& x, float& y) {
    asm("mov.b64 {%0,%1}, %2;" : "=f"(x), "=f"(y) : "l"(v));
}
__device__ __forceinline__ uint64_t fma2(uint64_t a, uint64_t b, uint64_t c) {
    uint64_t d; asm("fma.rn.f32x2 %0, %1, %2, %3;" : "=l"(d) : "l"(a), "l"(b), "l"(c)); return d;
}
__device__ __forceinline__ uint64_t mul2(uint64_t a, uint64_t b) {
    uint64_t d; asm("mul.rn.f32x2 %0, %1, %2;" : "=l"(d) : "l"(a), "l"(b)); return d;
}

// ---------------- packing ----------------
__global__ void pack_w_t(const float* __restrict__ W, uint32_t* __restrict__ Oh,
                         uint32_t* __restrict__ Ol, int K, int N) {
    __shared__ float s[64][33];
    int K2 = K >> 1;
    const float* Wl = W + (size_t)blockIdx.z * K * N;
    uint32_t* OhL = Oh + (size_t)blockIdx.z * N * K2;
    uint32_t* OlL = Ol + (size_t)blockIdx.z * N * K2;
    int k0 = blockIdx.x * 64, n0 = blockIdx.y * 32;
    int rr = threadIdx.x >> 5, cc = threadIdx.x & 31;
    #pragma unroll
    for (int i = 0; i < 8; i++)
        s[rr + i * 8][cc] = Wl[(size_t)(k0 + rr + i * 8) * N + n0 + cc];
    __syncthreads();
    #pragma unroll
    for (int i = 0; i < 4; i++) {
        int n = rr + i * 8;
        uint32_t h, l;
        cvt2h(s[2 * cc][n] * 256.f, s[2 * cc + 1][n] * 256.f, h, l);
        OhL[(size_t)(n0 + n) * K2 + (k0 >> 1) + cc] = h;
        OlL[(size_t)(n0 + n) * K2 + (k0 >> 1) + cc] = l;
    }
}
__global__ void pack_headf(const float* __restrict__ W, uint32_t* __restrict__ Oh) {
    int id = blockIdx.x * 256 + threadIdx.x;
    if (id >= VP * K2D) return;
    int n = id / K2D, kp = id - n * K2D;
    float x = 0.f, y = 0.f;
    if (n < VV) { const float* p = W + (size_t)n * DD + 2 * kp; x = p[0] * 256.f; y = p[1] * 256.f; }
    Oh[id] = pkh(x, y);
}

// ---------------- LN machinery ----------------
__device__ __forceinline__ float blk_sum(float v, float* red) {
    #pragma unroll
    for (int o = 16; o; o >>= 1) v += __shfl_xor_sync(0xffffffffu, v, o);
    if ((threadIdx.x & 31) == 0) red[threadIdx.x >> 5] = v;
    __syncthreads();
    float s = (threadIdx.x < 8) ? red[threadIdx.x] : 0.0f;
    #pragma unroll
    for (int o = 4; o; o >>= 1) s += __shfl_xor_sync(0xffffffffu, s, o);
    if (threadIdx.x == 0) red[0] = s;
    __syncthreads();
    s = red[0];
    __syncthreads();
    return s;
}

__device__ __forceinline__ void ln_body(float* v, float s, float ss, float* vb,
                                        const float* w, const float* b, int row,
                                        uint32_t* PF) {
    float mu = s * (1.0f / DD);
    float r = rsqrtf(ss * (1.0f / DD) - mu * mu + 1e-5f);
    #pragma unroll
    for (int i = 0; i < 3; i++) {
        int c = threadIdx.x + i * 256;
        vb[c] = (v[i] - mu) * r * w[c] + b[c];
    }
    __syncthreads();
    #pragma unroll
    for (int i = 0; i < 2; i++) {
        int p = threadIdx.x + i * 256;
        if (p < K2D)
            PF[(size_t)row * K2D + p] = pkh(vb[2 * p], vb[2 * p + 1]);
    }
}

__global__ void embed_ln_pack(const int* __restrict__ tok, const float* __restrict__ wte,
                              const float* __restrict__ wpe, float* __restrict__ x,
                              const float* __restrict__ w, const float* __restrict__ b,
                              uint32_t* __restrict__ PF) {
    __shared__ float vb[DD];
    __shared__ float red[32];
    int row = blockIdx.x, t = tok[row];
    const float* we = wte + (size_t)t * DD;
    const float* wp = wpe + (size_t)(row & (TT - 1)) * DD;
    float v[3], s = 0.f, ss = 0.f;
    #pragma unroll
    for (int i = 0; i < 3; i++) {
        int c = threadIdx.x + i * 256;
        v[i] = we[c] + wp[c];
        x[(size_t)row * DD + c] = v[i];
        s += v[i]; ss += v[i] * v[i];
    }
    s = blk_sum(s, red); ss = blk_sum(ss, red);
    ln_body(v, s, ss, vb, w, b, row, PF);
}

__global__ void red_ln_pack(const float* __restrict__ P, const float* __restrict__ bias,
                            float* __restrict__ x, const float* __restrict__ w,
                            const float* __restrict__ b, uint32_t* __restrict__ PF) {
    __shared__ float vb[DD];
    __shared__ float red[32];
    int row = blockIdx.x;
    float v[3], s = 0.f, ss = 0.f;
    #pragma unroll
    for (int i = 0; i < 3; i++) {
        int c = threadIdx.x + i * 256;
        size_t idx = (size_t)row * DD + c;
        float t = x[idx] + bias[c] + P[idx] + P[(size_t)NT * DD + idx] + P[2 * (size_t)NT * DD + idx];
        x[idx] = t;
        v[i] = t; s += t; ss += t * t;
    }
    s = blk_sum(s, red); ss = blk_sum(ss, red);
    ln_body(v, s, ss, vb, w, b, row, PF);
}

// ---------------- attention: split-KV (4-way) ----------------
// grid (TT/128, HH*NSPL, 2): blockIdx.y = h*NSPL + split.
__global__ void __launch_bounds__(128)
attn_split(const float* __restrict__ qkv, float* __restrict__ oP,
           float2* __restrict__ msP) {
    extern __shared__ __align__(16) unsigned sm_dyn[];
    float* Ks = (float*)sm_dyn;
    float* Vs = Ks + 4096;
    float* sc = Vs + 4096;
    int tid = threadIdx.x;
    int qt = blockIdx.x;
    int h = blockIdx.y >> 2, split = blockIdx.y & 3;
    int b = blockIdx.z;
    int qpos = qt * 128 + tid;
    const float* base = qkv + (size_t)b * TT * D3;
    uint64_t q2[32], o2[32];
    {
        const float* qp = base + (size_t)qpos * D3 + h * HD;
        #pragma unroll
        for (int j = 0; j < 32; j++) q2[j] = f2pk(qp[2 * j], qp[2 * j + 1]);
    }
    #pragma unroll
    for (int j = 0; j < 32; j++) o2[j] = 0ull;
    float m = -1e30f, ssum = 0.f;
    int nkt = (qt + 1) * 2;
    for (int kt = split; kt < nkt; kt += NSPL) {
        int k0 = kt * 64;
        __syncthreads();
        #pragma unroll
        for (int i = 0; i < 8; i++) {
            int idx = (i * 128 + tid) * 4;
            int kk = idx >> 6, e = idx & 63;
            const float* rowp = base + (size_t)(k0 + kk) * D3 + h * HD + e;
            *(float4*)(Ks + idx) = *(const float4*)(rowp + DD);
            *(float4*)(Vs + idx) = *(const float4*)(rowp + 2 * DD);
        }
        __syncthreads();
        float tm = -1e30f;
        for (int kk = 0; kk < 64; kk++) {
            const uint64_t* kr = (const uint64_t*)(Ks + (kk << 6));
            uint64_t a0 = 0ull, a1 = 0ull, a2 = 0ull, a3 = 0ull;
            #pragma unroll
            for (int j = 0; j < 32; j += 4) {
                a0 = fma2(q2[j], kr[j], a0);
                a1 = fma2(q2[j + 1], kr[j + 1], a1);
                a2 = fma2(q2[j + 2], kr[j + 2], a2);
                a3 = fma2(q2[j + 3], kr[j + 3], a3);
            }
            float x0, y0, x1, y1, x2, y2, x3, y3;
            f2un(a0, x0, y0); f2un(a1, x1, y1); f2un(a2, x2, y2); f2un(a3, x3, y3);
            float sv = (((x0 + y0) + (x1 + y1)) + ((x2 + y2) + (x3 + y3))) * 0.125f;
            if (k0 + kk > qpos) sv = -1e30f;
            sc[kk * 128 + tid] = sv;
            tm = fmaxf(tm, sv);
        }
        float mn = fmaxf(m, tm);
        if (mn < -1e29f) continue;   // tile fully masked & no prior keys
        float cr = __expf(m - mn);
        m = mn; ssum *= cr;
        uint64_t cr2 = f2pk(cr, cr);
        #pragma unroll
        for (int j = 0; j < 32; j++) o2[j] = mul2(o2[j], cr2);
        for (int kk = 0; kk < 64; kk++) {
            float p = __expf(sc[kk * 128 + tid] - m);
            ssum += p;
            uint64_t p2 = f2pk(p, p);
            const uint64_t* vr = (const uint64_t*)(Vs + (kk << 6));
            #pragma unroll
            for (int j = 0; j < 32; j++) o2[j] = fma2(p2, vr[j], o2[j]);
        }
    }
    size_t u = (((size_t)(split * 2 + b) * TT + qpos) * HH + h);
    float* op = oP + u * 64;
    #pragma unroll
    for (int j = 0; j < 16; j++) {
        float4 v;
        f2un(o2[2 * j], v.x, v.y);
        f2un(o2[2 * j + 1], v.z, v.w);
        *(float4*)(op + 4 * j) = v;
    }
    msP[u] = make_float2(m, ssum);
}

// merge NSPL softmax partials -> packed fp16 attn out; one warp per (row,h)
__global__ void attn_merge(const float* __restrict__ oP, const float2* __restrict__ msP,
                           uint32_t* __restrict__ attF) {
    int gid = blockIdx.x * 8 + (threadIdx.x >> 5);
    int lane = threadIdx.x & 31;
    int row = gid / HH, h = gid - row * HH;
    int b = row >> 10, q = row & 1023;
    size_t u[NSPL];
    float wgt[NSPL];
    float M = -1e30f;
    float2 ms[NSPL];
    #pragma unroll
    for (int s = 0; s < NSPL; s++) {
        u[s] = (((size_t)(s * 2 + b) * TT + q) * HH + h);
        ms[s] = msP[u[s]];
        if (ms[s].y > 0.f) M = fmaxf(M, ms[s].x);
    }
    float den = 0.f;
    #pragma unroll
    for (int s = 0; s < NSPL; s++) {
        wgt[s] = (ms[s].y > 0.f) ? __expf(ms[s].x - M) : 0.f;
        den += ms[s].y * wgt[s];
    }
    float inv = 1.0f / den;
    float v0 = 0.f, v1 = 0.f;
    #pragma unroll
    for (int s = 0; s < NSPL; s++) {
        float2 a = ((const float2*)(oP + u[s] * 64))[lane];
        v0 += a.x * wgt[s];
        v1 += a.y * wgt[s];
    }
    attF[(size_t)row * K2D + h * 32 + lane] = pkh(v0 * inv, v1 * inv);
}

// ---------------- fp16 MMA GEMM (ldmatrix), 128x128, BK=64 --------------
template<int EPI, bool HASBIAS, int TERMS>
__global__ void __launch_bounds__(256, 2)
gemm_lm(const uint32_t* __restrict__ AF, const uint32_t* __restrict__ BhG,
        const uint32_t* __restrict__ BlG, const float* __restrict__ bias,
        float* __restrict__ C, uint32_t* __restrict__ PF,
        int N, int Kslice, int K2s) {
    constexpr int BUFSZ  = (TERMS == 2) ? 49152 : 32768;
    constexpr int STAGES = (TERMS == 2) ? 2 : 3;
    extern __shared__ __align__(16) char smem[];
    uint32_t sbase = (uint32_t)__cvta_generic_to_shared(smem);
    int tid = threadIdx.x;
    int w = tid >> 5, lane = tid & 31;
    int wr = w >> 2, wc = w & 3;
    int q = lane >> 2, r4 = lane & 3;
    int jrow = ((lane >> 3) & 1) * 8 + (lane & 7);
    int gh = lane >> 4;
    int perm = jrow & 7;
    int row0 = blockIdx.x * 128, col0 = blockIdx.y * 128;
    int kofs = blockIdx.z * (Kslice >> 1);

    float acc[4][4][4];
    #pragma unroll
    for (int mi = 0; mi < 4; mi++)
        #pragma unroll
        for (int ni = 0; ni < 4; ni++)
            #pragma unroll
            for (int e = 0; e < 4; e++) acc[mi][ni][e] = 0.f;

    auto loadbuf = [&](int t, int buf) {
        uint32_t base = sbase + buf * BUFSZ;
        int kp0 = kofs + t * 32;
        #pragma unroll
        for (int i = 0; i < 4; i++) {
            int id = tid + i * 256;
            int mm = id >> 3, g = id & 7;
            uint32_t dst = base + (mm << 7) + ((g ^ (mm & 7)) << 4);
            cpa16(dst, AF + (size_t)(row0 + mm) * K2s + kp0 + g * 4);
        }
        #pragma unroll
        for (int i = 0; i < 4; i++) {
            int id = tid + i * 256;
            int nn = id >> 3, g = id & 7;
            uint32_t dst = base + 16384 + (nn << 7) + ((g ^ (nn & 7)) << 4);
            size_t off = (size_t)(col0 + nn) * K2s + kp0 + g * 4;
            cpa16(dst, BhG + off);
            if (TERMS == 2) cpa16(dst + 16384, BlG + off);
        }
    };

    int ntile = Kslice >> 6;
    #pragma unroll
    for (int pt = 0; pt < STAGES - 1; pt++) {
        if (pt < ntile) {
            loadbuf(pt, pt % STAGES);
            asm volatile("cp.async.commit_group;" ::: "memory");
        }
    }
    for (int t = 0; t < ntile; t++) {
        int buf = t % STAGES;
        if (t + STAGES - 1 < ntile) {
            loadbuf(t + STAGES - 1, (t + STAGES - 1) % STAGES);
            asm volatile("cp.async.commit_group;" ::: "memory");
        }
        int p = ntile - t;
        if (STAGES == 3) {
            if (p > 2)      asm volatile("cp.async.wait_group 2;" ::: "memory");
            else if (p > 1) asm volatile("cp.async.wait_group 1;" ::: "memory");
            else            asm volatile("cp.async.wait_group 0;" ::: "memory");
        } else {
            if (p > 1)      asm volatile("cp.async.wait_group 1;" ::: "memory");
            else            asm volatile("cp.async.wait_group 0;" ::: "memory");
        }
        __syncthreads();
        uint32_t base = sbase + buf * BUFSZ;
        #pragma unroll
        for (int s = 0; s < 4; s++) {
            int ks = 2 * s + gh;
            uint32_t ah[4][4], bh[2][4];
            #pragma unroll
            for (int mi = 0; mi < 4; mi++)
                ldsm4(ah[mi], base + ((wr * 64 + mi * 16 + jrow) << 7) + ((ks ^ perm) << 4));
            #pragma unroll
            for (int p2 = 0; p2 < 2; p2++)
                ldsm4(bh[p2], base + 16384 + ((wc * 32 + p2 * 16 + jrow) << 7) + ((ks ^ perm) << 4));
            #pragma unroll
            for (int mi = 0; mi < 4; mi++)
                #pragma unroll
                for (int ni = 0; ni < 4; ni++)
                    mmaf16(acc[mi][ni], ah[mi], bh[ni >> 1][ni & 1], bh[ni >> 1][2 + (ni & 1)]);
            if (TERMS == 2) {
                uint32_t bl[2][4];
                #pragma unroll
                for (int p2 = 0; p2 < 2; p2++)
                    ldsm4(bl[p2], base + 32768 + ((wc * 32 + p2 * 16 + jrow) << 7) + ((ks ^ perm) << 4));
                #pragma unroll
                for (int mi = 0; mi < 4; mi++)
                    #pragma unroll
                    for (int ni = 0; ni < 4; ni++)
                        mmaf16(acc[mi][ni], ah[mi], bl[ni >> 1][ni & 1], bl[ni >> 1][2 + (ni & 1)]);
            }
        }
        __syncthreads();
    }

    const float cg = 0.7978845608028654f;
    #pragma unroll
    for (int mi = 0; mi < 4; mi++) {
        int rbase = row0 + wr * 64 + mi * 16 + q;
        #pragma unroll
        for (int ni = 0; ni < 4; ni++) {
            int cbase = col0 + wc * 32 + ni * 8 + 2 * r4;
            #pragma unroll
            for (int rg = 0; rg < 2; rg++) {
                int rr = rbase + rg * 8;
                float v0 = acc[mi][ni][rg * 2 + 0] * 0.00390625f;
                float v1 = acc[mi][ni][rg * 2 + 1] * 0.00390625f;
                if (HASBIAS) { v0 += bias[cbase]; v1 += bias[cbase + 1]; }
                if (EPI == 2) {
                    float u0 = cg * (v0 + 0.044715f * v0 * v0 * v0);
                    v0 = 0.5f * v0 * (1.0f + tanhf(u0));
                    float u1 = cg * (v1 + 0.044715f * v1 * v1 * v1);
                    v1 = 0.5f * v1 * (1.0f + tanhf(u1));
                    PF[(size_t)rr * (N >> 1) + (cbase >> 1)] = pkh(v0, v1);
                } else if (EPI == 3) {
                    size_t idx = ((size_t)blockIdx.z * NT + rr) * N + cbase;
                    C[idx] = v0;
                    C[idx + 1] = v1;
                } else {
                    size_t idx = (size_t)rr * N + cbase;
                    if (cbase < N) C[idx] = v0;
                    if (cbase + 1 < N) C[idx + 1] = v1;
                }
            }
        }
    }
}

#define GSM1 98304

// ---------------- host ----------------
extern "C" void kernel_launch(void* const* d_in, const int* in_sizes, int n_in,
                              void* d_out, int out_size) {
    const int*   tok    = (const int*)  d_in[0];
    const float* wte    = (const float*)d_in[1];
    const float* wpe    = (const float*)d_in[2];
    const float* ln1_w  = (const float*)d_in[3];
    const float* ln1_b  = (const float*)d_in[4];
    const float* attn_w = (const float*)d_in[5];
    const float* attn_b = (const float*)d_in[6];
    const float* proj_w = (const float*)d_in[7];
    const float* proj_b = (const float*)d_in[8];
    const float* ln2_w  = (const float*)d_in[9];
    const float* ln2_b  = (const float*)d_in[10];
    const float* fc_w   = (const float*)d_in[11];
    const float* fc_b   = (const float*)d_in[12];
    const float* fc2_w  = (const float*)d_in[13];
    const float* fc2_b  = (const float*)d_in[14];
    const float* lnf_w  = (const float*)d_in[15];
    const float* lnf_b  = (const float*)d_in[16];
    const float* head_w = (const float*)d_in[17];
    float* out = (float*)d_out;

    float *x, *qkv, *oP;
    uint32_t *hF, *atF, *ffF;
    float2* attms;
    cudaGetSymbolAddress((void**)&x, g_x);
    cudaGetSymbolAddress((void**)&qkv, g_qkv);
    cudaGetSymbolAddress((void**)&hF, g_hF);
    cudaGetSymbolAddress((void**)&atF, g_atF);
    cudaGetSymbolAddress((void**)&ffF, g_ffF);
    cudaGetSymbolAddress((void**)&oP, g_oP);
    cudaGetSymbolAddress((void**)&attms, g_attms);
    uint32_t *wq_h, *wq_l, *wp_h, *wp_l, *wf_h, *wf_l, *w2_h, *w2_l, *wh_h;
    cudaGetSymbolAddress((void**)&wq_h, g_wq_h);
    cudaGetSymbolAddress((void**)&wq_l, g_wq_l);
    cudaGetSymbolAddress((void**)&wp_h, g_wp_h);
    cudaGetSymbolAddress((void**)&wp_l, g_wp_l);
    cudaGetSymbolAddress((void**)&wf_h, g_wf_h);
    cudaGetSymbolAddress((void**)&wf_l, g_wf_l);
    cudaGetSymbolAddress((void**)&w2_h, g_w2_h);
    cudaGetSymbolAddress((void**)&w2_l, g_w2_l);
    cudaGetSymbolAddress((void**)&wh_h, g_wh_h);

    cudaFuncSetAttribute(gemm_lm<0, true,  1>, cudaFuncAttributeMaxDynamicSharedMemorySize, GSM1);
    cudaFuncSetAttribute(gemm_lm<2, true,  1>, cudaFuncAttributeMaxDynamicSharedMemorySize, GSM1);
    cudaFuncSetAttribute(gemm_lm<3, false, 1>, cudaFuncAttributeMaxDynamicSharedMemorySize, GSM1);
    cudaFuncSetAttribute(gemm_lm<0, false, 1>, cudaFuncAttributeMaxDynamicSharedMemorySize, GSM1);
    cudaFuncSetAttribute(attn_split, cudaFuncAttributeMaxDynamicSharedMemorySize, 65536);

    pack_w_t<<<dim3(12, 72, LL), 256>>>(attn_w, wq_h, wq_l, DD, D3);
    pack_w_t<<<dim3(12, 24, LL), 256>>>(proj_w, wp_h, wp_l, DD, DD);
    pack_w_t<<<dim3(12, 96, LL), 256>>>(fc_w,  wf_h, wf_l, DD, FF);
    pack_w_t<<<dim3(48, 24, LL), 256>>>(fc2_w, w2_h, w2_l, FF, DD);
    pack_headf<<<(VP * K2D + 255) / 256, 256>>>(head_w, wh_h);

    embed_ln_pack<<<NT, 256>>>(tok, wte, wpe, x, ln1_w, ln1_b, hF);

    for (int l = 0; l < LL; l++) {
        size_t oq = (size_t)l * D3 * K2D, op = (size_t)l * DD * K2D;
        size_t of = (size_t)l * FF * K2D, o2 = (size_t)l * DD * K2F;

        gemm_lm<0, true, 1><<<dim3(NT / 128, D3 / 128, 1), 256, GSM1>>>(
            hF, wq_h + oq, wq_l + oq, attn_b + l * D3, qkv, nullptr, D3, DD, K2D);
        attn_split<<<dim3(TT / 128, HH * NSPL, 2), 128, 65536>>>(qkv, oP, attms);
        attn_merge<<<NT * HH / 8, 256>>>(oP, attms, atF);
        gemm_lm<3, false, 1><<<dim3(NT / 128, DD / 128, 3), 256, GSM1>>>(
            atF, wp_h + op, wp_l + op, nullptr, qkv, nullptr, DD, DD / 3, K2D);
        red_ln_pack<<<NT, 256>>>(qkv, proj_b + l * DD, x, ln2_w + l * DD, ln2_b + l * DD, hF);
        gemm_lm<2, true, 1><<<dim3(NT / 128, FF / 128, 1), 256, GSM1>>>(
            hF, wf_h + of, wf_l + of, fc_b + l * FF, nullptr, ffF, FF, DD, K2D);
        gemm_lm<3, false, 1><<<dim3(NT / 128, DD / 128, 3), 256, GSM1>>>(
            ffF, w2_h + o2, w2_l + o2, nullptr, qkv, nullptr, DD, FF / 3, K2F);
        const float* nw = (l < LL - 1) ? ln1_w + (l + 1) * DD : lnf_w;
        const float* nb = (l < LL - 1) ? ln1_b + (l + 1) * DD : lnf_b;
        red_ln_pack<<<NT, 256>>>(qkv, fc2_b + l * DD, x, nw, nb, hF);
    }

    gemm_lm<0, false, 1><<<dim3(NT / 128, VP / 128, 1), 256, GSM1>>>(
        hF, wh_h, nullptr, nullptr, out, nullptr, VV, DD, K2D);
}